// round 2
// baseline (speedup 1.0000x reference)
#include <cuda_runtime.h>

#define HH 64
#define CC 8
#define LL 96
#define TT 24
#define BB 4096

// Scratch (device globals — no allocations allowed)
__device__ float g_enc_out[(size_t)BB * LL * HH];  // ~100 MB
__device__ float g_h0[BB * HH];
__device__ float g_c0[BB * HH];

__device__ __forceinline__ float sigf(float x) { return 1.0f / (1.0f + __expf(-x)); }

// ---------------------------------------------------------------------------
// Encoder: one block per batch element, 256 threads = 256 gate rows.
// Weights live in registers; h broadcast from SMEM (float4).
// ---------------------------------------------------------------------------
__global__ __launch_bounds__(256) void enc_kernel(
    const float* __restrict__ x_enc,
    const float* __restrict__ Wih, const float* __restrict__ Whh,
    const float* __restrict__ bih, const float* __restrict__ bhh)
{
    int b = blockIdx.x;
    int t = threadIdx.x;

    __shared__ __align__(16) float sh[HH];
    __shared__ __align__(16) float sg[4 * HH];
    __shared__ __align__(16) float sx[CC];
    __shared__ __align__(16) float slast[CC];

    float wih[CC];
#pragma unroll
    for (int k = 0; k < CC; k++) wih[k] = Wih[t * CC + k];
    float whh[HH];
#pragma unroll
    for (int k = 0; k < HH; k += 4) {
        float4 v = *reinterpret_cast<const float4*>(Whh + t * HH + k);
        whh[k] = v.x; whh[k + 1] = v.y; whh[k + 2] = v.z; whh[k + 3] = v.w;
    }
    float bias = bih[t] + bhh[t];

    const float* xb = x_enc + (size_t)b * LL * CC;
    if (t < CC) slast[t] = xb[(LL - 1) * CC + t];
    if (t < HH) sh[t] = 0.0f;
    float c = 0.0f;
    __syncthreads();

    for (int step = 0; step < LL; step++) {
        if (t < CC) sx[t] = xb[step * CC + t] - slast[t];
        __syncthreads();

        float g = bias;
#pragma unroll
        for (int k = 0; k < CC; k++) g = fmaf(wih[k], sx[k], g);
#pragma unroll
        for (int k = 0; k < HH; k += 4) {
            float4 hv = *reinterpret_cast<const float4*>(&sh[k]);
            g = fmaf(whh[k],     hv.x, g);
            g = fmaf(whh[k + 1], hv.y, g);
            g = fmaf(whh[k + 2], hv.z, g);
            g = fmaf(whh[k + 3], hv.w, g);
        }
        sg[t] = g;
        __syncthreads();

        if (t < HH) {
            float i  = sigf(sg[t]);
            float f  = sigf(sg[HH + t]);
            float gg = tanhf(sg[2 * HH + t]);
            float o  = sigf(sg[3 * HH + t]);
            c = fmaf(f, c, i * gg);
            float hn = o * tanhf(c);
            sh[t] = hn;
            g_enc_out[((size_t)b * LL + step) * HH + t] = hn;
        }
        __syncthreads();
    }
    if (t < HH) {
        g_h0[b * HH + t] = sh[t];
        g_c0[b * HH + t] = c;
    }
}

// ---------------------------------------------------------------------------
// Decoder: one block per batch element. enc_out + attn/comb/emb/out weights
// (transposed k-major, conflict-free) live in SMEM; dec LSTM weights in regs.
// ---------------------------------------------------------------------------
struct DecSmem {
    float enc[LL * HH];       // 6144  [l][h]
    float attnW[128 * LL];    // 12288 [k][r]
    float combW[128 * HH];    // 8192  [k][j]
    float embW[CC * HH];      // 512   [k][j]
    float outW[HH * CC];      // 512   [k][c]
    float attn_b[LL];         // 96
    float comb_b[HH];         // 64
    float emb_b[HH];          // 64
    float out_b[CC];          // 8
    float inp[CC];            // 8
    float emb[HH];            // 64
    float aw[LL];             // 96
    float ctx[HH];            // 64
    float comb[HH];           // 64
    float h[HH];              // 64
    float g[4 * HH];          // 256
    float inv[4];             // 4
};

__global__ __launch_bounds__(256) void dec_kernel(
    const float* __restrict__ x_enc,
    const float* __restrict__ emb_W, const float* __restrict__ emb_b,
    const float* __restrict__ attn_W, const float* __restrict__ attn_b,
    const float* __restrict__ comb_W, const float* __restrict__ comb_b,
    const float* __restrict__ Wih, const float* __restrict__ Whh,
    const float* __restrict__ bih, const float* __restrict__ bhh,
    const float* __restrict__ out_W, const float* __restrict__ out_b,
    float* __restrict__ y)
{
    extern __shared__ float smem_raw[];
    DecSmem* s = reinterpret_cast<DecSmem*>(smem_raw);
    int b = blockIdx.x;
    int t = threadIdx.x;

    // Register LSTM weights: thread t owns gate row t.
    float wih[HH], whh[HH];
#pragma unroll
    for (int k = 0; k < HH; k += 4) {
        float4 v = *reinterpret_cast<const float4*>(Wih + t * HH + k);
        wih[k] = v.x; wih[k + 1] = v.y; wih[k + 2] = v.z; wih[k + 3] = v.w;
        float4 u = *reinterpret_cast<const float4*>(Whh + t * HH + k);
        whh[k] = u.x; whh[k + 1] = u.y; whh[k + 2] = u.z; whh[k + 3] = u.w;
    }
    float bias = bih[t] + bhh[t];

    // Stage SMEM: enc_out tile + transposed weights.
    const float* encg = g_enc_out + (size_t)b * LL * HH;
    for (int i = t; i < LL * HH; i += 256) s->enc[i] = encg[i];
    for (int i = t; i < LL * 128; i += 256) { int r = i >> 7, k = i & 127; s->attnW[k * LL + r] = attn_W[i]; }
    for (int i = t; i < HH * 128; i += 256) { int j = i >> 7, k = i & 127; s->combW[k * HH + j] = comb_W[i]; }
    for (int i = t; i < HH * CC;  i += 256) { int j = i >> 3, k = i & 7;   s->embW[k * HH + j]  = emb_W[i]; }
    for (int i = t; i < CC * HH;  i += 256) { int ci = i >> 6, k = i & 63; s->outW[k * CC + ci] = out_W[i]; }
    if (t < LL) s->attn_b[t] = attn_b[t];
    if (t < HH) { s->comb_b[t] = comb_b[t]; s->emb_b[t] = emb_b[t]; s->h[t] = g_h0[b * HH + t]; }
    if (t < CC) { s->out_b[t] = out_b[t]; s->inp[t] = 0.0f; }  // dec_in0 = x[:,-1,:] - seq_last == 0
    float c = (t < HH) ? g_c0[b * HH + t] : 0.0f;
    float slast = (t < CC) ? x_enc[(size_t)b * LL * CC + (LL - 1) * CC + t] : 0.0f;
    __syncthreads();

    for (int step = 0; step < TT; step++) {
        // emb = relu(inp @ emb_W.T + emb_b)   (threads 0..63)
        if (t < HH) {
            float e = s->emb_b[t];
#pragma unroll
            for (int k = 0; k < CC; k++) e = fmaf(s->embW[k * HH + t], s->inp[k], e);
            s->emb[t] = fmaxf(e, 0.0f);
        }
        __syncthreads();

        // attn logits: z[r] = [emb, h] @ attn_W[r,:] + attn_b[r]   (threads 0..95)
        if (t < LL) {
            float z = s->attn_b[t];
#pragma unroll
            for (int k = 0; k < HH; k += 4) {
                float4 e4 = *reinterpret_cast<const float4*>(&s->emb[k]);
                z = fmaf(s->attnW[(k    ) * LL + t], e4.x, z);
                z = fmaf(s->attnW[(k + 1) * LL + t], e4.y, z);
                z = fmaf(s->attnW[(k + 2) * LL + t], e4.z, z);
                z = fmaf(s->attnW[(k + 3) * LL + t], e4.w, z);
            }
#pragma unroll
            for (int k = 0; k < HH; k += 4) {
                float4 h4 = *reinterpret_cast<const float4*>(&s->h[k]);
                z = fmaf(s->attnW[(HH + k    ) * LL + t], h4.x, z);
                z = fmaf(s->attnW[(HH + k + 1) * LL + t], h4.y, z);
                z = fmaf(s->attnW[(HH + k + 2) * LL + t], h4.z, z);
                z = fmaf(s->attnW[(HH + k + 3) * LL + t], h4.w, z);
            }
            s->aw[t] = z;  // raw logits, softmaxed below
        }
        __syncthreads();

        // softmax over 96 logits (warp 0)
        if (t < 32) {
            float z0 = s->aw[t], z1 = s->aw[t + 32], z2 = s->aw[t + 64];
            float m = fmaxf(fmaxf(z0, z1), z2);
#pragma unroll
            for (int o = 16; o; o >>= 1) m = fmaxf(m, __shfl_xor_sync(0xffffffffu, m, o));
            float e0 = __expf(z0 - m), e1 = __expf(z1 - m), e2 = __expf(z2 - m);
            s->aw[t] = e0; s->aw[t + 32] = e1; s->aw[t + 64] = e2;
            float sum = e0 + e1 + e2;
#pragma unroll
            for (int o = 16; o; o >>= 1) sum += __shfl_xor_sync(0xffffffffu, sum, o);
            if (t == 0) s->inv[0] = 1.0f / sum;
        }
        __syncthreads();

        // ctx[j] = sum_l aw[l] * enc[l][j]  (unnormalized; scale by inv)  (threads 0..63)
        if (t < HH) {
            float acc = 0.0f;
#pragma unroll 4
            for (int l = 0; l < LL; l += 4) {
                float4 a4 = *reinterpret_cast<const float4*>(&s->aw[l]);
                acc = fmaf(a4.x, s->enc[(l    ) * HH + t], acc);
                acc = fmaf(a4.y, s->enc[(l + 1) * HH + t], acc);
                acc = fmaf(a4.z, s->enc[(l + 2) * HH + t], acc);
                acc = fmaf(a4.w, s->enc[(l + 3) * HH + t], acc);
            }
            s->ctx[t] = acc * s->inv[0];
        }
        __syncthreads();

        // comb[j] = [emb, ctx] @ comb_W[j,:] + comb_b[j]  (threads 0..63)
        if (t < HH) {
            float acc = s->comb_b[t];
#pragma unroll
            for (int k = 0; k < HH; k += 4) {
                float4 e4 = *reinterpret_cast<const float4*>(&s->emb[k]);
                acc = fmaf(s->combW[(k    ) * HH + t], e4.x, acc);
                acc = fmaf(s->combW[(k + 1) * HH + t], e4.y, acc);
                acc = fmaf(s->combW[(k + 2) * HH + t], e4.z, acc);
                acc = fmaf(s->combW[(k + 3) * HH + t], e4.w, acc);
            }
#pragma unroll
            for (int k = 0; k < HH; k += 4) {
                float4 c4 = *reinterpret_cast<const float4*>(&s->ctx[k]);
                acc = fmaf(s->combW[(HH + k    ) * HH + t], c4.x, acc);
                acc = fmaf(s->combW[(HH + k + 1) * HH + t], c4.y, acc);
                acc = fmaf(s->combW[(HH + k + 2) * HH + t], c4.z, acc);
                acc = fmaf(s->combW[(HH + k + 3) * HH + t], c4.w, acc);
            }
            s->comb[t] = acc;
        }
        __syncthreads();

        // LSTM gates: all 256 threads, register weights.
        {
            float g = bias;
#pragma unroll
            for (int k = 0; k < HH; k += 4) {
                float4 cv = *reinterpret_cast<const float4*>(&s->comb[k]);
                g = fmaf(wih[k],     cv.x, g);
                g = fmaf(wih[k + 1], cv.y, g);
                g = fmaf(wih[k + 2], cv.z, g);
                g = fmaf(wih[k + 3], cv.w, g);
            }
#pragma unroll
            for (int k = 0; k < HH; k += 4) {
                float4 hv = *reinterpret_cast<const float4*>(&s->h[k]);
                g = fmaf(whh[k],     hv.x, g);
                g = fmaf(whh[k + 1], hv.y, g);
                g = fmaf(whh[k + 2], hv.z, g);
                g = fmaf(whh[k + 3], hv.w, g);
            }
            s->g[t] = g;
        }
        __syncthreads();

        // cell update (threads 0..63)
        if (t < HH) {
            float i  = sigf(s->g[t]);
            float f  = sigf(s->g[HH + t]);
            float gg = tanhf(s->g[2 * HH + t]);
            float o  = sigf(s->g[3 * HH + t]);
            c = fmaf(f, c, i * gg);
            float hn = o * tanhf(c);
            s->h[t] = hn;
        }
        __syncthreads();

        // pred = h @ out_W.T + out_b; feed back; write output (threads 0..7)
        if (t < CC) {
            float p = s->out_b[t];
#pragma unroll
            for (int k = 0; k < HH; k++) p = fmaf(s->outW[k * CC + t], s->h[k], p);
            s->inp[t] = p;
            y[((size_t)b * TT + step) * CC + t] = p + slast;
        }
        __syncthreads();
    }
}

extern "C" void kernel_launch(void* const* d_in, const int* in_sizes, int n_in,
                              void* d_out, int out_size)
{
    const float* x_enc   = (const float*)d_in[0];
    // d_in[1] x_mark_enc, d_in[2] x_dec, d_in[3] x_mark_dec: unused by reference
    const float* enc_Wih = (const float*)d_in[4];
    const float* enc_Whh = (const float*)d_in[5];
    const float* enc_bih = (const float*)d_in[6];
    const float* enc_bhh = (const float*)d_in[7];
    const float* emb_W   = (const float*)d_in[8];
    const float* emb_b   = (const float*)d_in[9];
    const float* attn_W  = (const float*)d_in[10];
    const float* attn_b  = (const float*)d_in[11];
    const float* comb_W  = (const float*)d_in[12];
    const float* comb_b  = (const float*)d_in[13];
    const float* dec_Wih = (const float*)d_in[14];
    const float* dec_Whh = (const float*)d_in[15];
    const float* dec_bih = (const float*)d_in[16];
    const float* dec_bhh = (const float*)d_in[17];
    const float* out_W   = (const float*)d_in[18];
    const float* out_b   = (const float*)d_in[19];
    float* y = (float*)d_out;

    cudaFuncSetAttribute(dec_kernel, cudaFuncAttributeMaxDynamicSharedMemorySize,
                         (int)sizeof(DecSmem));

    enc_kernel<<<BB, 256>>>(x_enc, enc_Wih, enc_Whh, enc_bih, enc_bhh);
    dec_kernel<<<BB, 256, sizeof(DecSmem)>>>(x_enc, emb_W, emb_b, attn_W, attn_b,
                                             comb_W, comb_b, dec_Wih, dec_Whh,
                                             dec_bih, dec_bhh, out_W, out_b, y);
}

// round 3
// speedup vs baseline: 1.6985x; 1.6985x over previous
#include <cuda_runtime.h>

#define HH 64
#define CC 8
#define LL 96
#define TT 24
#define BB 4096

// Scratch (device globals — no allocations allowed)
__device__ float g_enc_out[(size_t)BB * LL * HH];  // ~100 MB
__device__ float g_h0[BB * HH];
__device__ float g_c0[BB * HH];

__device__ __forceinline__ float tanha(float x) {
    float r; asm("tanh.approx.f32 %0, %1;" : "=f"(r) : "f"(x)); return r;
}
__device__ __forceinline__ float sigt(float x) {  // sigmoid via tanh MUFU
    return fmaf(tanha(x * 0.5f), 0.5f, 0.5f);
}
__device__ __forceinline__ unsigned long long pk2(float a, float b) {
    unsigned long long r; asm("mov.b64 %0, {%1, %2};" : "=l"(r) : "f"(a), "f"(b)); return r;
}
#define FMA2(acc, a, b) asm("fma.rn.f32x2 %0, %1, %2, %0;" : "+l"(acc) : "l"(a), "l"(b))

// ---------------------------------------------------------------------------
// Encoder: 4 batches/block, 256 threads = 256 gate rows (each for 4 batches).
// Batch pairs packed into f32x2; weights duplicated into packed registers.
// ---------------------------------------------------------------------------
__global__ __launch_bounds__(256, 1) void enc_kernel(
    const float* __restrict__ x_enc,
    const float* __restrict__ Wih, const float* __restrict__ Whh,
    const float* __restrict__ bih, const float* __restrict__ bhh)
{
    const int b0 = blockIdx.x * 4;
    const int t  = threadIdx.x;

    __shared__ __align__(16) float2 sh01[HH], sh23[HH];        // h packed (b0,b1),(b2,b3)
    __shared__ __align__(16) float2 sg01[4 * HH], sg23[4 * HH];
    __shared__ __align__(16) float2 sx01[LL * CC], sx23[LL * CC];

    // Packed weights in registers (duplicated halves)
    unsigned long long wihp[CC], whhp[HH];
#pragma unroll
    for (int k = 0; k < CC; k++) { float w = Wih[t * CC + k]; wihp[k] = pk2(w, w); }
#pragma unroll
    for (int k = 0; k < HH; k++) { float w = Whh[t * HH + k]; whhp[k] = pk2(w, w); }
    const float bias = bih[t] + bhh[t];

    // Stage x deltas (x - seq_last) packed by batch pair
    const float* xg = x_enc + (size_t)b0 * LL * CC;
    for (int i = t; i < LL * CC; i += 256) {
        int k = i & 7;
        float l0 = xg[760 + k], l1 = xg[768 + 760 + k];
        float l2 = xg[2 * 768 + 760 + k], l3 = xg[3 * 768 + 760 + k];
        sx01[i] = make_float2(xg[i] - l0, xg[768 + i] - l1);
        sx23[i] = make_float2(xg[2 * 768 + i] - l2, xg[3 * 768 + i] - l3);
    }
    if (t < HH) { sh01[t] = make_float2(0.f, 0.f); sh23[t] = make_float2(0.f, 0.f); }
    float c = 0.0f, hn = 0.0f;
    const int batch = t >> 6, j = t & 63;
    __syncthreads();

    for (int step = 0; step < LL; step++) {
        // gates: row t, 4 batches (2 packed chains)
        unsigned long long acc01 = pk2(bias, bias), acc23 = pk2(bias, bias);
        const unsigned long long* xp01 = (const unsigned long long*)(sx01 + step * CC);
        const unsigned long long* xp23 = (const unsigned long long*)(sx23 + step * CC);
#pragma unroll
        for (int k = 0; k < CC; k++) {
            FMA2(acc01, wihp[k], xp01[k]);
            FMA2(acc23, wihp[k], xp23[k]);
        }
        const ulonglong2* hp01 = (const ulonglong2*)sh01;
        const ulonglong2* hp23 = (const ulonglong2*)sh23;
#pragma unroll
        for (int k = 0; k < HH / 2; k++) {
            ulonglong2 h01 = hp01[k], h23 = hp23[k];
            FMA2(acc01, whhp[2 * k],     h01.x);
            FMA2(acc01, whhp[2 * k + 1], h01.y);
            FMA2(acc23, whhp[2 * k],     h23.x);
            FMA2(acc23, whhp[2 * k + 1], h23.y);
        }
        *(unsigned long long*)&sg01[t] = acc01;
        *(unsigned long long*)&sg23[t] = acc23;
        __syncthreads();

        // cell: thread = (batch, j)
        {
            const float2* sgA = (batch < 2) ? sg01 : sg23;
            const int hi = batch & 1;
            float gi = ((const float*)&sgA[j])[hi];
            float gf = ((const float*)&sgA[HH + j])[hi];
            float gg = ((const float*)&sgA[2 * HH + j])[hi];
            float go = ((const float*)&sgA[3 * HH + j])[hi];
            float ii = sigt(gi), ff = sigt(gf), oo = sigt(go);
            c = fmaf(ff, c, ii * tanha(gg));
            hn = oo * tanha(c);
            float2* shA = (batch < 2) ? sh01 : sh23;
            ((float*)&shA[j])[hi] = hn;
            g_enc_out[((size_t)(b0 + batch) * LL + step) * HH + j] = hn;
        }
        __syncthreads();
    }
    g_h0[(b0 + batch) * HH + j] = hn;
    g_c0[(b0 + batch) * HH + j] = c;
}

// ---------------------------------------------------------------------------
// Decoder: 2 batches/block, 256 threads. enc tiles + attn weights in SMEM
// (bank-skewed halves), comb weights in 32 regs/thread, gate weights in
// 128 regs/thread. All phases multi-accumulator.
// ---------------------------------------------------------------------------
struct __align__(16) DecSmem {
    float enc[2 * LL * HH];       // 12288 [b][l][h]
    float attnWA[64 * LL];        // 6144  [k<64][r]   (emb part)
    float padA[16];               // bank skew: +16 banks for B half
    float attnWB[64 * LL];        // 6144  [k>=64][r]  (h part)
    float embW[CC * HH];          // [k][j]
    float outW[HH * CC];          // [k][c]
    float attn_b[LL];
    float emb_b[HH];
    float comb_b[HH];
    float out_b[CC];
    float inp[2 * CC];
    float emb[2 * HH];
    float aw[2 * LL];
    float ctx[2 * HH];
    float comb[2 * HH];
    float h[2 * HH];
    float g[2 * 4 * HH];
    float inv[4];
};

__global__ __launch_bounds__(256, 1) void dec_kernel(
    const float* __restrict__ x_enc,
    const float* __restrict__ emb_W, const float* __restrict__ emb_b,
    const float* __restrict__ attn_W, const float* __restrict__ attn_b,
    const float* __restrict__ comb_W, const float* __restrict__ comb_b,
    const float* __restrict__ Wih, const float* __restrict__ Whh,
    const float* __restrict__ bih, const float* __restrict__ bhh,
    const float* __restrict__ out_W, const float* __restrict__ out_b,
    float* __restrict__ y)
{
    extern __shared__ float smem_raw[];
    DecSmem* s = reinterpret_cast<DecSmem*>(smem_raw);
    const int b0 = blockIdx.x * 2;
    const int t  = threadIdx.x;

    // Register weights: gate row t (both batches share), comb quarter-row.
    float wih[HH], whh[HH];
#pragma unroll
    for (int k = 0; k < HH; k += 4) {
        float4 v = *reinterpret_cast<const float4*>(Wih + t * HH + k);
        wih[k] = v.x; wih[k + 1] = v.y; wih[k + 2] = v.z; wih[k + 3] = v.w;
        float4 u = *reinterpret_cast<const float4*>(Whh + t * HH + k);
        whh[k] = u.x; whh[k + 1] = u.y; whh[k + 2] = u.z; whh[k + 3] = u.w;
    }
    const float bias = bih[t] + bhh[t];
    float cw[32];
    {
        const int j = t >> 2, q = t & 3;
#pragma unroll
        for (int i = 0; i < 32; i += 4) {
            float4 v = *reinterpret_cast<const float4*>(comb_W + j * 128 + q * 32 + i);
            cw[i] = v.x; cw[i + 1] = v.y; cw[i + 2] = v.z; cw[i + 3] = v.w;
        }
    }

    // Stage SMEM
    {
        const float4* eg = (const float4*)(g_enc_out + (size_t)b0 * LL * HH);
        float4* es = (float4*)s->enc;
        for (int i = t; i < 2 * LL * HH / 4; i += 256) es[i] = eg[i];
    }
    for (int i = t; i < LL * 128; i += 256) {
        int r = i >> 7, k = i & 127;
        float v = attn_W[i];
        if (k < 64) s->attnWA[k * LL + r] = v;
        else        s->attnWB[(k - 64) * LL + r] = v;
    }
    for (int i = t; i < CC * HH; i += 256) { int j = i >> 3, k = i & 7;  s->embW[k * HH + j] = emb_W[i]; }
    for (int i = t; i < HH * CC; i += 256) { int ci = i >> 6, k = i & 63; s->outW[k * CC + ci] = out_W[i]; }
    if (t < LL) s->attn_b[t] = attn_b[t];
    if (t < HH) { s->emb_b[t] = emb_b[t]; s->comb_b[t] = comb_b[t]; }
    if (t < CC) s->out_b[t] = out_b[t];
    if (t < 2 * HH) s->h[t] = g_h0[b0 * HH + t];
    if (t < 2 * CC) s->inp[t] = 0.0f;  // dec_in0 - seq_last == 0
    float cst = (t < 2 * HH) ? g_c0[b0 * HH + t] : 0.0f;
    float slast = 0.0f;
    if (t < 16) {
        int ba = t >> 3, cc = t & 7;
        slast = x_enc[(size_t)(b0 + ba) * LL * CC + (LL - 1) * CC + cc];
    }
    __syncthreads();

    for (int step = 0; step < TT; step++) {
        // 1) emb = relu(inp @ emb_W.T + emb_b)  (128 threads)
        if (t < 128) {
            int ba = t >> 6, j = t & 63;
            float e = s->emb_b[j];
#pragma unroll
            for (int k = 0; k < CC; k++) e = fmaf(s->embW[k * HH + j], s->inp[ba * CC + k], e);
            s->emb[ba * HH + j] = fmaxf(e, 0.0f);
        }
        __syncthreads();

        // 2) attn logits, 192 threads: (r, k-half), both batches per thread
        if (t < 192) {
            const int r = t >> 1, hf = t & 1;
            const float* W  = hf ? s->attnWB : s->attnWA;
            const float* v0 = hf ? s->h      : s->emb;        // batch 0
            const float* v1 = hf ? s->h + HH : s->emb + HH;   // batch 1
            float a0 = 0.f, c0 = 0.f, a1 = 0.f, c1 = 0.f;
#pragma unroll
            for (int k = 0; k < 64; k += 4) {
                float4 x0 = *(const float4*)(v0 + k);
                float4 x1 = *(const float4*)(v1 + k);
                float w0 = W[k * LL + r], w1 = W[(k + 1) * LL + r];
                float w2 = W[(k + 2) * LL + r], w3 = W[(k + 3) * LL + r];
                a0 = fmaf(w0, x0.x, a0); c0 = fmaf(w1, x0.y, c0);
                a0 = fmaf(w2, x0.z, a0); c0 = fmaf(w3, x0.w, c0);
                a1 = fmaf(w0, x1.x, a1); c1 = fmaf(w1, x1.y, c1);
                a1 = fmaf(w2, x1.z, a1); c1 = fmaf(w3, x1.w, c1);
            }
            float z0 = a0 + c0, z1 = a1 + c1;
            z0 += __shfl_xor_sync(0xffffffffu, z0, 1);
            z1 += __shfl_xor_sync(0xffffffffu, z1, 1);
            if (!hf) {
                float bz = s->attn_b[r];
                s->aw[r]      = z0 + bz;
                s->aw[LL + r] = z1 + bz;
            }
        }
        __syncthreads();

        // 3) softmax over 96 logits, one warp per batch
        if (t < 64) {
            int ba = t >> 5, ln = t & 31;
            float* awp = s->aw + ba * LL;
            float z0 = awp[ln], z1 = awp[ln + 32], z2 = awp[ln + 64];
            float m = fmaxf(z0, fmaxf(z1, z2));
#pragma unroll
            for (int o = 16; o; o >>= 1) m = fmaxf(m, __shfl_xor_sync(0xffffffffu, m, o));
            float e0 = __expf(z0 - m), e1 = __expf(z1 - m), e2 = __expf(z2 - m);
            awp[ln] = e0; awp[ln + 32] = e1; awp[ln + 64] = e2;
            float sum = e0 + e1 + e2;
#pragma unroll
            for (int o = 16; o; o >>= 1) sum += __shfl_xor_sync(0xffffffffu, sum, o);
            if (ln == 0) s->inv[ba] = 1.0f / sum;
        }
        __syncthreads();

        // 4) ctx[j] = sum_l aw[l] * enc[l][j]  (128 threads, 4 accs)
        if (t < 128) {
            int ba = t >> 6, j = t & 63;
            const float* e   = s->enc + ba * LL * HH;
            const float* awp = s->aw + ba * LL;
            float a = 0.f, b = 0.f, c2 = 0.f, d = 0.f;
#pragma unroll 6
            for (int l = 0; l < LL; l += 4) {
                float4 w4 = *(const float4*)(awp + l);
                a  = fmaf(w4.x, e[(l    ) * HH + j], a);
                b  = fmaf(w4.y, e[(l + 1) * HH + j], b);
                c2 = fmaf(w4.z, e[(l + 2) * HH + j], c2);
                d  = fmaf(w4.w, e[(l + 3) * HH + j], d);
            }
            s->ctx[ba * HH + j] = (a + b + c2 + d) * s->inv[ba];
        }
        __syncthreads();

        // 5) comb: quarter-rows in regs, all 256 threads, shuffle-reduce by 4
        {
            const int j = t >> 2, q = t & 3;
            const float* src0 = ((q < 2) ? s->emb : s->ctx) + (q & 1) * 32;  // batch 0
            const float* src1 = src0 + HH;                                    // batch 1
            float a0 = 0.f, b0_ = 0.f, a1 = 0.f, b1_ = 0.f;
#pragma unroll
            for (int i = 0; i < 32; i += 4) {
                float4 x0 = *(const float4*)(src0 + i);
                float4 x1 = *(const float4*)(src1 + i);
                a0  = fmaf(cw[i],     x0.x, a0);  b0_ = fmaf(cw[i + 1], x0.y, b0_);
                a0  = fmaf(cw[i + 2], x0.z, a0);  b0_ = fmaf(cw[i + 3], x0.w, b0_);
                a1  = fmaf(cw[i],     x1.x, a1);  b1_ = fmaf(cw[i + 1], x1.y, b1_);
                a1  = fmaf(cw[i + 2], x1.z, a1);  b1_ = fmaf(cw[i + 3], x1.w, b1_);
            }
            float z0 = a0 + b0_, z1 = a1 + b1_;
            z0 += __shfl_xor_sync(0xffffffffu, z0, 1);
            z0 += __shfl_xor_sync(0xffffffffu, z0, 2);
            z1 += __shfl_xor_sync(0xffffffffu, z1, 1);
            z1 += __shfl_xor_sync(0xffffffffu, z1, 2);
            if (q == 0) {
                float bz = s->comb_b[j];
                s->comb[j]      = z0 + bz;
                s->comb[HH + j] = z1 + bz;
            }
        }
        __syncthreads();

        // 6) LSTM gates: row t for both batches, register weights, 4 chains
        {
            float g0a = bias, g0b = 0.f, g1a = bias, g1b = 0.f;
#pragma unroll
            for (int k = 0; k < HH; k += 4) {
                float4 cb0 = *(const float4*)(s->comb + k);
                float4 cb1 = *(const float4*)(s->comb + HH + k);
                float4 hb0 = *(const float4*)(s->h + k);
                float4 hb1 = *(const float4*)(s->h + HH + k);
                g0a = fmaf(wih[k],     cb0.x, g0a); g0b = fmaf(wih[k + 1], cb0.y, g0b);
                g0a = fmaf(wih[k + 2], cb0.z, g0a); g0b = fmaf(wih[k + 3], cb0.w, g0b);
                g0a = fmaf(whh[k],     hb0.x, g0a); g0b = fmaf(whh[k + 1], hb0.y, g0b);
                g0a = fmaf(whh[k + 2], hb0.z, g0a); g0b = fmaf(whh[k + 3], hb0.w, g0b);
                g1a = fmaf(wih[k],     cb1.x, g1a); g1b = fmaf(wih[k + 1], cb1.y, g1b);
                g1a = fmaf(wih[k + 2], cb1.z, g1a); g1b = fmaf(wih[k + 3], cb1.w, g1b);
                g1a = fmaf(whh[k],     hb1.x, g1a); g1b = fmaf(whh[k + 1], hb1.y, g1b);
                g1a = fmaf(whh[k + 2], hb1.z, g1a); g1b = fmaf(whh[k + 3], hb1.w, g1b);
            }
            s->g[t]       = g0a + g0b;
            s->g[256 + t] = g1a + g1b;
        }
        __syncthreads();

        // 7) cell update (128 threads)
        if (t < 128) {
            int ba = t >> 6, j = t & 63;
            const float* gp = s->g + ba * 256;
            float ii = sigt(gp[j]);
            float ff = sigt(gp[HH + j]);
            float gg = tanha(gp[2 * HH + j]);
            float oo = sigt(gp[3 * HH + j]);
            cst = fmaf(ff, cst, ii * gg);
            s->h[ba * HH + j] = oo * tanha(cst);
        }
        __syncthreads();

        // 8) pred = h @ out_W.T + out_b; feedback + output (16 threads)
        if (t < 16) {
            int ba = t >> 3, cc = t & 7;
            const float* hp = s->h + ba * HH;
            float a = 0.f, b = 0.f, c2 = 0.f, d = 0.f;
#pragma unroll
            for (int k = 0; k < HH; k += 4) {
                a  = fmaf(s->outW[(k    ) * CC + cc], hp[k],     a);
                b  = fmaf(s->outW[(k + 1) * CC + cc], hp[k + 1], b);
                c2 = fmaf(s->outW[(k + 2) * CC + cc], hp[k + 2], c2);
                d  = fmaf(s->outW[(k + 3) * CC + cc], hp[k + 3], d);
            }
            float p = a + b + c2 + d + s->out_b[cc];
            s->inp[ba * CC + cc] = p;
            y[((size_t)(b0 + ba) * TT + step) * CC + cc] = p + slast;
        }
        __syncthreads();
    }
}

extern "C" void kernel_launch(void* const* d_in, const int* in_sizes, int n_in,
                              void* d_out, int out_size)
{
    const float* x_enc   = (const float*)d_in[0];
    const float* enc_Wih = (const float*)d_in[4];
    const float* enc_Whh = (const float*)d_in[5];
    const float* enc_bih = (const float*)d_in[6];
    const float* enc_bhh = (const float*)d_in[7];
    const float* emb_W   = (const float*)d_in[8];
    const float* emb_b   = (const float*)d_in[9];
    const float* attn_W  = (const float*)d_in[10];
    const float* attn_b  = (const float*)d_in[11];
    const float* comb_W  = (const float*)d_in[12];
    const float* comb_b  = (const float*)d_in[13];
    const float* dec_Wih = (const float*)d_in[14];
    const float* dec_Whh = (const float*)d_in[15];
    const float* dec_bih = (const float*)d_in[16];
    const float* dec_bhh = (const float*)d_in[17];
    const float* out_W   = (const float*)d_in[18];
    const float* out_b   = (const float*)d_in[19];
    float* y = (float*)d_out;

    cudaFuncSetAttribute(dec_kernel, cudaFuncAttributeMaxDynamicSharedMemorySize,
                         (int)sizeof(DecSmem));

    enc_kernel<<<BB / 4, 256>>>(x_enc, enc_Wih, enc_Whh, enc_bih, enc_bhh);
    dec_kernel<<<BB / 2, 256, sizeof(DecSmem)>>>(x_enc, emb_W, emb_b, attn_W, attn_b,
                                                 comb_W, comb_b, dec_Wih, dec_Whh,
                                                 dec_bih, dec_bhh, out_W, out_b, y);
}

// round 4
// speedup vs baseline: 1.7960x; 1.0574x over previous
#include <cuda_runtime.h>

#define HH 64
#define CC 8
#define LL 96
#define TT 24
#define BB 4096

// Scratch (device globals — no allocations allowed).
// Batch-pair packed: g_enc_pk[bpair][l][j] = (enc[2p][l][j], enc[2p+1][l][j])
__device__ float2 g_enc_pk[(size_t)(BB / 2) * LL * HH];  // ~100 MB
__device__ float2 g_h0_pk[(BB / 2) * HH];
__device__ float2 g_c0_pk[(BB / 2) * HH];

__device__ __forceinline__ float tanha(float x) {
    float r; asm("tanh.approx.f32 %0, %1;" : "=f"(r) : "f"(x)); return r;
}
__device__ __forceinline__ float sigt(float x) {
    return fmaf(tanha(x * 0.5f), 0.5f, 0.5f);
}
__device__ __forceinline__ unsigned long long pk2(float a, float b) {
    unsigned long long r; asm("mov.b64 %0, {%1, %2};" : "=l"(r) : "f"(a), "f"(b)); return r;
}
__device__ __forceinline__ float2 upk(unsigned long long v) {
    float2 r; asm("mov.b64 {%0, %1}, %2;" : "=f"(r.x), "=f"(r.y) : "l"(v)); return r;
}
#define FMA2(acc, a, b) asm("fma.rn.f32x2 %0, %1, %2, %0;" : "+l"(acc) : "l"(a), "l"(b))

// ---------------------------------------------------------------------------
// Encoder: 8 batches/block (4 packed pairs), 256 threads = 256 gate rows.
// ---------------------------------------------------------------------------
__global__ __launch_bounds__(256, 1) void enc_kernel(
    const float* __restrict__ x_enc,
    const float* __restrict__ Wih, const float* __restrict__ Whh,
    const float* __restrict__ bih, const float* __restrict__ bhh)
{
    const int t = threadIdx.x;
    const size_t b0 = (size_t)blockIdx.x * 8;

    __shared__ __align__(16) float2 sx[4][LL * CC];
    __shared__ __align__(16) float2 sh[4][HH];
    __shared__ __align__(16) float2 sg[4][4 * HH];

    unsigned long long wihp[CC], whhp[HH];
#pragma unroll
    for (int k = 0; k < CC; k++) { float w = Wih[t * CC + k]; wihp[k] = pk2(w, w); }
#pragma unroll
    for (int k = 0; k < HH; k++) { float w = Whh[t * HH + k]; whhp[k] = pk2(w, w); }
    const float bias = bih[t] + bhh[t];

#pragma unroll
    for (int p = 0; p < 4; p++) {
        const float* xa = x_enc + (b0 + 2 * p) * (LL * CC);
        const float* xb = xa + LL * CC;
        for (int i = t; i < LL * CC; i += 256) {
            int k = i & 7;
            sx[p][i] = make_float2(xa[i] - xa[(LL - 1) * CC + k],
                                   xb[i] - xb[(LL - 1) * CC + k]);
        }
    }
    if (t < HH) {
#pragma unroll
        for (int p = 0; p < 4; p++) sh[p][t] = make_float2(0.f, 0.f);
    }
    const int pc = t >> 6, j = t & 63;
    float2 c = make_float2(0.f, 0.f), hn = c;
    __syncthreads();

    for (int step = 0; step < LL; step++) {
        unsigned long long acc0 = pk2(bias, bias), acc1 = acc0, acc2 = acc0, acc3 = acc0;
        {
            const unsigned long long* x0 = (const unsigned long long*)(sx[0] + step * CC);
            const unsigned long long* x1 = (const unsigned long long*)(sx[1] + step * CC);
            const unsigned long long* x2 = (const unsigned long long*)(sx[2] + step * CC);
            const unsigned long long* x3 = (const unsigned long long*)(sx[3] + step * CC);
#pragma unroll
            for (int k = 0; k < CC; k++) {
                FMA2(acc0, wihp[k], x0[k]);
                FMA2(acc1, wihp[k], x1[k]);
                FMA2(acc2, wihp[k], x2[k]);
                FMA2(acc3, wihp[k], x3[k]);
            }
        }
        {
            const ulonglong2* h0 = (const ulonglong2*)sh[0];
            const ulonglong2* h1 = (const ulonglong2*)sh[1];
            const ulonglong2* h2 = (const ulonglong2*)sh[2];
            const ulonglong2* h3 = (const ulonglong2*)sh[3];
#pragma unroll 8
            for (int k = 0; k < HH / 2; k++) {
                ulonglong2 v0 = h0[k], v1 = h1[k], v2 = h2[k], v3 = h3[k];
                FMA2(acc0, whhp[2 * k], v0.x); FMA2(acc0, whhp[2 * k + 1], v0.y);
                FMA2(acc1, whhp[2 * k], v1.x); FMA2(acc1, whhp[2 * k + 1], v1.y);
                FMA2(acc2, whhp[2 * k], v2.x); FMA2(acc2, whhp[2 * k + 1], v2.y);
                FMA2(acc3, whhp[2 * k], v3.x); FMA2(acc3, whhp[2 * k + 1], v3.y);
            }
        }
        *(unsigned long long*)&sg[0][t] = acc0;
        *(unsigned long long*)&sg[1][t] = acc1;
        *(unsigned long long*)&sg[2][t] = acc2;
        *(unsigned long long*)&sg[3][t] = acc3;
        __syncthreads();

        {
            float2 gi = sg[pc][j], gf = sg[pc][HH + j];
            float2 gg = sg[pc][2 * HH + j], go = sg[pc][3 * HH + j];
            float ix = sigt(gi.x), iy = sigt(gi.y);
            float fx = sigt(gf.x), fy = sigt(gf.y);
            float gx = tanha(gg.x), gy = tanha(gg.y);
            float ox = sigt(go.x), oy = sigt(go.y);
            c.x = fmaf(fx, c.x, ix * gx);
            c.y = fmaf(fy, c.y, iy * gy);
            hn.x = ox * tanha(c.x);
            hn.y = oy * tanha(c.y);
            sh[pc][j] = hn;
            g_enc_pk[((size_t)(blockIdx.x * 4 + pc) * LL + step) * HH + j] = hn;
        }
        __syncthreads();
    }
    g_h0_pk[(blockIdx.x * 4 + pc) * HH + j] = hn;
    g_c0_pk[(blockIdx.x * 4 + pc) * HH + j] = c;
}

// ---------------------------------------------------------------------------
// Decoder: 4 batches/block (2 packed pairs), 256 threads.
// ---------------------------------------------------------------------------
struct __align__(16) DecSmem {
    float2 enc[2][LL * HH];     // 98304 B, [pair][l*HH+j]
    float attnWA[64 * LL];      // [k<64][r]
    float padA[16];
    float attnWB[64 * LL];      // [k>=64][r]
    float combWA[64 * HH];      // [k<64][j]
    float padC[16];
    float combWB[64 * HH];      // [k>=64][j]
    float embW[CC * HH];        // [k][j]
    float outW[HH * CC];        // [k][c]
    float attn_b[LL];
    float emb_b[HH];
    float comb_b[HH];
    float out_b[CC];
    float2 inp[2][CC];
    float2 emb[2][HH];
    float2 aw[2][LL];
    float2 ctx[2][HH];
    float2 comb[2][HH];
    float2 h[2][HH];
    float2 g[2][4 * HH];
    float inv[4];
};

__global__ __launch_bounds__(256, 1) void dec_kernel(
    const float* __restrict__ x_enc,
    const float* __restrict__ emb_W, const float* __restrict__ emb_b,
    const float* __restrict__ attn_W, const float* __restrict__ attn_b,
    const float* __restrict__ comb_W, const float* __restrict__ comb_b,
    const float* __restrict__ Wih, const float* __restrict__ Whh,
    const float* __restrict__ bih, const float* __restrict__ bhh,
    const float* __restrict__ out_W, const float* __restrict__ out_b,
    float* __restrict__ y)
{
    extern __shared__ float smem_raw[];
    DecSmem* s = reinterpret_cast<DecSmem*>(smem_raw);
    const int t = threadIdx.x;
    const int b0 = blockIdx.x * 4;       // 4 batches
    const int bp0 = blockIdx.x * 2;      // 2 batch pairs

    // Gate weights in registers (row t, shared across all 4 batches)
    float wih[HH], whh[HH];
#pragma unroll
    for (int k = 0; k < HH; k += 4) {
        float4 v = *reinterpret_cast<const float4*>(Wih + t * HH + k);
        wih[k] = v.x; wih[k + 1] = v.y; wih[k + 2] = v.z; wih[k + 3] = v.w;
        float4 u = *reinterpret_cast<const float4*>(Whh + t * HH + k);
        whh[k] = u.x; whh[k + 1] = u.y; whh[k + 2] = u.z; whh[k + 3] = u.w;
    }
    const float bias = bih[t] + bhh[t];

    // Stage SMEM
    {
        const float4* eg = (const float4*)(g_enc_pk + (size_t)bp0 * LL * HH);
        float4* es = (float4*)s->enc;
        for (int i = t; i < 2 * LL * HH / 2; i += 256) es[i] = eg[i];
    }
    for (int i = t; i < LL * 128; i += 256) {
        int r = i >> 7, k = i & 127;
        float v = attn_W[i];
        if (k < 64) s->attnWA[k * LL + r] = v;
        else        s->attnWB[(k - 64) * LL + r] = v;
    }
    for (int i = t; i < HH * 128; i += 256) {
        int j = i >> 7, k = i & 127;
        float v = comb_W[i];
        if (k < 64) s->combWA[k * HH + j] = v;
        else        s->combWB[(k - 64) * HH + j] = v;
    }
    for (int i = t; i < CC * HH; i += 256) { int j = i >> 3, k = i & 7;   s->embW[k * HH + j]  = emb_W[i]; }
    for (int i = t; i < HH * CC; i += 256) { int ci = i >> 6, k = i & 63; s->outW[k * CC + ci] = out_W[i]; }
    if (t < LL) s->attn_b[t] = attn_b[t];
    if (t < HH) { s->emb_b[t] = emb_b[t]; s->comb_b[t] = comb_b[t]; }
    if (t < CC) s->out_b[t] = out_b[t];

    float2 cst = make_float2(0.f, 0.f);
    if (t < 128) {
        int p = t >> 6, j = t & 63;
        s->h[p][j] = g_h0_pk[(bp0 + p) * HH + j];
        cst = g_c0_pk[(bp0 + p) * HH + j];
    }
    float slast = 0.0f;
    if (t < 32) {
        int ba = t >> 3, cc = t & 7;
        int p = ba >> 1, lane = ba & 1;
        ((float*)&s->inp[p][cc])[lane] = 0.0f;  // dec_in0 - seq_last == 0
        slast = x_enc[(size_t)(b0 + ba) * LL * CC + (LL - 1) * CC + cc];
    }
    __syncthreads();

    for (int step = 0; step < TT; step++) {
        // 1) emb = relu(inp @ emb_W.T + emb_b)   (128 threads, packed pairs)
        if (t < 128) {
            const int p = t >> 6, j = t & 63;
            float ex = s->emb_b[j], ey = ex;
#pragma unroll
            for (int k = 0; k < CC; k++) {
                float w = s->embW[k * HH + j];
                float2 x = s->inp[p][k];
                ex = fmaf(w, x.x, ex);
                ey = fmaf(w, x.y, ey);
            }
            s->emb[p][j] = make_float2(fmaxf(ex, 0.f), fmaxf(ey, 0.f));
        }
        __syncthreads();

        // 2) attn logits: 192 threads = (r, k-half), 4 batches each
        if (t < 192) {
            const int r = t >> 1, hf = t & 1;
            const float*  W  = hf ? s->attnWB : s->attnWA;
            const float2* xa = hf ? s->h[0]   : s->emb[0];
            const float2* xb = hf ? s->h[1]   : s->emb[1];
            float a0 = 0.f, a1 = 0.f, a2 = 0.f, a3 = 0.f;
#pragma unroll 8
            for (int k = 0; k < 64; k += 2) {
                float w0 = W[k * LL + r], w1 = W[(k + 1) * LL + r];
                float4 x01 = *(const float4*)&xa[k];
                float4 x23 = *(const float4*)&xb[k];
                a0 = fmaf(w0, x01.x, a0); a0 = fmaf(w1, x01.z, a0);
                a1 = fmaf(w0, x01.y, a1); a1 = fmaf(w1, x01.w, a1);
                a2 = fmaf(w0, x23.x, a2); a2 = fmaf(w1, x23.z, a2);
                a3 = fmaf(w0, x23.y, a3); a3 = fmaf(w1, x23.w, a3);
            }
            a0 += __shfl_xor_sync(0xffffffffu, a0, 1);
            a1 += __shfl_xor_sync(0xffffffffu, a1, 1);
            a2 += __shfl_xor_sync(0xffffffffu, a2, 1);
            a3 += __shfl_xor_sync(0xffffffffu, a3, 1);
            if (!hf) {
                float bz = s->attn_b[r];
                s->aw[0][r] = make_float2(a0 + bz, a1 + bz);
                s->aw[1][r] = make_float2(a2 + bz, a3 + bz);
            }
        }
        __syncthreads();

        // 3) softmax: 4 warps, one per batch (strided component reads)
        if (t < 128) {
            const int ba = t >> 5, ln = t & 31;
            float* awf = (float*)s->aw[ba >> 1] + (ba & 1);
            float z0 = awf[2 * ln], z1 = awf[2 * (ln + 32)], z2 = awf[2 * (ln + 64)];
            float m = fmaxf(z0, fmaxf(z1, z2));
#pragma unroll
            for (int o = 16; o; o >>= 1) m = fmaxf(m, __shfl_xor_sync(0xffffffffu, m, o));
            float e0 = __expf(z0 - m), e1 = __expf(z1 - m), e2 = __expf(z2 - m);
            awf[2 * ln] = e0; awf[2 * (ln + 32)] = e1; awf[2 * (ln + 64)] = e2;
            float sum = e0 + e1 + e2;
#pragma unroll
            for (int o = 16; o; o >>= 1) sum += __shfl_xor_sync(0xffffffffu, sum, o);
            if (ln == 0) s->inv[ba] = 1.0f / sum;
        }
        __syncthreads();

        // 4) ctx: packed fma.f32x2 (128 threads)
        if (t < 128) {
            const int p = t >> 6, j = t & 63;
            const unsigned long long* ep = (const unsigned long long*)&s->enc[p][0];
            const ulonglong2* awp = (const ulonglong2*)&s->aw[p][0];
            unsigned long long acc2a = 0ull, acc2b = 0ull;
#pragma unroll 8
            for (int l = 0; l < LL; l += 2) {
                ulonglong2 av = awp[l >> 1];
                FMA2(acc2a, av.x, ep[l * HH + j]);
                FMA2(acc2b, av.y, ep[(l + 1) * HH + j]);
            }
            float2 A = upk(acc2a), Bv = upk(acc2b);
            s->ctx[p][j] = make_float2((A.x + Bv.x) * s->inv[2 * p],
                                       (A.y + Bv.y) * s->inv[2 * p + 1]);
        }
        __syncthreads();

        // 5) comb: 256 threads = (p*64+j, k-half), shuffle-reduce
        {
            const int r = t >> 1, kh = t & 1;
            const int p = r >> 6, j = r & 63;
            const float*  W = kh ? s->combWB : s->combWA;
            const float2* X = kh ? s->ctx[p] : s->emb[p];
            float a0 = 0.f, a1 = 0.f, b0_ = 0.f, b1_ = 0.f;
#pragma unroll 8
            for (int k = 0; k < 64; k += 2) {
                float w0 = W[k * HH + j], w1 = W[(k + 1) * HH + j];
                float4 x = *(const float4*)&X[k];
                a0  = fmaf(w0, x.x, a0);  a1  = fmaf(w0, x.y, a1);
                b0_ = fmaf(w1, x.z, b0_); b1_ = fmaf(w1, x.w, b1_);
            }
            a0 += b0_; a1 += b1_;
            a0 += __shfl_xor_sync(0xffffffffu, a0, 1);
            a1 += __shfl_xor_sync(0xffffffffu, a1, 1);
            if (!kh) {
                float bz = s->comb_b[j];
                s->comb[p][j] = make_float2(a0 + bz, a1 + bz);
            }
        }
        __syncthreads();

        // 6) LSTM gates: row t, 4 batches, register weights
        {
            float g0 = bias, g1 = bias, g2 = bias, g3 = bias;
#pragma unroll 8
            for (int j2 = 0; j2 < HH; j2 += 2) {
                float4 c01 = *(const float4*)&s->comb[0][j2];
                float4 c23 = *(const float4*)&s->comb[1][j2];
                float4 h01 = *(const float4*)&s->h[0][j2];
                float4 h23 = *(const float4*)&s->h[1][j2];
                float w0 = wih[j2], w1 = wih[j2 + 1];
                float u0 = whh[j2], u1 = whh[j2 + 1];
                g0 = fmaf(w0, c01.x, g0); g0 = fmaf(w1, c01.z, g0);
                g0 = fmaf(u0, h01.x, g0); g0 = fmaf(u1, h01.z, g0);
                g1 = fmaf(w0, c01.y, g1); g1 = fmaf(w1, c01.w, g1);
                g1 = fmaf(u0, h01.y, g1); g1 = fmaf(u1, h01.w, g1);
                g2 = fmaf(w0, c23.x, g2); g2 = fmaf(w1, c23.z, g2);
                g2 = fmaf(u0, h23.x, g2); g2 = fmaf(u1, h23.z, g2);
                g3 = fmaf(w0, c23.y, g3); g3 = fmaf(w1, c23.w, g3);
                g3 = fmaf(u0, h23.y, g3); g3 = fmaf(u1, h23.w, g3);
            }
            s->g[0][t] = make_float2(g0, g1);
            s->g[1][t] = make_float2(g2, g3);
        }
        __syncthreads();

        // 7) cell update: 128 threads, packed pairs
        if (t < 128) {
            const int p = t >> 6, j = t & 63;
            float2 gi = s->g[p][j], gf = s->g[p][HH + j];
            float2 gg = s->g[p][2 * HH + j], go = s->g[p][3 * HH + j];
            float ix = sigt(gi.x), iy = sigt(gi.y);
            float fx = sigt(gf.x), fy = sigt(gf.y);
            float gx = tanha(gg.x), gy = tanha(gg.y);
            float ox = sigt(go.x), oy = sigt(go.y);
            cst.x = fmaf(fx, cst.x, ix * gx);
            cst.y = fmaf(fy, cst.y, iy * gy);
            s->h[p][j] = make_float2(ox * tanha(cst.x), oy * tanha(cst.y));
        }
        __syncthreads();

        // 8) pred + feedback + output: 32 threads = (batch, channel)
        if (t < 32) {
            const int ba = t >> 3, cc = t & 7;
            const int p = ba >> 1, lane = ba & 1;
            const float* hp = (const float*)&s->h[p][0] + lane;
            float a = 0.f, b = 0.f, c2 = 0.f, d = 0.f;
#pragma unroll
            for (int k = 0; k < HH; k += 4) {
                a  = fmaf(s->outW[(k    ) * CC + cc], hp[2 * k],     a);
                b  = fmaf(s->outW[(k + 1) * CC + cc], hp[2 * k + 2], b);
                c2 = fmaf(s->outW[(k + 2) * CC + cc], hp[2 * k + 4], c2);
                d  = fmaf(s->outW[(k + 3) * CC + cc], hp[2 * k + 6], d);
            }
            float pv = a + b + c2 + d + s->out_b[cc];
            ((float*)&s->inp[p][cc])[lane] = pv;
            y[((size_t)(b0 + ba) * TT + step) * CC + cc] = pv + slast;
        }
        __syncthreads();
    }
}

extern "C" void kernel_launch(void* const* d_in, const int* in_sizes, int n_in,
                              void* d_out, int out_size)
{
    const float* x_enc   = (const float*)d_in[0];
    const float* enc_Wih = (const float*)d_in[4];
    const float* enc_Whh = (const float*)d_in[5];
    const float* enc_bih = (const float*)d_in[6];
    const float* enc_bhh = (const float*)d_in[7];
    const float* emb_W   = (const float*)d_in[8];
    const float* emb_b   = (const float*)d_in[9];
    const float* attn_W  = (const float*)d_in[10];
    const float* attn_b  = (const float*)d_in[11];
    const float* comb_W  = (const float*)d_in[12];
    const float* comb_b  = (const float*)d_in[13];
    const float* dec_Wih = (const float*)d_in[14];
    const float* dec_Whh = (const float*)d_in[15];
    const float* dec_bih = (const float*)d_in[16];
    const float* dec_bhh = (const float*)d_in[17];
    const float* out_W   = (const float*)d_in[18];
    const float* out_b   = (const float*)d_in[19];
    float* y = (float*)d_out;

    cudaFuncSetAttribute(dec_kernel, cudaFuncAttributeMaxDynamicSharedMemorySize,
                         (int)sizeof(DecSmem));

    enc_kernel<<<BB / 8, 256>>>(x_enc, enc_Wih, enc_Whh, enc_bih, enc_bhh);
    dec_kernel<<<BB / 4, 256, sizeof(DecSmem)>>>(x_enc, emb_W, emb_b, attn_W, attn_b,
                                                 comb_W, comb_b, dec_Wih, dec_Whh,
                                                 dec_bih, dec_bhh, out_W, out_b, y);
}

// round 5
// speedup vs baseline: 1.8846x; 1.0493x over previous
#include <cuda_runtime.h>
#include <cuda_fp16.h>

#define HH 64
#define CC 8
#define LL 96
#define TT 24
#define BB 4096

// Scratch (device globals — no allocations allowed)
__device__ __half2 g_enc_h2[(size_t)(BB / 2) * LL * HH];  // ~50 MB, batch-pair packed
__device__ float2 g_h0_pk[(BB / 2) * HH];
__device__ float2 g_c0_pk[(BB / 2) * HH];

__device__ __forceinline__ float tanha(float x) {
    float r; asm("tanh.approx.f32 %0, %1;" : "=f"(r) : "f"(x)); return r;
}
__device__ __forceinline__ float sigt(float x) {
    return fmaf(tanha(x * 0.5f), 0.5f, 0.5f);
}
__device__ __forceinline__ unsigned long long pk2(float a, float b) {
    unsigned long long r; asm("mov.b64 %0, {%1, %2};" : "=l"(r) : "f"(a), "f"(b)); return r;
}
__device__ __forceinline__ float2 upk(unsigned long long v) {
    float2 r; asm("mov.b64 {%0, %1}, %2;" : "=f"(r.x), "=f"(r.y) : "l"(v)); return r;
}
#define FMA2(acc, a, b) asm("fma.rn.f32x2 %0, %1, %2, %0;" : "+l"(acc) : "l"(a), "l"(b))

// skewed index within a 64-entry state row (sections of 32 offset by +2)
#define SIDX(j)  ((j) + 2 * ((j) >> 5))
#define ST 68          // float2 stride of state rows
#define ENCROW 65      // half2 stride of enc rows

// ---------------------------------------------------------------------------
// Encoder: 512 threads, 8 batches (4 packed pairs). thread = (row r, k-half).
// ---------------------------------------------------------------------------
__global__ __launch_bounds__(512, 1) void enc_kernel(
    const float* __restrict__ x_enc,
    const float* __restrict__ Wih, const float* __restrict__ Whh,
    const float* __restrict__ bih, const float* __restrict__ bhh)
{
    const int t = threadIdx.x;
    const int r = t >> 1, kh = t & 1;
    const size_t b0 = (size_t)blockIdx.x * 8;
    const int bp0 = blockIdx.x * 4;

    __shared__ __align__(16) float2 sx[4][LL * CC];
    __shared__ __align__(16) float2 sh[4][ST];
    __shared__ __align__(16) float2 sg[4][4 * HH];

    unsigned long long wihp[4], whhp[32];
#pragma unroll
    for (int k = 0; k < 4; k++) { float w = Wih[r * CC + kh * 4 + k]; wihp[k] = pk2(w, w); }
#pragma unroll
    for (int k = 0; k < 32; k++) { float w = Whh[r * HH + kh * 32 + k]; whhp[k] = pk2(w, w); }
    const float bias = bih[r] + bhh[r];
    const unsigned long long binit = kh ? pk2(0.f, 0.f) : pk2(bias, bias);

    // Stage x deltas packed by batch pair
#pragma unroll
    for (int p = 0; p < 4; p++) {
        const float* xa = x_enc + (b0 + 2 * p) * (LL * CC);
        const float* xb = xa + LL * CC;
        for (int i = t; i < LL * CC; i += 512) {
            int k = i & 7;
            sx[p][i] = make_float2(xa[i] - xa[(LL - 1) * CC + k],
                                   xb[i] - xb[(LL - 1) * CC + k]);
        }
    }
    if (t < 256) {
        int p = t >> 6, j = t & 63;
        sh[p][SIDX(j)] = make_float2(0.f, 0.f);
    }
    const int pc = (t < 256) ? (t >> 6) : 0, jc = t & 63;
    float2 c2 = make_float2(0.f, 0.f), hn2 = c2;
    __syncthreads();

    for (int step = 0; step < LL; step++) {
        unsigned long long a0 = binit, a1 = binit, a2 = binit, a3 = binit;
        {
            // x part: 4 ks of this k-half
            const int xo = step * CC + kh * 4;
#pragma unroll
            for (int p = 0; p < 4; p++) {
                unsigned long long* acc = (p == 0) ? &a0 : (p == 1) ? &a1 : (p == 2) ? &a2 : &a3;
                const ulonglong2* xp = (const ulonglong2*)&sx[p][xo];
                ulonglong2 v0 = xp[0], v1 = xp[1];
                FMA2(*acc, wihp[0], v0.x); FMA2(*acc, wihp[1], v0.y);
                FMA2(*acc, wihp[2], v1.x); FMA2(*acc, wihp[3], v1.y);
            }
        }
        {
            const int hb = kh * 34;
#pragma unroll 8
            for (int kk = 0; kk < 16; kk++) {
                unsigned long long w0 = whhp[2 * kk], w1 = whhp[2 * kk + 1];
                ulonglong2 v0 = *(const ulonglong2*)&sh[0][hb + 2 * kk];
                ulonglong2 v1 = *(const ulonglong2*)&sh[1][hb + 2 * kk];
                ulonglong2 v2 = *(const ulonglong2*)&sh[2][hb + 2 * kk];
                ulonglong2 v3 = *(const ulonglong2*)&sh[3][hb + 2 * kk];
                FMA2(a0, w0, v0.x); FMA2(a0, w1, v0.y);
                FMA2(a1, w0, v1.x); FMA2(a1, w1, v1.y);
                FMA2(a2, w0, v2.x); FMA2(a2, w1, v2.y);
                FMA2(a3, w0, v3.x); FMA2(a3, w1, v3.y);
            }
        }
        {
            float2 f0 = upk(a0), f1 = upk(a1), f2 = upk(a2), f3 = upk(a3);
            f0.x += __shfl_xor_sync(0xffffffffu, f0.x, 1);
            f0.y += __shfl_xor_sync(0xffffffffu, f0.y, 1);
            f1.x += __shfl_xor_sync(0xffffffffu, f1.x, 1);
            f1.y += __shfl_xor_sync(0xffffffffu, f1.y, 1);
            f2.x += __shfl_xor_sync(0xffffffffu, f2.x, 1);
            f2.y += __shfl_xor_sync(0xffffffffu, f2.y, 1);
            f3.x += __shfl_xor_sync(0xffffffffu, f3.x, 1);
            f3.y += __shfl_xor_sync(0xffffffffu, f3.y, 1);
            if (!kh) {
                sg[0][r] = f0; sg[1][r] = f1; sg[2][r] = f2; sg[3][r] = f3;
            }
        }
        __syncthreads();

        if (t < 256) {
            float2 gi = sg[pc][jc], gf = sg[pc][HH + jc];
            float2 gg = sg[pc][2 * HH + jc], go = sg[pc][3 * HH + jc];
            float ix = sigt(gi.x), iy = sigt(gi.y);
            float fx = sigt(gf.x), fy = sigt(gf.y);
            float gx = tanha(gg.x), gy = tanha(gg.y);
            float ox = sigt(go.x), oy = sigt(go.y);
            c2.x = fmaf(fx, c2.x, ix * gx);
            c2.y = fmaf(fy, c2.y, iy * gy);
            hn2.x = ox * tanha(c2.x);
            hn2.y = oy * tanha(c2.y);
            sh[pc][SIDX(jc)] = hn2;
            g_enc_h2[((size_t)(bp0 + pc) * LL + step) * HH + jc] = __float22half2_rn(hn2);
        }
        __syncthreads();
    }
    if (t < 256) {
        g_h0_pk[(bp0 + pc) * HH + jc] = hn2;
        g_c0_pk[(bp0 + pc) * HH + jc] = c2;
    }
}

// ---------------------------------------------------------------------------
// Decoder: 512 threads, 8 batches/block (4 packed pairs).
// ---------------------------------------------------------------------------
struct __align__(16) DecSmem {
    __half2 enc2[4][LL * ENCROW];  // 99840 B
    float attnW[128 * LL];         // 49152 B [k][r]
    float combWA[64 * HH];         // [k][j], k<64 (emb)
    float padc[16];
    float combWB[64 * HH];         // [k][j], k>=64 (ctx)
    float embW[CC * HH];           // [k][j]
    float outW[HH * CC];           // [k][c]
    float attn_b[LL];
    float comb_b[HH];
    float emb_b[HH];
    float out_b[CC];
    float2 inp[4][CC];
    float2 emb[4][ST];
    float2 h[4][ST];
    float2 ctx[4][ST];
    float2 comb[4][ST];
    float2 aw[4][LL];
    __half2 aw2[4][LL];
    float2 g[4][4 * HH];
};  // ~208.6 KB

__global__ __launch_bounds__(512, 1) void dec_kernel(
    const float* __restrict__ x_enc,
    const float* __restrict__ emb_W, const float* __restrict__ emb_b,
    const float* __restrict__ attn_W, const float* __restrict__ attn_b,
    const float* __restrict__ comb_W, const float* __restrict__ comb_b,
    const float* __restrict__ Wih, const float* __restrict__ Whh,
    const float* __restrict__ bih, const float* __restrict__ bhh,
    const float* __restrict__ out_W, const float* __restrict__ out_b,
    float* __restrict__ y)
{
    extern __shared__ float smem_raw[];
    DecSmem* s = reinterpret_cast<DecSmem*>(smem_raw);
    const int t = threadIdx.x;
    const int b0 = blockIdx.x * 8;
    const int bp0 = blockIdx.x * 4;

    // Gate weights: row r = t>>1, k-half kh = t&1
    const int r = t >> 1, kh = t & 1;
    float wih[32], whh[32];
#pragma unroll
    for (int k = 0; k < 32; k += 4) {
        float4 v = *reinterpret_cast<const float4*>(Wih + r * HH + kh * 32 + k);
        wih[k] = v.x; wih[k + 1] = v.y; wih[k + 2] = v.z; wih[k + 3] = v.w;
        float4 u = *reinterpret_cast<const float4*>(Whh + r * HH + kh * 32 + k);
        whh[k] = u.x; whh[k + 1] = u.y; whh[k + 2] = u.z; whh[k + 3] = u.w;
    }
    const float bias = bih[r] + bhh[r];

    // ---- Stage SMEM ----
#pragma unroll
    for (int p = 0; p < 4; p++) {
        const __half2* eg = g_enc_h2 + (size_t)(bp0 + p) * (LL * HH);
        for (int i = t; i < LL * HH; i += 512)
            s->enc2[p][(i >> 6) * ENCROW + (i & 63)] = eg[i];
    }
    for (int i = t; i < LL * 128; i += 512) {
        int rr = i >> 7, k = i & 127;
        s->attnW[k * LL + rr] = attn_W[i];
    }
    for (int i = t; i < HH * 128; i += 512) {
        int j = i >> 7, k = i & 127;
        float v = comb_W[i];
        if (k < 64) s->combWA[k * HH + j] = v;
        else        s->combWB[(k - 64) * HH + j] = v;
    }
    for (int i = t; i < CC * HH; i += 512) { int j = i >> 3, k = i & 7;   s->embW[k * HH + j]  = emb_W[i]; }
    for (int i = t; i < HH * CC; i += 512) { int ci = i >> 6, k = i & 63; s->outW[k * CC + ci] = out_W[i]; }
    if (t < LL) s->attn_b[t] = attn_b[t];
    if (t < HH) { s->emb_b[t] = emb_b[t]; s->comb_b[t] = comb_b[t]; }
    if (t < CC) s->out_b[t] = out_b[t];

    float2 cst = make_float2(0.f, 0.f);
    if (t < 256) {
        int p = t >> 6, j = t & 63;
        s->h[p][SIDX(j)] = g_h0_pk[(bp0 + p) * HH + j];
        cst = g_c0_pk[(bp0 + p) * HH + j];
    }
    float slast = 0.0f;
    if (t < 64) {
        int ba = t >> 3, cc = t & 7;
        int p = ba >> 1, c = ba & 1;
        ((float*)&s->inp[p][cc])[c] = 0.0f;  // dec_in0 - seq_last == 0
        slast = x_enc[(size_t)(b0 + ba) * LL * CC + (LL - 1) * CC + cc];
    }
    __syncthreads();

    for (int step = 0; step < TT; step++) {
        // 1) emb = relu(inp @ emb_W.T + emb_b)  (256 threads)
        if (t < 256) {
            const int p = t >> 6, j = t & 63;
            float ex = s->emb_b[j], ey = ex;
#pragma unroll
            for (int k = 0; k < CC; k++) {
                float w = s->embW[k * HH + j];
                float2 x = s->inp[p][k];
                ex = fmaf(w, x.x, ex);
                ey = fmaf(w, x.y, ey);
            }
            s->emb[p][SIDX(j)] = make_float2(fmaxf(ex, 0.f), fmaxf(ey, 0.f));
        }
        __syncthreads();

        // 2) attn logits: 384 threads = (r, pair), fp32
        if (t < 384) {
            const int rr = t >> 2, pq = t & 3;
            const float* E = (const float*)&s->emb[pq][0];
            const float* H = (const float*)&s->h[pq][0];
            float a0 = 0.f, a1 = 0.f, b0v = 0.f, b1v = 0.f;
#pragma unroll 8
            for (int kk = 0; kk < 32; kk++) {
                const int fo = 4 * kk + ((kk >= 16) ? 4 : 0);
                float4 x = *(const float4*)(E + fo);
                float w0 = s->attnW[(2 * kk) * LL + rr];
                float w1 = s->attnW[(2 * kk + 1) * LL + rr];
                a0  = fmaf(w0, x.x, a0);  a1  = fmaf(w0, x.y, a1);
                b0v = fmaf(w1, x.z, b0v); b1v = fmaf(w1, x.w, b1v);
            }
#pragma unroll 8
            for (int kk = 0; kk < 32; kk++) {
                const int fo = 4 * kk + ((kk >= 16) ? 4 : 0);
                float4 x = *(const float4*)(H + fo);
                float w0 = s->attnW[(64 + 2 * kk) * LL + rr];
                float w1 = s->attnW[(64 + 2 * kk + 1) * LL + rr];
                a0  = fmaf(w0, x.x, a0);  a1  = fmaf(w0, x.y, a1);
                b0v = fmaf(w1, x.z, b0v); b1v = fmaf(w1, x.w, b1v);
            }
            float bz = s->attn_b[rr];
            s->aw[pq][rr] = make_float2(a0 + b0v + bz, a1 + b1v + bz);
        }
        __syncthreads();

        // 3) softmax: 8 warps (one per batch); writes normalized half into aw2
        if (t < 256) {
            const int ba = t >> 5, ln = t & 31;
            const int p = ba >> 1, c = ba & 1;
            const float* awf = (const float*)&s->aw[p][0] + c;
            float z0 = awf[2 * ln], z1 = awf[2 * (ln + 32)], z2 = awf[2 * (ln + 64)];
            float m = fmaxf(z0, fmaxf(z1, z2));
#pragma unroll
            for (int o = 16; o; o >>= 1) m = fmaxf(m, __shfl_xor_sync(0xffffffffu, m, o));
            float e0 = __expf(z0 - m), e1 = __expf(z1 - m), e2 = __expf(z2 - m);
            float sum = e0 + e1 + e2;
#pragma unroll
            for (int o = 16; o; o >>= 1) sum += __shfl_xor_sync(0xffffffffu, sum, o);
            float inv = 1.0f / sum;
            __half* dst = (__half*)&s->aw2[p][0] + c;
            dst[2 * ln]        = __float2half_rn(e0 * inv);
            dst[2 * (ln + 32)] = __float2half_rn(e1 * inv);
            dst[2 * (ln + 64)] = __float2half_rn(e2 * inv);
        }
        __syncthreads();

        // 4) ctx: 512 threads = (p, j, l-half), HFMA2
        {
            const int p = t >> 7, j = (t >> 1) & 63, lh = t & 1;
            const __half2* erow = &s->enc2[p][0];
            const __half2* awp  = &s->aw2[p][0];
            __half2 acc0 = __float2half2_rn(0.f), acc1 = acc0;
            const int lb = lh * 48;
#pragma unroll 8
            for (int li = 0; li < 48; li += 2) {
                acc0 = __hfma2(awp[lb + li],     erow[(lb + li) * ENCROW + j],     acc0);
                acc1 = __hfma2(awp[lb + li + 1], erow[(lb + li + 1) * ENCROW + j], acc1);
            }
            acc0 = __hadd2(acc0, acc1);
            unsigned int u = *(unsigned int*)&acc0;
            unsigned int v = __shfl_xor_sync(0xffffffffu, u, 1);
            acc0 = __hadd2(acc0, *(__half2*)&v);
            if (!lh) s->ctx[p][SIDX(j)] = __half22float2(acc0);
        }
        __syncthreads();

        // 5) comb: 512 threads = (p, j, k-half), fp32, shuffle reduce
        {
            const int p = t >> 7, j = (t >> 1) & 63, kh2 = t & 1;
            const float* W = kh2 ? s->combWB : s->combWA;
            const float* X = (const float*)(kh2 ? &s->ctx[p][0] : &s->emb[p][0]);
            float a0 = 0.f, a1 = 0.f, b0v = 0.f, b1v = 0.f;
#pragma unroll 8
            for (int kk = 0; kk < 32; kk++) {
                const int fo = 4 * kk + ((kk >= 16) ? 4 : 0);
                float4 x = *(const float4*)(X + fo);
                float w0 = W[(2 * kk) * HH + j], w1 = W[(2 * kk + 1) * HH + j];
                a0  = fmaf(w0, x.x, a0);  a1  = fmaf(w0, x.y, a1);
                b0v = fmaf(w1, x.z, b0v); b1v = fmaf(w1, x.w, b1v);
            }
            float z0 = a0 + b0v, z1 = a1 + b1v;
            z0 += __shfl_xor_sync(0xffffffffu, z0, 1);
            z1 += __shfl_xor_sync(0xffffffffu, z1, 1);
            if (!kh2) {
                float bz = s->comb_b[j];
                s->comb[p][SIDX(j)] = make_float2(z0 + bz, z1 + bz);
            }
        }
        __syncthreads();

        // 6) LSTM gates: 512 threads = (row r, k-half kh), packed f32x2
        {
            unsigned long long acc0, acc1, acc2, acc3;
            acc0 = kh ? pk2(0.f, 0.f) : pk2(bias, bias);
            acc1 = acc0; acc2 = acc0; acc3 = acc0;
            const int base = kh * 34;
#pragma unroll 8
            for (int kk = 0; kk < 16; kk++) {
                unsigned long long w0 = pk2(wih[2 * kk], wih[2 * kk]);
                unsigned long long w1 = pk2(wih[2 * kk + 1], wih[2 * kk + 1]);
                unsigned long long u0 = pk2(whh[2 * kk], whh[2 * kk]);
                unsigned long long u1 = pk2(whh[2 * kk + 1], whh[2 * kk + 1]);
                ulonglong2 c0 = *(const ulonglong2*)&s->comb[0][base + 2 * kk];
                ulonglong2 h0 = *(const ulonglong2*)&s->h[0][base + 2 * kk];
                FMA2(acc0, w0, c0.x); FMA2(acc0, w1, c0.y);
                FMA2(acc0, u0, h0.x); FMA2(acc0, u1, h0.y);
                ulonglong2 c1 = *(const ulonglong2*)&s->comb[1][base + 2 * kk];
                ulonglong2 h1 = *(const ulonglong2*)&s->h[1][base + 2 * kk];
                FMA2(acc1, w0, c1.x); FMA2(acc1, w1, c1.y);
                FMA2(acc1, u0, h1.x); FMA2(acc1, u1, h1.y);
                ulonglong2 cc2 = *(const ulonglong2*)&s->comb[2][base + 2 * kk];
                ulonglong2 h2 = *(const ulonglong2*)&s->h[2][base + 2 * kk];
                FMA2(acc2, w0, cc2.x); FMA2(acc2, w1, cc2.y);
                FMA2(acc2, u0, h2.x); FMA2(acc2, u1, h2.y);
                ulonglong2 c3 = *(const ulonglong2*)&s->comb[3][base + 2 * kk];
                ulonglong2 h3 = *(const ulonglong2*)&s->h[3][base + 2 * kk];
                FMA2(acc3, w0, c3.x); FMA2(acc3, w1, c3.y);
                FMA2(acc3, u0, h3.x); FMA2(acc3, u1, h3.y);
            }
            float2 f0 = upk(acc0), f1 = upk(acc1), f2 = upk(acc2), f3 = upk(acc3);
            f0.x += __shfl_xor_sync(0xffffffffu, f0.x, 1);
            f0.y += __shfl_xor_sync(0xffffffffu, f0.y, 1);
            f1.x += __shfl_xor_sync(0xffffffffu, f1.x, 1);
            f1.y += __shfl_xor_sync(0xffffffffu, f1.y, 1);
            f2.x += __shfl_xor_sync(0xffffffffu, f2.x, 1);
            f2.y += __shfl_xor_sync(0xffffffffu, f2.y, 1);
            f3.x += __shfl_xor_sync(0xffffffffu, f3.x, 1);
            f3.y += __shfl_xor_sync(0xffffffffu, f3.y, 1);
            if (!kh) {
                s->g[0][r] = f0; s->g[1][r] = f1; s->g[2][r] = f2; s->g[3][r] = f3;
            }
        }
        __syncthreads();

        // 7) cell update: 256 threads
        if (t < 256) {
            const int p = t >> 6, j = t & 63;
            float2 gi = s->g[p][j], gf = s->g[p][HH + j];
            float2 gg = s->g[p][2 * HH + j], go = s->g[p][3 * HH + j];
            float ix = sigt(gi.x), iy = sigt(gi.y);
            float fx = sigt(gf.x), fy = sigt(gf.y);
            float gx = tanha(gg.x), gy = tanha(gg.y);
            float ox = sigt(go.x), oy = sigt(go.y);
            cst.x = fmaf(fx, cst.x, ix * gx);
            cst.y = fmaf(fy, cst.y, iy * gy);
            s->h[p][SIDX(j)] = make_float2(ox * tanha(cst.x), oy * tanha(cst.y));
        }
        __syncthreads();

        // 8) pred + feedback + output: 64 threads = (batch, channel)
        if (t < 64) {
            const int ba = t >> 3, cc = t & 7;
            const int p = ba >> 1, c = ba & 1;
            const float* hp = (const float*)&s->h[p][0] + c;
            float a = 0.f, b = 0.f, c2v = 0.f, d = 0.f;
#pragma unroll
            for (int k = 0; k < HH; k += 4) {
                a   = fmaf(s->outW[(k    ) * CC + cc], hp[2 * SIDX(k)],     a);
                b   = fmaf(s->outW[(k + 1) * CC + cc], hp[2 * SIDX(k + 1)], b);
                c2v = fmaf(s->outW[(k + 2) * CC + cc], hp[2 * SIDX(k + 2)], c2v);
                d   = fmaf(s->outW[(k + 3) * CC + cc], hp[2 * SIDX(k + 3)], d);
            }
            float pv = a + b + c2v + d + s->out_b[cc];
            ((float*)&s->inp[p][cc])[c] = pv;
            y[((size_t)(b0 + ba) * TT + step) * CC + cc] = pv + slast;
        }
        __syncthreads();
    }
}

extern "C" void kernel_launch(void* const* d_in, const int* in_sizes, int n_in,
                              void* d_out, int out_size)
{
    const float* x_enc   = (const float*)d_in[0];
    const float* enc_Wih = (const float*)d_in[4];
    const float* enc_Whh = (const float*)d_in[5];
    const float* enc_bih = (const float*)d_in[6];
    const float* enc_bhh = (const float*)d_in[7];
    const float* emb_W   = (const float*)d_in[8];
    const float* emb_b   = (const float*)d_in[9];
    const float* attn_W  = (const float*)d_in[10];
    const float* attn_b  = (const float*)d_in[11];
    const float* comb_W  = (const float*)d_in[12];
    const float* comb_b  = (const float*)d_in[13];
    const float* dec_Wih = (const float*)d_in[14];
    const float* dec_Whh = (const float*)d_in[15];
    const float* dec_bih = (const float*)d_in[16];
    const float* dec_bhh = (const float*)d_in[17];
    const float* out_W   = (const float*)d_in[18];
    const float* out_b   = (const float*)d_in[19];
    float* y = (float*)d_out;

    cudaFuncSetAttribute(dec_kernel, cudaFuncAttributeMaxDynamicSharedMemorySize,
                         (int)sizeof(DecSmem));

    enc_kernel<<<BB / 8, 512>>>(x_enc, enc_Wih, enc_Whh, enc_bih, enc_bhh);
    dec_kernel<<<BB / 8, 512, sizeof(DecSmem)>>>(x_enc, emb_W, emb_b, attn_W, attn_b,
                                                 comb_W, comb_b, dec_Wih, dec_Whh,
                                                 dec_bih, dec_bhh, out_W, out_b, y);
}

// round 6
// speedup vs baseline: 7.1268x; 3.7815x over previous
#include <cuda_runtime.h>
#include <cuda_fp16.h>

#define HH 64
#define CC 8
#define LL 96
#define TT 24
#define BB 4096
#define ENB 32   // encoder batches per block
#define DNB 8    // decoder batches per block

// Scratch (device globals — no allocations allowed)
__device__ __half2 g_enc_h2[(size_t)(BB / 2) * LL * HH];  // batch-pair packed fp16
__device__ float2 g_h0_pk[(BB / 2) * HH];
__device__ float2 g_c0_pk[(BB / 2) * HH];

__device__ __forceinline__ float tanha(float x) {
    float r; asm("tanh.approx.f32 %0, %1;" : "=f"(r) : "f"(x)); return r;
}
__device__ __forceinline__ float sigt(float x) {
    return fmaf(tanha(x * 0.5f), 0.5f, 0.5f);
}
__device__ __forceinline__ unsigned h2u(float x, float y) {
    __half2 h = __floats2half2_rn(x, y);
    return *reinterpret_cast<unsigned*>(&h);
}
__device__ __forceinline__ void mma16816(
    float& d0, float& d1, float& d2, float& d3,
    unsigned a0, unsigned a1, unsigned a2, unsigned a3,
    unsigned b0, unsigned b1)
{
    asm volatile(
        "mma.sync.aligned.m16n8k16.row.col.f32.f16.f16.f32 "
        "{%0,%1,%2,%3}, {%4,%5,%6,%7}, {%8,%9}, {%0,%1,%2,%3};"
        : "+f"(d0), "+f"(d1), "+f"(d2), "+f"(d3)
        : "r"(a0), "r"(a1), "r"(a2), "r"(a3), "r"(b0), "r"(b1));
}

// ---------------------------------------------------------------------------
// Encoder: 32 batches/block, grid = 128 (one wave). Gates via HMMA.
// K layout: [h(0..63) ; x(64..71) ; pad(72..79)] -> 5 k16 tiles.
// ---------------------------------------------------------------------------
struct __align__(16) EncSmem {
    __half xT[ENB][776];   // x deltas fp16, [n][step*8+c], padded stride
    __half hT[ENB][72];    // h fp16, [n][k], padded stride
    float  sg[256][34];    // gate pre-activations [row][n], padded stride
    float  bias[256];
};

__global__ __launch_bounds__(512, 1) void enc_kernel(
    const float* __restrict__ x_enc,
    const float* __restrict__ Wih, const float* __restrict__ Whh,
    const float* __restrict__ bih, const float* __restrict__ bhh)
{
    extern __shared__ char smem_raw[];
    EncSmem* s = reinterpret_cast<EncSmem*>(smem_raw);
    const int t = threadIdx.x;
    const int wid = t >> 5, lane = t & 31;
    const int g4 = lane >> 2, tig = lane & 3;
    const size_t b0 = (size_t)blockIdx.x * ENB;
    const int bp0 = blockIdx.x * (ENB / 2);

    // A fragments: rows 16*wid .. 16*wid+15, 5 k-tiles, packed fp16, in regs forever.
    unsigned A[5][4];
    {
        const int r0 = 16 * wid + g4;
#pragma unroll
        for (int kt = 0; kt < 5; kt++) {
            const int c0 = 16 * kt + 2 * tig;
#pragma unroll
            for (int half_ = 0; half_ < 4; half_++) {
                const int rr = r0 + ((half_ & 1) ? 8 : 0);
                const int cc = c0 + ((half_ & 2) ? 8 : 0);
                float w0, w1;
                // W(r,c): c<64 -> Whh[r][c]; c<72 -> Wih[r][c-64]; else 0
                w0 = (cc < 64) ? Whh[rr * 64 + cc] : ((cc < 72) ? Wih[rr * 8 + cc - 64] : 0.f);
                w1 = (cc + 1 < 64) ? Whh[rr * 64 + cc + 1] : ((cc + 1 < 72) ? Wih[rr * 8 + cc + 1 - 64] : 0.f);
                A[kt][half_] = h2u(w0, w1);
            }
        }
    }
    if (t < 256) s->bias[t] = bih[t] + bhh[t];

    // Stage xT (x - seq_last) fp16, zero hT
    for (int i = t; i < ENB * 768; i += 512) {
        int n = i / 768, idx = i % 768, c = idx & 7;
        const float* xb = x_enc + (b0 + n) * 768;
        s->xT[n][idx] = __float2half_rn(xb[idx] - xb[760 + c]);
    }
    for (int i = t; i < ENB * 72; i += 512) ((__half*)s->hT)[i] = __ushort_as_half(0);
    __syncthreads();

    const int jc = t & 63, qc = t >> 6;   // cell: thread -> (j, batch group 4qc..4qc+3)
    float cs0 = 0.f, cs1 = 0.f, cs2 = 0.f, cs3 = 0.f;
    float h0r = 0.f, h1r = 0.f, h2r = 0.f, h3r = 0.f;

    for (int step = 0; step < LL; step++) {
        // ---- gates via MMA: D[256 x 32] ----
        float d[4][4];
#pragma unroll
        for (int nt = 0; nt < 4; nt++) { d[nt][0] = d[nt][1] = d[nt][2] = d[nt][3] = 0.f; }
#pragma unroll
        for (int nt = 0; nt < 4; nt++) {
            const __half* hrow = s->hT[nt * 8 + g4];
#pragma unroll
            for (int kt = 0; kt < 4; kt++) {
                unsigned bf0 = *(const unsigned*)&hrow[16 * kt + 2 * tig];
                unsigned bf1 = *(const unsigned*)&hrow[16 * kt + 2 * tig + 8];
                mma16816(d[nt][0], d[nt][1], d[nt][2], d[nt][3],
                         A[kt][0], A[kt][1], A[kt][2], A[kt][3], bf0, bf1);
            }
            unsigned bx = *(const unsigned*)&s->xT[nt * 8 + g4][step * 8 + 2 * tig];
            mma16816(d[nt][0], d[nt][1], d[nt][2], d[nt][3],
                     A[4][0], A[4][1], A[4][2], A[4][3], bx, 0u);
        }
        {
            const int r0 = 16 * wid + g4;
#pragma unroll
            for (int nt = 0; nt < 4; nt++) {
                const int cidx = nt * 8 + 2 * tig;
                *(float2*)&s->sg[r0][cidx]     = make_float2(d[nt][0], d[nt][1]);
                *(float2*)&s->sg[r0 + 8][cidx] = make_float2(d[nt][2], d[nt][3]);
            }
        }
        __syncthreads();

        // ---- cell: 4 batches per thread ----
        {
            float2 giA = *(const float2*)&s->sg[jc][4 * qc];
            float2 giB = *(const float2*)&s->sg[jc][4 * qc + 2];
            float2 gfA = *(const float2*)&s->sg[64 + jc][4 * qc];
            float2 gfB = *(const float2*)&s->sg[64 + jc][4 * qc + 2];
            float2 ggA = *(const float2*)&s->sg[128 + jc][4 * qc];
            float2 ggB = *(const float2*)&s->sg[128 + jc][4 * qc + 2];
            float2 goA = *(const float2*)&s->sg[192 + jc][4 * qc];
            float2 goB = *(const float2*)&s->sg[192 + jc][4 * qc + 2];
            float bi = s->bias[jc], bf = s->bias[64 + jc];
            float bg = s->bias[128 + jc], bo = s->bias[192 + jc];

            float i0 = sigt(giA.x + bi), i1 = sigt(giA.y + bi), i2 = sigt(giB.x + bi), i3 = sigt(giB.y + bi);
            float f0 = sigt(gfA.x + bf), f1 = sigt(gfA.y + bf), f2 = sigt(gfB.x + bf), f3 = sigt(gfB.y + bf);
            float t0 = tanha(ggA.x + bg), t1 = tanha(ggA.y + bg), t2 = tanha(ggB.x + bg), t3 = tanha(ggB.y + bg);
            float o0 = sigt(goA.x + bo), o1 = sigt(goA.y + bo), o2 = sigt(goB.x + bo), o3 = sigt(goB.y + bo);
            cs0 = fmaf(f0, cs0, i0 * t0); cs1 = fmaf(f1, cs1, i1 * t1);
            cs2 = fmaf(f2, cs2, i2 * t2); cs3 = fmaf(f3, cs3, i3 * t3);
            h0r = o0 * tanha(cs0); h1r = o1 * tanha(cs1);
            h2r = o2 * tanha(cs2); h3r = o3 * tanha(cs3);

            s->hT[4 * qc + 0][jc] = __float2half_rn(h0r);
            s->hT[4 * qc + 1][jc] = __float2half_rn(h1r);
            s->hT[4 * qc + 2][jc] = __float2half_rn(h2r);
            s->hT[4 * qc + 3][jc] = __float2half_rn(h3r);
            g_enc_h2[((size_t)(bp0 + 2 * qc) * LL + step) * HH + jc]     = __floats2half2_rn(h0r, h1r);
            g_enc_h2[((size_t)(bp0 + 2 * qc + 1) * LL + step) * HH + jc] = __floats2half2_rn(h2r, h3r);
        }
        __syncthreads();
    }
    g_h0_pk[(bp0 + 2 * qc) * HH + jc]     = make_float2(h0r, h1r);
    g_h0_pk[(bp0 + 2 * qc + 1) * HH + jc] = make_float2(h2r, h3r);
    g_c0_pk[(bp0 + 2 * qc) * HH + jc]     = make_float2(cs0, cs1);
    g_c0_pk[(bp0 + 2 * qc + 1) * HH + jc] = make_float2(cs2, cs3);
}

// ---------------------------------------------------------------------------
// Decoder: 8 batches/block, grid = 512. attn/comb/gates via HMMA.
// ---------------------------------------------------------------------------
struct __align__(16) DecSmem {
    __half2 enc2[4][LL * HH];   // 98304 B, enc_out fp16 pairs
    __half  abT[DNB][136];      // attn B: [emb(0..63); h(64..127)]
    __half  cbT[DNB][136];      // comb B: [emb; ctx]
    __half  gbT[DNB][136];      // gates B: [comb; h]
    __half2 aw2[4][98];         // normalized softmax weights (pair-packed)
    float   awl[96][10];        // raw attn logits [l][n]
    float   sg[256][10];        // gate pre-acts [row][n]
    float   inp[DNB][CC];
    float   embW[CC][HH];       // [k][j]
    float   outWsm[CC][HH];     // [c][k]
    float   biasg[256];
    float   attn_bS[LL];
    float   comb_bS[HH];
    float   emb_bS[HH];
    float   out_bS[CC];
};

__global__ __launch_bounds__(512, 1) void dec_kernel(
    const float* __restrict__ x_enc,
    const float* __restrict__ emb_W, const float* __restrict__ emb_b,
    const float* __restrict__ attn_W, const float* __restrict__ attn_b,
    const float* __restrict__ comb_W, const float* __restrict__ comb_b,
    const float* __restrict__ Wih, const float* __restrict__ Whh,
    const float* __restrict__ bih, const float* __restrict__ bhh,
    const float* __restrict__ out_W, const float* __restrict__ out_b,
    float* __restrict__ y)
{
    extern __shared__ char smem_raw[];
    DecSmem* s = reinterpret_cast<DecSmem*>(smem_raw);
    const int t = threadIdx.x;
    const int wid = t >> 5, lane = t & 31;
    const int g4 = lane >> 2, tig = lane & 3;
    const int b0 = blockIdx.x * DNB;
    const int bp0 = blockIdx.x * (DNB / 2);

    // ---- A fragments in registers ----
    unsigned Ag[8][4];   // gates: all warps, rows 16*wid..
    unsigned Ax[8][4] = {};  // attn (wid<6) or comb (6<=wid<10)
    {
        const int r0 = 16 * wid + g4;
#pragma unroll
        for (int kt = 0; kt < 8; kt++) {
            const int c0 = 16 * kt + 2 * tig;
#pragma unroll
            for (int h_ = 0; h_ < 4; h_++) {
                const int rr = r0 + ((h_ & 1) ? 8 : 0);
                const int cc = c0 + ((h_ & 2) ? 8 : 0);
                // gates: k<64 -> Wih (input = comb), k>=64 -> Whh (hidden)
                float w0 = (cc < 64) ? Wih[rr * 64 + cc] : Whh[rr * 64 + cc - 64];
                float w1 = (cc + 1 < 64) ? Wih[rr * 64 + cc + 1] : Whh[rr * 64 + cc + 1 - 64];
                Ag[kt][h_] = h2u(w0, w1);
            }
        }
        if (wid < 6) {
            const int ra = 16 * wid + g4;
#pragma unroll
            for (int kt = 0; kt < 8; kt++) {
                const int c0 = 16 * kt + 2 * tig;
#pragma unroll
                for (int h_ = 0; h_ < 4; h_++) {
                    const int rr = ra + ((h_ & 1) ? 8 : 0);
                    const int cc = c0 + ((h_ & 2) ? 8 : 0);
                    Ax[kt][h_] = h2u(attn_W[rr * 128 + cc], attn_W[rr * 128 + cc + 1]);
                }
            }
        } else if (wid < 10) {
            const int rc = 16 * (wid - 6) + g4;
#pragma unroll
            for (int kt = 0; kt < 8; kt++) {
                const int c0 = 16 * kt + 2 * tig;
#pragma unroll
                for (int h_ = 0; h_ < 4; h_++) {
                    const int rr = rc + ((h_ & 1) ? 8 : 0);
                    const int cc = c0 + ((h_ & 2) ? 8 : 0);
                    Ax[kt][h_] = h2u(comb_W[rr * 128 + cc], comb_W[rr * 128 + cc + 1]);
                }
            }
        }
    }

    // ---- Stage SMEM ----
#pragma unroll
    for (int p = 0; p < 4; p++) {
        const float4* eg = (const float4*)(g_enc_h2 + (size_t)(bp0 + p) * (LL * HH));
        float4* es = (float4*)&s->enc2[p][0];
        for (int i = t; i < LL * HH / 4; i += 512) es[i] = eg[i];
    }
    for (int i = t; i < CC * HH; i += 512) { int j = i >> 3, k = i & 7; s->embW[k][j] = emb_W[i]; }
    for (int i = t; i < CC * HH; i += 512) ((float*)s->outWsm)[i] = out_W[i];  // same [c][k] layout
    if (t < 256) s->biasg[t] = bih[t] + bhh[t];
    if (t < LL) s->attn_bS[t] = attn_b[t];
    if (t < HH) { s->comb_bS[t] = comb_b[t]; s->emb_bS[t] = emb_b[t]; }
    if (t < CC) s->out_bS[t] = out_b[t];

    float2 cst = make_float2(0.f, 0.f);
    if (t < 256) {
        const int p = t >> 6, j = t & 63;
        float2 h0 = g_h0_pk[(bp0 + p) * HH + j];
        cst = g_c0_pk[(bp0 + p) * HH + j];
        __half hx = __float2half_rn(h0.x), hy = __float2half_rn(h0.y);
        s->abT[2 * p][64 + j] = hx; s->abT[2 * p + 1][64 + j] = hy;
        s->gbT[2 * p][64 + j] = hx; s->gbT[2 * p + 1][64 + j] = hy;
    }
    float slast = 0.f;
    if (t < 64) {
        const int ba = t >> 3, cc = t & 7;
        s->inp[ba][cc] = 0.f;   // dec_in0 - seq_last == 0
        slast = x_enc[(size_t)(b0 + ba) * LL * CC + (LL - 1) * CC + cc];
    }
    __syncthreads();

    for (int step = 0; step < TT; step++) {
        // 1) emb = relu(inp @ emb_W.T + b) -> abT, cbT (512 threads)
        {
            const int n = t >> 6, j = t & 63;
            float e = s->emb_bS[j];
#pragma unroll
            for (int k = 0; k < CC; k++) e = fmaf(s->embW[k][j], s->inp[n][k], e);
            __half he = __float2half_rn(fmaxf(e, 0.f));
            s->abT[n][j] = he;
            s->cbT[n][j] = he;
        }
        __syncthreads();

        // 2) attn logits via MMA (warps 0-5)
        if (wid < 6) {
            const __half* brow = s->abT[g4];
            float d0 = 0.f, d1 = 0.f, d2 = 0.f, d3 = 0.f;
#pragma unroll
            for (int kt = 0; kt < 8; kt++) {
                unsigned bf0 = *(const unsigned*)&brow[16 * kt + 2 * tig];
                unsigned bf1 = *(const unsigned*)&brow[16 * kt + 2 * tig + 8];
                mma16816(d0, d1, d2, d3, Ax[kt][0], Ax[kt][1], Ax[kt][2], Ax[kt][3], bf0, bf1);
            }
            const int r0 = 16 * wid + g4;
            *(float2*)&s->awl[r0][2 * tig]     = make_float2(d0, d1);
            *(float2*)&s->awl[r0 + 8][2 * tig] = make_float2(d2, d3);
        }
        __syncthreads();

        // 3) softmax (warps 0-7, one batch each) -> normalized fp16 pair-packed aw2
        if (wid < 8) {
            const int n = wid, p = n >> 1, comp = n & 1;
            float z0 = s->awl[lane][n]      + s->attn_bS[lane];
            float z1 = s->awl[lane + 32][n] + s->attn_bS[lane + 32];
            float z2 = s->awl[lane + 64][n] + s->attn_bS[lane + 64];
            float m = fmaxf(z0, fmaxf(z1, z2));
#pragma unroll
            for (int o = 16; o; o >>= 1) m = fmaxf(m, __shfl_xor_sync(0xffffffffu, m, o));
            float e0 = __expf(z0 - m), e1 = __expf(z1 - m), e2 = __expf(z2 - m);
            float sum = e0 + e1 + e2;
#pragma unroll
            for (int o = 16; o; o >>= 1) sum += __shfl_xor_sync(0xffffffffu, sum, o);
            float inv = 1.0f / sum;
            __half* dst = (__half*)&s->aw2[p][0] + comp;
            dst[2 * lane]        = __float2half_rn(e0 * inv);
            dst[2 * (lane + 32)] = __float2half_rn(e1 * inv);
            dst[2 * (lane + 64)] = __float2half_rn(e2 * inv);
        }
        __syncthreads();

        // 4) ctx: HFMA2 over enc2 (512 threads = pair x j x l-half) -> cbT
        {
            const int p = t >> 7, j = (t >> 1) & 63, lh = t & 1;
            const __half2* erow = &s->enc2[p][0];
            const __half2* awp = &s->aw2[p][0];
            __half2 acc0 = __float2half2_rn(0.f), acc1 = acc0;
            const int lb = lh * 48;
#pragma unroll 8
            for (int li = 0; li < 48; li += 2) {
                acc0 = __hfma2(awp[lb + li],     erow[(lb + li) * HH + j],     acc0);
                acc1 = __hfma2(awp[lb + li + 1], erow[(lb + li + 1) * HH + j], acc1);
            }
            acc0 = __hadd2(acc0, acc1);
            unsigned u = *(unsigned*)&acc0;
            unsigned v = __shfl_xor_sync(0xffffffffu, u, 1);
            acc0 = __hadd2(acc0, *(__half2*)&v);
            if (!lh) {
                s->cbT[2 * p][64 + j]     = __low2half(acc0);
                s->cbT[2 * p + 1][64 + j] = __high2half(acc0);
            }
        }
        __syncthreads();

        // 5) comb via MMA (warps 6-9) -> gbT (fp16, +bias)
        if (wid >= 6 && wid < 10) {
            const __half* brow = s->cbT[g4];
            float d0 = 0.f, d1 = 0.f, d2 = 0.f, d3 = 0.f;
#pragma unroll
            for (int kt = 0; kt < 8; kt++) {
                unsigned bf0 = *(const unsigned*)&brow[16 * kt + 2 * tig];
                unsigned bf1 = *(const unsigned*)&brow[16 * kt + 2 * tig + 8];
                mma16816(d0, d1, d2, d3, Ax[kt][0], Ax[kt][1], Ax[kt][2], Ax[kt][3], bf0, bf1);
            }
            const int r0 = 16 * (wid - 6) + g4;
            float cb0 = s->comb_bS[r0], cb8 = s->comb_bS[r0 + 8];
            s->gbT[2 * tig][r0]         = __float2half_rn(d0 + cb0);
            s->gbT[2 * tig + 1][r0]     = __float2half_rn(d1 + cb0);
            s->gbT[2 * tig][r0 + 8]     = __float2half_rn(d2 + cb8);
            s->gbT[2 * tig + 1][r0 + 8] = __float2half_rn(d3 + cb8);
        }
        __syncthreads();

        // 6) gates via MMA (all 16 warps) -> sg
        {
            const __half* brow = s->gbT[g4];
            float d0 = 0.f, d1 = 0.f, d2 = 0.f, d3 = 0.f;
#pragma unroll
            for (int kt = 0; kt < 8; kt++) {
                unsigned bf0 = *(const unsigned*)&brow[16 * kt + 2 * tig];
                unsigned bf1 = *(const unsigned*)&brow[16 * kt + 2 * tig + 8];
                mma16816(d0, d1, d2, d3, Ag[kt][0], Ag[kt][1], Ag[kt][2], Ag[kt][3], bf0, bf1);
            }
            const int r0 = 16 * wid + g4;
            *(float2*)&s->sg[r0][2 * tig]     = make_float2(d0, d1);
            *(float2*)&s->sg[r0 + 8][2 * tig] = make_float2(d2, d3);
        }
        __syncthreads();

        // 7) cell update (256 threads = pair x j)
        if (t < 256) {
            const int p = t >> 6, j = t & 63;
            float2 gi = *(const float2*)&s->sg[j][2 * p];
            float2 gf = *(const float2*)&s->sg[64 + j][2 * p];
            float2 gg = *(const float2*)&s->sg[128 + j][2 * p];
            float2 go = *(const float2*)&s->sg[192 + j][2 * p];
            float bi = s->biasg[j], bf = s->biasg[64 + j];
            float bg = s->biasg[128 + j], bo = s->biasg[192 + j];
            float ix = sigt(gi.x + bi), iy = sigt(gi.y + bi);
            float fx = sigt(gf.x + bf), fy = sigt(gf.y + bf);
            float gx = tanha(gg.x + bg), gy = tanha(gg.y + bg);
            float ox = sigt(go.x + bo), oy = sigt(go.y + bo);
            cst.x = fmaf(fx, cst.x, ix * gx);
            cst.y = fmaf(fy, cst.y, iy * gy);
            float hx = ox * tanha(cst.x), hy = oy * tanha(cst.y);
            __half hhx = __float2half_rn(hx), hhy = __float2half_rn(hy);
            s->abT[2 * p][64 + j] = hhx; s->abT[2 * p + 1][64 + j] = hhy;
            s->gbT[2 * p][64 + j] = hhx; s->gbT[2 * p + 1][64 + j] = hhy;
        }
        __syncthreads();

        // 8) pred = h @ out_W.T + b; feedback + output (64 threads)
        if (t < 64) {
            const int ba = t >> 3, cc = t & 7;
            float a0 = 0.f, a1 = 0.f;
#pragma unroll
            for (int kk = 0; kk < 32; kk++) {
                __half2 hh = *(const __half2*)&s->abT[ba][64 + 2 * kk];
                float2 hf = __half22float2(hh);
                float2 w = *(const float2*)&s->outWsm[cc][2 * kk];
                a0 = fmaf(w.x, hf.x, a0);
                a1 = fmaf(w.y, hf.y, a1);
            }
            float pv = a0 + a1 + s->out_bS[cc];
            s->inp[ba][cc] = pv;
            y[((size_t)(b0 + ba) * TT + step) * CC + cc] = pv + slast;
        }
        __syncthreads();
    }
}

extern "C" void kernel_launch(void* const* d_in, const int* in_sizes, int n_in,
                              void* d_out, int out_size)
{
    const float* x_enc   = (const float*)d_in[0];
    const float* enc_Wih = (const float*)d_in[4];
    const float* enc_Whh = (const float*)d_in[5];
    const float* enc_bih = (const float*)d_in[6];
    const float* enc_bhh = (const float*)d_in[7];
    const float* emb_W   = (const float*)d_in[8];
    const float* emb_b   = (const float*)d_in[9];
    const float* attn_W  = (const float*)d_in[10];
    const float* attn_b  = (const float*)d_in[11];
    const float* comb_W  = (const float*)d_in[12];
    const float* comb_b  = (const float*)d_in[13];
    const float* dec_Wih = (const float*)d_in[14];
    const float* dec_Whh = (const float*)d_in[15];
    const float* dec_bih = (const float*)d_in[16];
    const float* dec_bhh = (const float*)d_in[17];
    const float* out_W   = (const float*)d_in[18];
    const float* out_b   = (const float*)d_in[19];
    float* y = (float*)d_out;

    cudaFuncSetAttribute(enc_kernel, cudaFuncAttributeMaxDynamicSharedMemorySize,
                         (int)sizeof(EncSmem));
    cudaFuncSetAttribute(dec_kernel, cudaFuncAttributeMaxDynamicSharedMemorySize,
                         (int)sizeof(DecSmem));

    enc_kernel<<<BB / ENB, 512, sizeof(EncSmem)>>>(x_enc, enc_Wih, enc_Whh, enc_bih, enc_bhh);
    dec_kernel<<<BB / DNB, 512, sizeof(DecSmem)>>>(x_enc, emb_W, emb_b, attn_W, attn_b,
                                                   comb_W, comb_b, dec_Wih, dec_Whh,
                                                   dec_bih, dec_bhh, out_W, out_b, y);
}

// round 7
// speedup vs baseline: 7.1465x; 1.0028x over previous
#include <cuda_runtime.h>
#include <cuda_fp16.h>

#define HH 64
#define CC 8
#define LL 96
#define TT 24
#define BB 4096
#define ENB 32   // encoder batches per block
#define DNB 8    // decoder batches per block

// Scratch (device globals — no allocations allowed)
__device__ __half2 g_enc_h2[(size_t)(BB / 2) * LL * HH];  // batch-pair packed fp16
__device__ float2 g_h0_pk[(BB / 2) * HH];
__device__ float2 g_c0_pk[(BB / 2) * HH];

__device__ __forceinline__ float tanha(float x) {
    float r; asm("tanh.approx.f32 %0, %1;" : "=f"(r) : "f"(x)); return r;
}
__device__ __forceinline__ float sigt(float x) {
    return fmaf(tanha(x * 0.5f), 0.5f, 0.5f);
}
__device__ __forceinline__ unsigned h2u(float x, float y) {
    __half2 h = __floats2half2_rn(x, y);
    return *reinterpret_cast<unsigned*>(&h);
}
__device__ __forceinline__ void mma16816(
    float& d0, float& d1, float& d2, float& d3,
    unsigned a0, unsigned a1, unsigned a2, unsigned a3,
    unsigned b0, unsigned b1)
{
    asm volatile(
        "mma.sync.aligned.m16n8k16.row.col.f32.f16.f16.f32 "
        "{%0,%1,%2,%3}, {%4,%5,%6,%7}, {%8,%9}, {%0,%1,%2,%3};"
        : "+f"(d0), "+f"(d1), "+f"(d2), "+f"(d3)
        : "r"(a0), "r"(a1), "r"(a2), "r"(a3), "r"(b0), "r"(b1));
}

// ---------------------------------------------------------------------------
// Encoder: 32 batches/block, grid = 128 (one wave). Gates via HMMA.
// K layout: [h(0..63) ; x(64..71) ; pad(72..79)] -> 5 k16 tiles.
// ---------------------------------------------------------------------------
struct __align__(16) EncSmem {
    __half xT[ENB][776];   // x deltas fp16, [n][step*8+c], padded stride
    __half hT[ENB][72];    // h fp16, [n][k], padded stride
    float  sg[256][34];    // gate pre-activations [row][n], padded stride
    float  bias[256];
};

__global__ __launch_bounds__(512, 1) void enc_kernel(
    const float* __restrict__ x_enc,
    const float* __restrict__ Wih, const float* __restrict__ Whh,
    const float* __restrict__ bih, const float* __restrict__ bhh)
{
    extern __shared__ char smem_raw[];
    EncSmem* s = reinterpret_cast<EncSmem*>(smem_raw);
    const int t = threadIdx.x;
    const int wid = t >> 5, lane = t & 31;
    const int g4 = lane >> 2, tig = lane & 3;
    const size_t b0 = (size_t)blockIdx.x * ENB;
    const int bp0 = blockIdx.x * (ENB / 2);

    // A fragments: rows 16*wid .. 16*wid+15, 5 k-tiles, packed fp16, in regs forever.
    unsigned A[5][4];
    {
        const int r0 = 16 * wid + g4;
#pragma unroll
        for (int kt = 0; kt < 5; kt++) {
            const int c0 = 16 * kt + 2 * tig;
#pragma unroll
            for (int half_ = 0; half_ < 4; half_++) {
                const int rr = r0 + ((half_ & 1) ? 8 : 0);
                const int cc = c0 + ((half_ & 2) ? 8 : 0);
                float w0, w1;
                // W(r,c): c<64 -> Whh[r][c]; c<72 -> Wih[r][c-64]; else 0
                w0 = (cc < 64) ? Whh[rr * 64 + cc] : ((cc < 72) ? Wih[rr * 8 + cc - 64] : 0.f);
                w1 = (cc + 1 < 64) ? Whh[rr * 64 + cc + 1] : ((cc + 1 < 72) ? Wih[rr * 8 + cc + 1 - 64] : 0.f);
                A[kt][half_] = h2u(w0, w1);
            }
        }
    }
    if (t < 256) s->bias[t] = bih[t] + bhh[t];

    // Stage xT (x - seq_last) fp16, zero hT
    for (int i = t; i < ENB * 768; i += 512) {
        int n = i / 768, idx = i % 768, c = idx & 7;
        const float* xb = x_enc + (b0 + n) * 768;
        s->xT[n][idx] = __float2half_rn(xb[idx] - xb[760 + c]);
    }
    for (int i = t; i < ENB * 72; i += 512) ((__half*)s->hT)[i] = __ushort_as_half(0);
    __syncthreads();

    const int jc = t & 63, qc = t >> 6;   // cell: thread -> (j, batch group 4qc..4qc+3)
    float cs0 = 0.f, cs1 = 0.f, cs2 = 0.f, cs3 = 0.f;
    float h0r = 0.f, h1r = 0.f, h2r = 0.f, h3r = 0.f;

    for (int step = 0; step < LL; step++) {
        // ---- gates via MMA: D[256 x 32] ----
        float d[4][4];
#pragma unroll
        for (int nt = 0; nt < 4; nt++) { d[nt][0] = d[nt][1] = d[nt][2] = d[nt][3] = 0.f; }
#pragma unroll
        for (int nt = 0; nt < 4; nt++) {
            const __half* hrow = s->hT[nt * 8 + g4];
#pragma unroll
            for (int kt = 0; kt < 4; kt++) {
                unsigned bf0 = *(const unsigned*)&hrow[16 * kt + 2 * tig];
                unsigned bf1 = *(const unsigned*)&hrow[16 * kt + 2 * tig + 8];
                mma16816(d[nt][0], d[nt][1], d[nt][2], d[nt][3],
                         A[kt][0], A[kt][1], A[kt][2], A[kt][3], bf0, bf1);
            }
            unsigned bx = *(const unsigned*)&s->xT[nt * 8 + g4][step * 8 + 2 * tig];
            mma16816(d[nt][0], d[nt][1], d[nt][2], d[nt][3],
                     A[4][0], A[4][1], A[4][2], A[4][3], bx, 0u);
        }
        {
            const int r0 = 16 * wid + g4;
#pragma unroll
            for (int nt = 0; nt < 4; nt++) {
                const int cidx = nt * 8 + 2 * tig;
                *(float2*)&s->sg[r0][cidx]     = make_float2(d[nt][0], d[nt][1]);
                *(float2*)&s->sg[r0 + 8][cidx] = make_float2(d[nt][2], d[nt][3]);
            }
        }
        __syncthreads();

        // ---- cell: 4 batches per thread ----
        {
            float2 giA = *(const float2*)&s->sg[jc][4 * qc];
            float2 giB = *(const float2*)&s->sg[jc][4 * qc + 2];
            float2 gfA = *(const float2*)&s->sg[64 + jc][4 * qc];
            float2 gfB = *(const float2*)&s->sg[64 + jc][4 * qc + 2];
            float2 ggA = *(const float2*)&s->sg[128 + jc][4 * qc];
            float2 ggB = *(const float2*)&s->sg[128 + jc][4 * qc + 2];
            float2 goA = *(const float2*)&s->sg[192 + jc][4 * qc];
            float2 goB = *(const float2*)&s->sg[192 + jc][4 * qc + 2];
            float bi = s->bias[jc], bf = s->bias[64 + jc];
            float bg = s->bias[128 + jc], bo = s->bias[192 + jc];

            float i0 = sigt(giA.x + bi), i1 = sigt(giA.y + bi), i2 = sigt(giB.x + bi), i3 = sigt(giB.y + bi);
            float f0 = sigt(gfA.x + bf), f1 = sigt(gfA.y + bf), f2 = sigt(gfB.x + bf), f3 = sigt(gfB.y + bf);
            float t0 = tanha(ggA.x + bg), t1 = tanha(ggA.y + bg), t2 = tanha(ggB.x + bg), t3 = tanha(ggB.y + bg);
            float o0 = sigt(goA.x + bo), o1 = sigt(goA.y + bo), o2 = sigt(goB.x + bo), o3 = sigt(goB.y + bo);
            cs0 = fmaf(f0, cs0, i0 * t0); cs1 = fmaf(f1, cs1, i1 * t1);
            cs2 = fmaf(f2, cs2, i2 * t2); cs3 = fmaf(f3, cs3, i3 * t3);
            h0r = o0 * tanha(cs0); h1r = o1 * tanha(cs1);
            h2r = o2 * tanha(cs2); h3r = o3 * tanha(cs3);

            s->hT[4 * qc + 0][jc] = __float2half_rn(h0r);
            s->hT[4 * qc + 1][jc] = __float2half_rn(h1r);
            s->hT[4 * qc + 2][jc] = __float2half_rn(h2r);
            s->hT[4 * qc + 3][jc] = __float2half_rn(h3r);
            g_enc_h2[((size_t)(bp0 + 2 * qc) * LL + step) * HH + jc]     = __floats2half2_rn(h0r, h1r);
            g_enc_h2[((size_t)(bp0 + 2 * qc + 1) * LL + step) * HH + jc] = __floats2half2_rn(h2r, h3r);
        }
        __syncthreads();
    }
    g_h0_pk[(bp0 + 2 * qc) * HH + jc]     = make_float2(h0r, h1r);
    g_h0_pk[(bp0 + 2 * qc + 1) * HH + jc] = make_float2(h2r, h3r);
    g_c0_pk[(bp0 + 2 * qc) * HH + jc]     = make_float2(cs0, cs1);
    g_c0_pk[(bp0 + 2 * qc + 1) * HH + jc] = make_float2(cs2, cs3);
}

// ---------------------------------------------------------------------------
// Decoder: 8 batches/block, grid = 512. attn/comb/gates via HMMA.
// ---------------------------------------------------------------------------
struct __align__(16) DecSmem {
    __half2 enc2[4][LL * HH];   // 98304 B, enc_out fp16 pairs
    __half  abT[DNB][136];      // attn B: [emb(0..63); h(64..127)]
    __half  cbT[DNB][136];      // comb B: [emb; ctx]
    __half  gbT[DNB][136];      // gates B: [comb; h]
    __half2 aw2[4][98];         // normalized softmax weights (pair-packed)
    float   awl[96][10];        // raw attn logits [l][n]
    float   sg[256][10];        // gate pre-acts [row][n]
    float   inp[DNB][CC];
    float   embW[CC][HH];       // [k][j]
    float   outWsm[CC][HH];     // [c][k]
    float   biasg[256];
    float   attn_bS[LL];
    float   comb_bS[HH];
    float   emb_bS[HH];
    float   out_bS[CC];
};

__global__ __launch_bounds__(512, 1) void dec_kernel(
    const float* __restrict__ x_enc,
    const float* __restrict__ emb_W, const float* __restrict__ emb_b,
    const float* __restrict__ attn_W, const float* __restrict__ attn_b,
    const float* __restrict__ comb_W, const float* __restrict__ comb_b,
    const float* __restrict__ Wih, const float* __restrict__ Whh,
    const float* __restrict__ bih, const float* __restrict__ bhh,
    const float* __restrict__ out_W, const float* __restrict__ out_b,
    float* __restrict__ y)
{
    extern __shared__ char smem_raw[];
    DecSmem* s = reinterpret_cast<DecSmem*>(smem_raw);
    const int t = threadIdx.x;
    const int wid = t >> 5, lane = t & 31;
    const int g4 = lane >> 2, tig = lane & 3;
    const int b0 = blockIdx.x * DNB;
    const int bp0 = blockIdx.x * (DNB / 2);

    // ---- A fragments in registers ----
    unsigned Ag[8][4];   // gates: all warps, rows 16*wid..
    unsigned Ax[8][4] = {};  // attn (wid<6) or comb (6<=wid<10)
    {
        const int r0 = 16 * wid + g4;
#pragma unroll
        for (int kt = 0; kt < 8; kt++) {
            const int c0 = 16 * kt + 2 * tig;
#pragma unroll
            for (int h_ = 0; h_ < 4; h_++) {
                const int rr = r0 + ((h_ & 1) ? 8 : 0);
                const int cc = c0 + ((h_ & 2) ? 8 : 0);
                // gates: k<64 -> Wih (input = comb), k>=64 -> Whh (hidden)
                float w0 = (cc < 64) ? Wih[rr * 64 + cc] : Whh[rr * 64 + cc - 64];
                float w1 = (cc + 1 < 64) ? Wih[rr * 64 + cc + 1] : Whh[rr * 64 + cc + 1 - 64];
                Ag[kt][h_] = h2u(w0, w1);
            }
        }
        if (wid < 6) {
            const int ra = 16 * wid + g4;
#pragma unroll
            for (int kt = 0; kt < 8; kt++) {
                const int c0 = 16 * kt + 2 * tig;
#pragma unroll
                for (int h_ = 0; h_ < 4; h_++) {
                    const int rr = ra + ((h_ & 1) ? 8 : 0);
                    const int cc = c0 + ((h_ & 2) ? 8 : 0);
                    Ax[kt][h_] = h2u(attn_W[rr * 128 + cc], attn_W[rr * 128 + cc + 1]);
                }
            }
        } else if (wid < 10) {
            const int rc = 16 * (wid - 6) + g4;
#pragma unroll
            for (int kt = 0; kt < 8; kt++) {
                const int c0 = 16 * kt + 2 * tig;
#pragma unroll
                for (int h_ = 0; h_ < 4; h_++) {
                    const int rr = rc + ((h_ & 1) ? 8 : 0);
                    const int cc = c0 + ((h_ & 2) ? 8 : 0);
                    Ax[kt][h_] = h2u(comb_W[rr * 128 + cc], comb_W[rr * 128 + cc + 1]);
                }
            }
        }
    }

    // ---- Stage SMEM ----
#pragma unroll
    for (int p = 0; p < 4; p++) {
        const float4* eg = (const float4*)(g_enc_h2 + (size_t)(bp0 + p) * (LL * HH));
        float4* es = (float4*)&s->enc2[p][0];
        for (int i = t; i < LL * HH / 4; i += 512) es[i] = eg[i];
    }
    for (int i = t; i < CC * HH; i += 512) { int j = i >> 3, k = i & 7; s->embW[k][j] = emb_W[i]; }
    for (int i = t; i < CC * HH; i += 512) ((float*)s->outWsm)[i] = out_W[i];  // same [c][k] layout
    if (t < 256) s->biasg[t] = bih[t] + bhh[t];
    if (t < LL) s->attn_bS[t] = attn_b[t];
    if (t < HH) { s->comb_bS[t] = comb_b[t]; s->emb_bS[t] = emb_b[t]; }
    if (t < CC) s->out_bS[t] = out_b[t];

    float2 cst = make_float2(0.f, 0.f);
    if (t < 256) {
        const int p = t >> 6, j = t & 63;
        float2 h0 = g_h0_pk[(bp0 + p) * HH + j];
        cst = g_c0_pk[(bp0 + p) * HH + j];
        __half hx = __float2half_rn(h0.x), hy = __float2half_rn(h0.y);
        s->abT[2 * p][64 + j] = hx; s->abT[2 * p + 1][64 + j] = hy;
        s->gbT[2 * p][64 + j] = hx; s->gbT[2 * p + 1][64 + j] = hy;
    }
    float slast = 0.f;
    if (t < 64) {
        const int ba = t >> 3, cc = t & 7;
        s->inp[ba][cc] = 0.f;   // dec_in0 - seq_last == 0
        slast = x_enc[(size_t)(b0 + ba) * LL * CC + (LL - 1) * CC + cc];
    }
    __syncthreads();

    for (int step = 0; step < TT; step++) {
        // 1) emb = relu(inp @ emb_W.T + b) -> abT, cbT (512 threads)
        {
            const int n = t >> 6, j = t & 63;
            float e = s->emb_bS[j];
#pragma unroll
            for (int k = 0; k < CC; k++) e = fmaf(s->embW[k][j], s->inp[n][k], e);
            __half he = __float2half_rn(fmaxf(e, 0.f));
            s->abT[n][j] = he;
            s->cbT[n][j] = he;
        }
        __syncthreads();

        // 2) attn logits via MMA (warps 0-5)
        if (wid < 6) {
            const __half* brow = s->abT[g4];
            float d0 = 0.f, d1 = 0.f, d2 = 0.f, d3 = 0.f;
#pragma unroll
            for (int kt = 0; kt < 8; kt++) {
                unsigned bf0 = *(const unsigned*)&brow[16 * kt + 2 * tig];
                unsigned bf1 = *(const unsigned*)&brow[16 * kt + 2 * tig + 8];
                mma16816(d0, d1, d2, d3, Ax[kt][0], Ax[kt][1], Ax[kt][2], Ax[kt][3], bf0, bf1);
            }
            const int r0 = 16 * wid + g4;
            *(float2*)&s->awl[r0][2 * tig]     = make_float2(d0, d1);
            *(float2*)&s->awl[r0 + 8][2 * tig] = make_float2(d2, d3);
        }
        __syncthreads();

        // 3) softmax (warps 0-7, one batch each) -> normalized fp16 pair-packed aw2
        if (wid < 8) {
            const int n = wid, p = n >> 1, comp = n & 1;
            float z0 = s->awl[lane][n]      + s->attn_bS[lane];
            float z1 = s->awl[lane + 32][n] + s->attn_bS[lane + 32];
            float z2 = s->awl[lane + 64][n] + s->attn_bS[lane + 64];
            float m = fmaxf(z0, fmaxf(z1, z2));
#pragma unroll
            for (int o = 16; o; o >>= 1) m = fmaxf(m, __shfl_xor_sync(0xffffffffu, m, o));
            float e0 = __expf(z0 - m), e1 = __expf(z1 - m), e2 = __expf(z2 - m);
            float sum = e0 + e1 + e2;
#pragma unroll
            for (int o = 16; o; o >>= 1) sum += __shfl_xor_sync(0xffffffffu, sum, o);
            float inv = 1.0f / sum;
            __half* dst = (__half*)&s->aw2[p][0] + comp;
            dst[2 * lane]        = __float2half_rn(e0 * inv);
            dst[2 * (lane + 32)] = __float2half_rn(e1 * inv);
            dst[2 * (lane + 64)] = __float2half_rn(e2 * inv);
        }
        __syncthreads();

        // 4) ctx: HFMA2 over enc2 (512 threads = pair x j x l-half) -> cbT
        {
            const int p = t >> 7, j = (t >> 1) & 63, lh = t & 1;
            const __half2* erow = &s->enc2[p][0];
            const __half2* awp = &s->aw2[p][0];
            __half2 acc0 = __float2half2_rn(0.f), acc1 = acc0;
            const int lb = lh * 48;
#pragma unroll 8
            for (int li = 0; li < 48; li += 2) {
                acc0 = __hfma2(awp[lb + li],     erow[(lb + li) * HH + j],     acc0);
                acc1 = __hfma2(awp[lb + li + 1], erow[(lb + li + 1) * HH + j], acc1);
            }
            acc0 = __hadd2(acc0, acc1);
            unsigned u = *(unsigned*)&acc0;
            unsigned v = __shfl_xor_sync(0xffffffffu, u, 1);
            acc0 = __hadd2(acc0, *(__half2*)&v);
            if (!lh) {
                s->cbT[2 * p][64 + j]     = __low2half(acc0);
                s->cbT[2 * p + 1][64 + j] = __high2half(acc0);
            }
        }
        __syncthreads();

        // 5) comb via MMA (warps 6-9) -> gbT (fp16, +bias)
        if (wid >= 6 && wid < 10) {
            const __half* brow = s->cbT[g4];
            float d0 = 0.f, d1 = 0.f, d2 = 0.f, d3 = 0.f;
#pragma unroll
            for (int kt = 0; kt < 8; kt++) {
                unsigned bf0 = *(const unsigned*)&brow[16 * kt + 2 * tig];
                unsigned bf1 = *(const unsigned*)&brow[16 * kt + 2 * tig + 8];
                mma16816(d0, d1, d2, d3, Ax[kt][0], Ax[kt][1], Ax[kt][2], Ax[kt][3], bf0, bf1);
            }
            const int r0 = 16 * (wid - 6) + g4;
            float cb0 = s->comb_bS[r0], cb8 = s->comb_bS[r0 + 8];
            s->gbT[2 * tig][r0]         = __float2half_rn(d0 + cb0);
            s->gbT[2 * tig + 1][r0]     = __float2half_rn(d1 + cb0);
            s->gbT[2 * tig][r0 + 8]     = __float2half_rn(d2 + cb8);
            s->gbT[2 * tig + 1][r0 + 8] = __float2half_rn(d3 + cb8);
        }
        __syncthreads();

        // 6) gates via MMA (all 16 warps) -> sg
        {
            const __half* brow = s->gbT[g4];
            float d0 = 0.f, d1 = 0.f, d2 = 0.f, d3 = 0.f;
#pragma unroll
            for (int kt = 0; kt < 8; kt++) {
                unsigned bf0 = *(const unsigned*)&brow[16 * kt + 2 * tig];
                unsigned bf1 = *(const unsigned*)&brow[16 * kt + 2 * tig + 8];
                mma16816(d0, d1, d2, d3, Ag[kt][0], Ag[kt][1], Ag[kt][2], Ag[kt][3], bf0, bf1);
            }
            const int r0 = 16 * wid + g4;
            *(float2*)&s->sg[r0][2 * tig]     = make_float2(d0, d1);
            *(float2*)&s->sg[r0 + 8][2 * tig] = make_float2(d2, d3);
        }
        __syncthreads();

        // 7) cell update (256 threads = pair x j)
        if (t < 256) {
            const int p = t >> 6, j = t & 63;
            float2 gi = *(const float2*)&s->sg[j][2 * p];
            float2 gf = *(const float2*)&s->sg[64 + j][2 * p];
            float2 gg = *(const float2*)&s->sg[128 + j][2 * p];
            float2 go = *(const float2*)&s->sg[192 + j][2 * p];
            float bi = s->biasg[j], bf = s->biasg[64 + j];
            float bg = s->biasg[128 + j], bo = s->biasg[192 + j];
            float ix = sigt(gi.x + bi), iy = sigt(gi.y + bi);
            float fx = sigt(gf.x + bf), fy = sigt(gf.y + bf);
            float gx = tanha(gg.x + bg), gy = tanha(gg.y + bg);
            float ox = sigt(go.x + bo), oy = sigt(go.y + bo);
            cst.x = fmaf(fx, cst.x, ix * gx);
            cst.y = fmaf(fy, cst.y, iy * gy);
            float hx = ox * tanha(cst.x), hy = oy * tanha(cst.y);
            __half hhx = __float2half_rn(hx), hhy = __float2half_rn(hy);
            s->abT[2 * p][64 + j] = hhx; s->abT[2 * p + 1][64 + j] = hhy;
            s->gbT[2 * p][64 + j] = hhx; s->gbT[2 * p + 1][64 + j] = hhy;
        }
        __syncthreads();

        // 8) pred = h @ out_W.T + b; feedback + output (64 threads)
        if (t < 64) {
            const int ba = t >> 3, cc = t & 7;
            float a0 = 0.f, a1 = 0.f;
#pragma unroll
            for (int kk = 0; kk < 32; kk++) {
                __half2 hh = *(const __half2*)&s->abT[ba][64 + 2 * kk];
                float2 hf = __half22float2(hh);
                float2 w = *(const float2*)&s->outWsm[cc][2 * kk];
                a0 = fmaf(w.x, hf.x, a0);
                a1 = fmaf(w.y, hf.y, a1);
            }
            float pv = a0 + a1 + s->out_bS[cc];
            s->inp[ba][cc] = pv;
            y[((size_t)(b0 + ba) * TT + step) * CC + cc] = pv + slast;
        }
        __syncthreads();
    }
}

extern "C" void kernel_launch(void* const* d_in, const int* in_sizes, int n_in,
                              void* d_out, int out_size)
{
    const float* x_enc   = (const float*)d_in[0];
    const float* enc_Wih = (const float*)d_in[4];
    const float* enc_Whh = (const float*)d_in[5];
    const float* enc_bih = (const float*)d_in[6];
    const float* enc_bhh = (const float*)d_in[7];
    const float* emb_W   = (const float*)d_in[8];
    const float* emb_b   = (const float*)d_in[9];
    const float* attn_W  = (const float*)d_in[10];
    const float* attn_b  = (const float*)d_in[11];
    const float* comb_W  = (const float*)d_in[12];
    const float* comb_b  = (const float*)d_in[13];
    const float* dec_Wih = (const float*)d_in[14];
    const float* dec_Whh = (const float*)d_in[15];
    const float* dec_bih = (const float*)d_in[16];
    const float* dec_bhh = (const float*)d_in[17];
    const float* out_W   = (const float*)d_in[18];
    const float* out_b   = (const float*)d_in[19];
    float* y = (float*)d_out;

    cudaFuncSetAttribute(enc_kernel, cudaFuncAttributeMaxDynamicSharedMemorySize,
                         (int)sizeof(EncSmem));
    cudaFuncSetAttribute(dec_kernel, cudaFuncAttributeMaxDynamicSharedMemorySize,
                         (int)sizeof(DecSmem));

    enc_kernel<<<BB / ENB, 512, sizeof(EncSmem)>>>(x_enc, enc_Wih, enc_Whh, enc_bih, enc_bhh);
    dec_kernel<<<BB / DNB, 512, sizeof(DecSmem)>>>(x_enc, emb_W, emb_b, attn_W, attn_b,
                                                   comb_W, comb_b, dec_Wih, dec_Whh,
                                                   dec_bih, dec_bhh, out_W, out_b, y);
}

// round 8
// speedup vs baseline: 9.9372x; 1.3905x over previous
#include <cuda_runtime.h>
#include <cuda_fp16.h>

#define HH 64
#define CC 8
#define LL 96
#define TT 24
#define BB 4096
#define ENB 32   // encoder batches per block
#define DNB 16   // decoder batches per block

// Scratch (device globals — no allocations allowed)
__device__ __half2 g_enc_h2[(size_t)(BB / 2) * LL * HH];  // batch-pair packed fp16
__device__ float2 g_h0_pk[(BB / 2) * HH];
__device__ float2 g_c0_pk[(BB / 2) * HH];

__device__ __forceinline__ float tanha(float x) {
    float r; asm("tanh.approx.f32 %0, %1;" : "=f"(r) : "f"(x)); return r;
}
__device__ __forceinline__ float sigt(float x) {
    return fmaf(tanha(x * 0.5f), 0.5f, 0.5f);
}
__device__ __forceinline__ unsigned h2u(float x, float y) {
    __half2 h = __floats2half2_rn(x, y);
    return *reinterpret_cast<unsigned*>(&h);
}
__device__ __forceinline__ void mma16816(
    float& d0, float& d1, float& d2, float& d3,
    unsigned a0, unsigned a1, unsigned a2, unsigned a3,
    unsigned b0, unsigned b1)
{
    asm volatile(
        "mma.sync.aligned.m16n8k16.row.col.f32.f16.f16.f32 "
        "{%0,%1,%2,%3}, {%4,%5,%6,%7}, {%8,%9}, {%0,%1,%2,%3};"
        : "+f"(d0), "+f"(d1), "+f"(d2), "+f"(d3)
        : "r"(a0), "r"(a1), "r"(a2), "r"(a3), "r"(b0), "r"(b1));
}

// ---------------------------------------------------------------------------
// Encoder: 32 batches/block, grid = 128 (one wave). Gates via HMMA. (as R6)
// ---------------------------------------------------------------------------
struct __align__(16) EncSmem {
    __half xT[ENB][776];
    __half hT[ENB][72];
    float  sg[256][34];
    float  bias[256];
};

__global__ __launch_bounds__(512, 1) void enc_kernel(
    const float* __restrict__ x_enc,
    const float* __restrict__ Wih, const float* __restrict__ Whh,
    const float* __restrict__ bih, const float* __restrict__ bhh)
{
    extern __shared__ char smem_raw[];
    EncSmem* s = reinterpret_cast<EncSmem*>(smem_raw);
    const int t = threadIdx.x;
    const int wid = t >> 5, lane = t & 31;
    const int g4 = lane >> 2, tig = lane & 3;
    const size_t b0 = (size_t)blockIdx.x * ENB;
    const int bp0 = blockIdx.x * (ENB / 2);

    unsigned A[5][4];
    {
        const int r0 = 16 * wid + g4;
#pragma unroll
        for (int kt = 0; kt < 5; kt++) {
            const int c0 = 16 * kt + 2 * tig;
#pragma unroll
            for (int half_ = 0; half_ < 4; half_++) {
                const int rr = r0 + ((half_ & 1) ? 8 : 0);
                const int cc = c0 + ((half_ & 2) ? 8 : 0);
                float w0, w1;
                w0 = (cc < 64) ? Whh[rr * 64 + cc] : ((cc < 72) ? Wih[rr * 8 + cc - 64] : 0.f);
                w1 = (cc + 1 < 64) ? Whh[rr * 64 + cc + 1] : ((cc + 1 < 72) ? Wih[rr * 8 + cc + 1 - 64] : 0.f);
                A[kt][half_] = h2u(w0, w1);
            }
        }
    }
    if (t < 256) s->bias[t] = bih[t] + bhh[t];

    for (int i = t; i < ENB * 768; i += 512) {
        int n = i / 768, idx = i % 768, c = idx & 7;
        const float* xb = x_enc + (b0 + n) * 768;
        s->xT[n][idx] = __float2half_rn(xb[idx] - xb[760 + c]);
    }
    for (int i = t; i < ENB * 72; i += 512) ((__half*)s->hT)[i] = __ushort_as_half(0);
    __syncthreads();

    const int jc = t & 63, qc = t >> 6;
    float cs0 = 0.f, cs1 = 0.f, cs2 = 0.f, cs3 = 0.f;
    float h0r = 0.f, h1r = 0.f, h2r = 0.f, h3r = 0.f;

    for (int step = 0; step < LL; step++) {
        float d[4][4];
#pragma unroll
        for (int nt = 0; nt < 4; nt++) { d[nt][0] = d[nt][1] = d[nt][2] = d[nt][3] = 0.f; }
#pragma unroll
        for (int nt = 0; nt < 4; nt++) {
            const __half* hrow = s->hT[nt * 8 + g4];
#pragma unroll
            for (int kt = 0; kt < 4; kt++) {
                unsigned bf0 = *(const unsigned*)&hrow[16 * kt + 2 * tig];
                unsigned bf1 = *(const unsigned*)&hrow[16 * kt + 2 * tig + 8];
                mma16816(d[nt][0], d[nt][1], d[nt][2], d[nt][3],
                         A[kt][0], A[kt][1], A[kt][2], A[kt][3], bf0, bf1);
            }
            unsigned bx = *(const unsigned*)&s->xT[nt * 8 + g4][step * 8 + 2 * tig];
            mma16816(d[nt][0], d[nt][1], d[nt][2], d[nt][3],
                     A[4][0], A[4][1], A[4][2], A[4][3], bx, 0u);
        }
        {
            const int r0 = 16 * wid + g4;
#pragma unroll
            for (int nt = 0; nt < 4; nt++) {
                const int cidx = nt * 8 + 2 * tig;
                *(float2*)&s->sg[r0][cidx]     = make_float2(d[nt][0], d[nt][1]);
                *(float2*)&s->sg[r0 + 8][cidx] = make_float2(d[nt][2], d[nt][3]);
            }
        }
        __syncthreads();

        {
            float2 giA = *(const float2*)&s->sg[jc][4 * qc];
            float2 giB = *(const float2*)&s->sg[jc][4 * qc + 2];
            float2 gfA = *(const float2*)&s->sg[64 + jc][4 * qc];
            float2 gfB = *(const float2*)&s->sg[64 + jc][4 * qc + 2];
            float2 ggA = *(const float2*)&s->sg[128 + jc][4 * qc];
            float2 ggB = *(const float2*)&s->sg[128 + jc][4 * qc + 2];
            float2 goA = *(const float2*)&s->sg[192 + jc][4 * qc];
            float2 goB = *(const float2*)&s->sg[192 + jc][4 * qc + 2];
            float bi = s->bias[jc], bf = s->bias[64 + jc];
            float bg = s->bias[128 + jc], bo = s->bias[192 + jc];

            float i0 = sigt(giA.x + bi), i1 = sigt(giA.y + bi), i2 = sigt(giB.x + bi), i3 = sigt(giB.y + bi);
            float f0 = sigt(gfA.x + bf), f1 = sigt(gfA.y + bf), f2 = sigt(gfB.x + bf), f3 = sigt(gfB.y + bf);
            float t0 = tanha(ggA.x + bg), t1 = tanha(ggA.y + bg), t2 = tanha(ggB.x + bg), t3 = tanha(ggB.y + bg);
            float o0 = sigt(goA.x + bo), o1 = sigt(goA.y + bo), o2 = sigt(goB.x + bo), o3 = sigt(goB.y + bo);
            cs0 = fmaf(f0, cs0, i0 * t0); cs1 = fmaf(f1, cs1, i1 * t1);
            cs2 = fmaf(f2, cs2, i2 * t2); cs3 = fmaf(f3, cs3, i3 * t3);
            h0r = o0 * tanha(cs0); h1r = o1 * tanha(cs1);
            h2r = o2 * tanha(cs2); h3r = o3 * tanha(cs3);

            s->hT[4 * qc + 0][jc] = __float2half_rn(h0r);
            s->hT[4 * qc + 1][jc] = __float2half_rn(h1r);
            s->hT[4 * qc + 2][jc] = __float2half_rn(h2r);
            s->hT[4 * qc + 3][jc] = __float2half_rn(h3r);
            g_enc_h2[((size_t)(bp0 + 2 * qc) * LL + step) * HH + jc]     = __floats2half2_rn(h0r, h1r);
            g_enc_h2[((size_t)(bp0 + 2 * qc + 1) * LL + step) * HH + jc] = __floats2half2_rn(h2r, h3r);
        }
        __syncthreads();
    }
    g_h0_pk[(bp0 + 2 * qc) * HH + jc]     = make_float2(h0r, h1r);
    g_h0_pk[(bp0 + 2 * qc + 1) * HH + jc] = make_float2(h2r, h3r);
    g_c0_pk[(bp0 + 2 * qc) * HH + jc]     = make_float2(cs0, cs1);
    g_c0_pk[(bp0 + 2 * qc + 1) * HH + jc] = make_float2(cs2, cs3);
}

// ---------------------------------------------------------------------------
// Decoder: 16 batches/block, grid = 256. Warp n owns batch n for serial
// phases (cell+pred+emb fused, softmax). 6 barriers/step.
// ---------------------------------------------------------------------------
struct __align__(16) DecSmem {
    __half2 enc2[DNB / 2][LL * HH];  // 196608 B
    __half  abT[DNB][136];           // [emb|comb (0..63); h (64..127)]
    __half  cbT[DNB][136];           // [emb (0..63); ctx (64..127)]
    __half2 aw2[DNB / 2][98];        // normalized softmax weights
    float   awl[LL][17];             // raw attn logits [l][n], odd stride
    __half  sg[256][18];             // gate pre-acts [row][n] fp16, stride 18h
    float   embW[CC][HH];            // [k][j]
    float   outW[CC][HH];            // [c][k] (raw layout)
    float   biasg[256];
    float   attn_bS[LL];
    float   comb_bS[HH];
    float   emb_bS[HH];
    float   out_bS[CC];
};  // ~230 KB

__global__ __launch_bounds__(512, 1) void dec_kernel(
    const float* __restrict__ x_enc,
    const float* __restrict__ emb_W, const float* __restrict__ emb_b,
    const float* __restrict__ attn_W, const float* __restrict__ attn_b,
    const float* __restrict__ comb_W, const float* __restrict__ comb_b,
    const float* __restrict__ Wih, const float* __restrict__ Whh,
    const float* __restrict__ bih, const float* __restrict__ bhh,
    const float* __restrict__ out_W, const float* __restrict__ out_b,
    float* __restrict__ y)
{
    extern __shared__ char smem_raw[];
    DecSmem* s = reinterpret_cast<DecSmem*>(smem_raw);
    const int t = threadIdx.x;
    const int wid = t >> 5, lane = t & 31;
    const int g4 = lane >> 2, tig = lane & 3;
    const int b0 = blockIdx.x * DNB;
    const int bp0 = blockIdx.x * (DNB / 2);

    // ---- A fragments in registers ----
    unsigned Ag[8][4];        // gates (all warps): rows 16*wid
    unsigned Ax[8][4] = {};   // attn (wid<6, rows 16*wid) / comb (6..9, rows 16*(wid-6))
    {
        const int r0 = 16 * wid + g4;
#pragma unroll
        for (int kt = 0; kt < 8; kt++) {
            const int c0 = 16 * kt + 2 * tig;
#pragma unroll
            for (int h_ = 0; h_ < 4; h_++) {
                const int rr = r0 + ((h_ & 1) ? 8 : 0);
                const int cc = c0 + ((h_ & 2) ? 8 : 0);
                float w0 = (cc < 64) ? Wih[rr * 64 + cc] : Whh[rr * 64 + cc - 64];
                float w1 = (cc + 1 < 64) ? Wih[rr * 64 + cc + 1] : Whh[rr * 64 + cc + 1 - 64];
                Ag[kt][h_] = h2u(w0, w1);
            }
        }
        if (wid < 6) {
#pragma unroll
            for (int kt = 0; kt < 8; kt++) {
                const int c0 = 16 * kt + 2 * tig;
#pragma unroll
                for (int h_ = 0; h_ < 4; h_++) {
                    const int rr = r0 + ((h_ & 1) ? 8 : 0);
                    const int cc = c0 + ((h_ & 2) ? 8 : 0);
                    Ax[kt][h_] = h2u(attn_W[rr * 128 + cc], attn_W[rr * 128 + cc + 1]);
                }
            }
        } else if (wid < 10) {
            const int rc = 16 * (wid - 6) + g4;
#pragma unroll
            for (int kt = 0; kt < 8; kt++) {
                const int c0 = 16 * kt + 2 * tig;
#pragma unroll
                for (int h_ = 0; h_ < 4; h_++) {
                    const int rr = rc + ((h_ & 1) ? 8 : 0);
                    const int cc = c0 + ((h_ & 2) ? 8 : 0);
                    Ax[kt][h_] = h2u(comb_W[rr * 128 + cc], comb_W[rr * 128 + cc + 1]);
                }
            }
        }
    }

    // ---- Stage SMEM ----
    {
        const float4* eg = (const float4*)(g_enc_h2 + (size_t)bp0 * (LL * HH));
        float4* es = (float4*)s->enc2;
        for (int i = t; i < (DNB / 2) * LL * HH / 4; i += 512) es[i] = eg[i];
    }
    for (int i = t; i < CC * HH; i += 512) {
        int j = i >> 3, k = i & 7;
        s->embW[k][j] = emb_W[i];
        ((float*)s->outW)[i] = out_W[i];
    }
    if (t < 256) s->biasg[t] = bih[t] + bhh[t];
    if (t < LL) s->attn_bS[t] = attn_b[t];
    if (t < HH) { s->comb_bS[t] = comb_b[t]; s->emb_bS[t] = emb_b[t]; }
    if (t < CC) s->out_bS[t] = out_b[t];
    __syncthreads();

    // ---- Per-warp batch state ----
    const int n = wid, j0 = lane, j1 = lane + 32;
    float cst0, cst1, hv0, hv1;
    {
        float2 hA = g_h0_pk[(bp0 + (n >> 1)) * HH + j0];
        float2 hB = g_h0_pk[(bp0 + (n >> 1)) * HH + j1];
        float2 cA = g_c0_pk[(bp0 + (n >> 1)) * HH + j0];
        float2 cB = g_c0_pk[(bp0 + (n >> 1)) * HH + j1];
        hv0 = (n & 1) ? hA.y : hA.x;  hv1 = (n & 1) ? hB.y : hB.x;
        cst0 = (n & 1) ? cA.y : cA.x; cst1 = (n & 1) ? cB.y : cB.x;
    }
    float4 sl0 = make_float4(0, 0, 0, 0), sl1 = sl0;
    if (lane == 0) {
        const float* xb = x_enc + (size_t)(b0 + n) * (LL * CC) + (LL - 1) * CC;
        sl0 = *(const float4*)xb;
        sl1 = *(const float4*)(xb + 4);
    }

    // init abT/cbT: emb = relu(emb_b) (inp0 == 0), h part
    {
        float e0 = fmaxf(s->emb_bS[j0], 0.f), e1 = fmaxf(s->emb_bS[j1], 0.f);
        s->abT[n][j0] = __float2half_rn(e0); s->abT[n][j1] = __float2half_rn(e1);
        s->cbT[n][j0] = __float2half_rn(e0); s->cbT[n][j1] = __float2half_rn(e1);
        s->abT[n][64 + j0] = __float2half_rn(hv0);
        s->abT[n][64 + j1] = __float2half_rn(hv1);
    }
    __syncthreads();

    for (int step = 0; step < TT; step++) {
        // B) attn logits via MMA (warps 0-5), N=16
        if (wid < 6) {
            const __half* br0 = s->abT[g4];
            const __half* br1 = s->abT[8 + g4];
            float d0[4] = {0, 0, 0, 0}, d1[4] = {0, 0, 0, 0};
#pragma unroll
            for (int kt = 0; kt < 8; kt++) {
                unsigned a0f = *(const unsigned*)&br0[16 * kt + 2 * tig];
                unsigned a1f = *(const unsigned*)&br0[16 * kt + 2 * tig + 8];
                mma16816(d0[0], d0[1], d0[2], d0[3], Ax[kt][0], Ax[kt][1], Ax[kt][2], Ax[kt][3], a0f, a1f);
                unsigned b0f = *(const unsigned*)&br1[16 * kt + 2 * tig];
                unsigned b1f = *(const unsigned*)&br1[16 * kt + 2 * tig + 8];
                mma16816(d1[0], d1[1], d1[2], d1[3], Ax[kt][0], Ax[kt][1], Ax[kt][2], Ax[kt][3], b0f, b1f);
            }
            const int r0 = 16 * wid + g4;
            s->awl[r0][2 * tig]         = d0[0]; s->awl[r0][2 * tig + 1]     = d0[1];
            s->awl[r0 + 8][2 * tig]     = d0[2]; s->awl[r0 + 8][2 * tig + 1] = d0[3];
            s->awl[r0][8 + 2 * tig]     = d1[0]; s->awl[r0][8 + 2 * tig + 1] = d1[1];
            s->awl[r0 + 8][8 + 2 * tig] = d1[2]; s->awl[r0 + 8][8 + 2 * tig + 1] = d1[3];
        }
        __syncthreads();

        // C) softmax: warp n for batch n
        {
            float z0 = s->awl[lane][n]      + s->attn_bS[lane];
            float z1 = s->awl[lane + 32][n] + s->attn_bS[lane + 32];
            float z2 = s->awl[lane + 64][n] + s->attn_bS[lane + 64];
            float m = fmaxf(z0, fmaxf(z1, z2));
#pragma unroll
            for (int o = 16; o; o >>= 1) m = fmaxf(m, __shfl_xor_sync(0xffffffffu, m, o));
            float e0 = __expf(z0 - m), e1 = __expf(z1 - m), e2 = __expf(z2 - m);
            float sum = e0 + e1 + e2;
#pragma unroll
            for (int o = 16; o; o >>= 1) sum += __shfl_xor_sync(0xffffffffu, sum, o);
            float inv = 1.0f / sum;
            __half* dst = (__half*)&s->aw2[n >> 1][0] + (n & 1);
            dst[2 * lane]        = __float2half_rn(e0 * inv);
            dst[2 * (lane + 32)] = __float2half_rn(e1 * inv);
            dst[2 * (lane + 64)] = __float2half_rn(e2 * inv);
        }
        __syncthreads();

        // D) ctx: HFMA2 (512 threads = pair p x j)
        {
            const int p = t >> 6, j = t & 63;
            const __half2* erow = &s->enc2[p][0];
            const __half2* awp = &s->aw2[p][0];
            __half2 a0 = __float2half2_rn(0.f), a1 = a0, a2 = a0, a3 = a0;
#pragma unroll 6
            for (int l = 0; l < LL; l += 4) {
                a0 = __hfma2(awp[l],     erow[(l    ) * HH + j], a0);
                a1 = __hfma2(awp[l + 1], erow[(l + 1) * HH + j], a1);
                a2 = __hfma2(awp[l + 2], erow[(l + 2) * HH + j], a2);
                a3 = __hfma2(awp[l + 3], erow[(l + 3) * HH + j], a3);
            }
            a0 = __hadd2(__hadd2(a0, a1), __hadd2(a2, a3));
            s->cbT[2 * p][64 + j]     = __low2half(a0);
            s->cbT[2 * p + 1][64 + j] = __high2half(a0);
        }
        __syncthreads();

        // E) comb via MMA (warps 6-9) -> abT[.][0..63] (+bias), overwrites emb
        if (wid >= 6 && wid < 10) {
            const __half* br0 = s->cbT[g4];
            const __half* br1 = s->cbT[8 + g4];
            float d0[4] = {0, 0, 0, 0}, d1[4] = {0, 0, 0, 0};
#pragma unroll
            for (int kt = 0; kt < 8; kt++) {
                unsigned a0f = *(const unsigned*)&br0[16 * kt + 2 * tig];
                unsigned a1f = *(const unsigned*)&br0[16 * kt + 2 * tig + 8];
                mma16816(d0[0], d0[1], d0[2], d0[3], Ax[kt][0], Ax[kt][1], Ax[kt][2], Ax[kt][3], a0f, a1f);
                unsigned b0f = *(const unsigned*)&br1[16 * kt + 2 * tig];
                unsigned b1f = *(const unsigned*)&br1[16 * kt + 2 * tig + 8];
                mma16816(d1[0], d1[1], d1[2], d1[3], Ax[kt][0], Ax[kt][1], Ax[kt][2], Ax[kt][3], b0f, b1f);
            }
            const int r0 = 16 * (wid - 6) + g4;
            float cb0 = s->comb_bS[r0], cb8 = s->comb_bS[r0 + 8];
            s->abT[2 * tig][r0]         = __float2half_rn(d0[0] + cb0);
            s->abT[2 * tig + 1][r0]     = __float2half_rn(d0[1] + cb0);
            s->abT[2 * tig][r0 + 8]     = __float2half_rn(d0[2] + cb8);
            s->abT[2 * tig + 1][r0 + 8] = __float2half_rn(d0[3] + cb8);
            s->abT[8 + 2 * tig][r0]         = __float2half_rn(d1[0] + cb0);
            s->abT[8 + 2 * tig + 1][r0]     = __float2half_rn(d1[1] + cb0);
            s->abT[8 + 2 * tig][r0 + 8]     = __float2half_rn(d1[2] + cb8);
            s->abT[8 + 2 * tig + 1][r0 + 8] = __float2half_rn(d1[3] + cb8);
        }
        __syncthreads();

        // F) gates via MMA (all 16 warps): B = abT = [comb; h]
        {
            const __half* br0 = s->abT[g4];
            const __half* br1 = s->abT[8 + g4];
            float d0[4] = {0, 0, 0, 0}, d1[4] = {0, 0, 0, 0};
#pragma unroll
            for (int kt = 0; kt < 8; kt++) {
                unsigned a0f = *(const unsigned*)&br0[16 * kt + 2 * tig];
                unsigned a1f = *(const unsigned*)&br0[16 * kt + 2 * tig + 8];
                mma16816(d0[0], d0[1], d0[2], d0[3], Ag[kt][0], Ag[kt][1], Ag[kt][2], Ag[kt][3], a0f, a1f);
                unsigned b0f = *(const unsigned*)&br1[16 * kt + 2 * tig];
                unsigned b1f = *(const unsigned*)&br1[16 * kt + 2 * tig + 8];
                mma16816(d1[0], d1[1], d1[2], d1[3], Ag[kt][0], Ag[kt][1], Ag[kt][2], Ag[kt][3], b0f, b1f);
            }
            const int r0 = 16 * wid + g4;
            s->sg[r0][2 * tig]         = __float2half_rn(d0[0]);
            s->sg[r0][2 * tig + 1]     = __float2half_rn(d0[1]);
            s->sg[r0 + 8][2 * tig]     = __float2half_rn(d0[2]);
            s->sg[r0 + 8][2 * tig + 1] = __float2half_rn(d0[3]);
            s->sg[r0][8 + 2 * tig]         = __float2half_rn(d1[0]);
            s->sg[r0][8 + 2 * tig + 1]     = __float2half_rn(d1[1]);
            s->sg[r0 + 8][8 + 2 * tig]     = __float2half_rn(d1[2]);
            s->sg[r0 + 8][8 + 2 * tig + 1] = __float2half_rn(d1[3]);
        }
        __syncthreads();

        // A) cell + pred + y + next emb (warp n = batch n, fully warp-local)
        {
            float gi0 = __half2float(s->sg[j0][n])       + s->biasg[j0];
            float gi1 = __half2float(s->sg[j1][n])       + s->biasg[j1];
            float gf0 = __half2float(s->sg[64 + j0][n])  + s->biasg[64 + j0];
            float gf1 = __half2float(s->sg[64 + j1][n])  + s->biasg[64 + j1];
            float gg0 = __half2float(s->sg[128 + j0][n]) + s->biasg[128 + j0];
            float gg1 = __half2float(s->sg[128 + j1][n]) + s->biasg[128 + j1];
            float go0 = __half2float(s->sg[192 + j0][n]) + s->biasg[192 + j0];
            float go1 = __half2float(s->sg[192 + j1][n]) + s->biasg[192 + j1];
            float i0 = sigt(gi0), i1 = sigt(gi1);
            float f0 = sigt(gf0), f1 = sigt(gf1);
            float tg0 = tanha(gg0), tg1 = tanha(gg1);
            float o0 = sigt(go0), o1 = sigt(go1);
            cst0 = fmaf(f0, cst0, i0 * tg0);
            cst1 = fmaf(f1, cst1, i1 * tg1);
            hv0 = o0 * tanha(cst0);
            hv1 = o1 * tanha(cst1);

            // pred: butterfly reduce 8 channels
            float pc[8];
#pragma unroll
            for (int c = 0; c < 8; c++)
                pc[c] = fmaf(s->outW[c][j0], hv0, s->outW[c][j1] * hv1);
#pragma unroll
            for (int o = 16; o; o >>= 1) {
#pragma unroll
                for (int c = 0; c < 8; c++) pc[c] += __shfl_xor_sync(0xffffffffu, pc[c], o);
            }
#pragma unroll
            for (int c = 0; c < 8; c++) pc[c] += s->out_bS[c];

            if (lane == 0) {
                float* yp = y + ((size_t)(b0 + n) * TT + step) * CC;
                *(float4*)yp       = make_float4(pc[0] + sl0.x, pc[1] + sl0.y, pc[2] + sl0.z, pc[3] + sl0.w);
                *(float4*)(yp + 4) = make_float4(pc[4] + sl1.x, pc[5] + sl1.y, pc[6] + sl1.z, pc[7] + sl1.w);
            }

            // emb for next step
            float e0 = s->emb_bS[j0], e1 = s->emb_bS[j1];
#pragma unroll
            for (int c = 0; c < 8; c++) {
                e0 = fmaf(s->embW[c][j0], pc[c], e0);
                e1 = fmaf(s->embW[c][j1], pc[c], e1);
            }
            e0 = fmaxf(e0, 0.f); e1 = fmaxf(e1, 0.f);
            s->abT[n][j0] = __float2half_rn(e0); s->abT[n][j1] = __float2half_rn(e1);
            s->cbT[n][j0] = __float2half_rn(e0); s->cbT[n][j1] = __float2half_rn(e1);
            s->abT[n][64 + j0] = __float2half_rn(hv0);
            s->abT[n][64 + j1] = __float2half_rn(hv1);
        }
        __syncthreads();
    }
}

extern "C" void kernel_launch(void* const* d_in, const int* in_sizes, int n_in,
                              void* d_out, int out_size)
{
    const float* x_enc   = (const float*)d_in[0];
    const float* enc_Wih = (const float*)d_in[4];
    const float* enc_Whh = (const float*)d_in[5];
    const float* enc_bih = (const float*)d_in[6];
    const float* enc_bhh = (const float*)d_in[7];
    const float* emb_W   = (const float*)d_in[8];
    const float* emb_b   = (const float*)d_in[9];
    const float* attn_W  = (const float*)d_in[10];
    const float* attn_b  = (const float*)d_in[11];
    const float* comb_W  = (const float*)d_in[12];
    const float* comb_b  = (const float*)d_in[13];
    const float* dec_Wih = (const float*)d_in[14];
    const float* dec_Whh = (const float*)d_in[15];
    const float* dec_bih = (const float*)d_in[16];
    const float* dec_bhh = (const float*)d_in[17];
    const float* out_W   = (const float*)d_in[18];
    const float* out_b   = (const float*)d_in[19];
    float* y = (float*)d_out;

    cudaFuncSetAttribute(enc_kernel, cudaFuncAttributeMaxDynamicSharedMemorySize,
                         (int)sizeof(EncSmem));
    cudaFuncSetAttribute(dec_kernel, cudaFuncAttributeMaxDynamicSharedMemorySize,
                         (int)sizeof(DecSmem));

    enc_kernel<<<BB / ENB, 512, sizeof(EncSmem)>>>(x_enc, enc_Wih, enc_Whh, enc_bih, enc_bhh);
    dec_kernel<<<BB / DNB, 512, sizeof(DecSmem)>>>(x_enc, emb_W, emb_b, attn_W, attn_b,
                                                   comb_W, comb_b, dec_Wih, dec_Whh,
                                                   dec_bih, dec_bhh, out_W, out_b, y);
}

// round 9
// speedup vs baseline: 10.0014x; 1.0065x over previous
#include <cuda_runtime.h>
#include <cuda_fp16.h>

#define HH 64
#define CC 8
#define LL 96
#define TT 24
#define BB 4096
#define ENB 32   // encoder batches per block
#define DNB 16   // decoder batches per block

// Scratch (device globals — no allocations allowed)
__device__ __half g_enc_h[(size_t)BB * LL * HH];   // batch-major fp16 enc_out
__device__ float2 g_h0_pk[(BB / 2) * HH];
__device__ float2 g_c0_pk[(BB / 2) * HH];

__device__ __forceinline__ float tanha(float x) {
    float r; asm("tanh.approx.f32 %0, %1;" : "=f"(r) : "f"(x)); return r;
}
__device__ __forceinline__ float sigt(float x) {
    return fmaf(tanha(x * 0.5f), 0.5f, 0.5f);
}
__device__ __forceinline__ unsigned h2u(float x, float y) {
    __half2 h = __floats2half2_rn(x, y);
    return *reinterpret_cast<unsigned*>(&h);
}
__device__ __forceinline__ void mma16816(
    float& d0, float& d1, float& d2, float& d3,
    unsigned a0, unsigned a1, unsigned a2, unsigned a3,
    unsigned b0, unsigned b1)
{
    asm volatile(
        "mma.sync.aligned.m16n8k16.row.col.f32.f16.f16.f32 "
        "{%0,%1,%2,%3}, {%4,%5,%6,%7}, {%8,%9}, {%0,%1,%2,%3};"
        : "+f"(d0), "+f"(d1), "+f"(d2), "+f"(d3)
        : "r"(a0), "r"(a1), "r"(a2), "r"(a3), "r"(b0), "r"(b1));
}

// ---------------------------------------------------------------------------
// Encoder: 32 batches/block, grid = 128 (one wave). Gates via HMMA.
// ---------------------------------------------------------------------------
struct __align__(16) EncSmem {
    __half xT[ENB][776];
    __half hT[ENB][72];
    float  sg[256][34];
    float  bias[256];
};

__global__ __launch_bounds__(512, 1) void enc_kernel(
    const float* __restrict__ x_enc,
    const float* __restrict__ Wih, const float* __restrict__ Whh,
    const float* __restrict__ bih, const float* __restrict__ bhh)
{
    extern __shared__ char smem_raw[];
    EncSmem* s = reinterpret_cast<EncSmem*>(smem_raw);
    const int t = threadIdx.x;
    const int wid = t >> 5, lane = t & 31;
    const int g4 = lane >> 2, tig = lane & 3;
    const size_t b0 = (size_t)blockIdx.x * ENB;
    const int bp0 = blockIdx.x * (ENB / 2);

    unsigned A[5][4];
    {
        const int r0 = 16 * wid + g4;
#pragma unroll
        for (int kt = 0; kt < 5; kt++) {
            const int c0 = 16 * kt + 2 * tig;
#pragma unroll
            for (int half_ = 0; half_ < 4; half_++) {
                const int rr = r0 + ((half_ & 1) ? 8 : 0);
                const int cc = c0 + ((half_ & 2) ? 8 : 0);
                float w0, w1;
                w0 = (cc < 64) ? Whh[rr * 64 + cc] : ((cc < 72) ? Wih[rr * 8 + cc - 64] : 0.f);
                w1 = (cc + 1 < 64) ? Whh[rr * 64 + cc + 1] : ((cc + 1 < 72) ? Wih[rr * 8 + cc + 1 - 64] : 0.f);
                A[kt][half_] = h2u(w0, w1);
            }
        }
    }
    if (t < 256) s->bias[t] = bih[t] + bhh[t];

    for (int i = t; i < ENB * 768; i += 512) {
        int n = i / 768, idx = i % 768, c = idx & 7;
        const float* xb = x_enc + (b0 + n) * 768;
        s->xT[n][idx] = __float2half_rn(xb[idx] - xb[760 + c]);
    }
    for (int i = t; i < ENB * 72; i += 512) ((__half*)s->hT)[i] = __ushort_as_half(0);
    __syncthreads();

    const int jc = t & 63, qc = t >> 6;
    float cs0 = 0.f, cs1 = 0.f, cs2 = 0.f, cs3 = 0.f;
    float h0r = 0.f, h1r = 0.f, h2r = 0.f, h3r = 0.f;

    for (int step = 0; step < LL; step++) {
        float d[4][4];
#pragma unroll
        for (int nt = 0; nt < 4; nt++) { d[nt][0] = d[nt][1] = d[nt][2] = d[nt][3] = 0.f; }
#pragma unroll
        for (int nt = 0; nt < 4; nt++) {
            const __half* hrow = s->hT[nt * 8 + g4];
#pragma unroll
            for (int kt = 0; kt < 4; kt++) {
                unsigned bf0 = *(const unsigned*)&hrow[16 * kt + 2 * tig];
                unsigned bf1 = *(const unsigned*)&hrow[16 * kt + 2 * tig + 8];
                mma16816(d[nt][0], d[nt][1], d[nt][2], d[nt][3],
                         A[kt][0], A[kt][1], A[kt][2], A[kt][3], bf0, bf1);
            }
            unsigned bx = *(const unsigned*)&s->xT[nt * 8 + g4][step * 8 + 2 * tig];
            mma16816(d[nt][0], d[nt][1], d[nt][2], d[nt][3],
                     A[4][0], A[4][1], A[4][2], A[4][3], bx, 0u);
        }
        {
            const int r0 = 16 * wid + g4;
#pragma unroll
            for (int nt = 0; nt < 4; nt++) {
                const int cidx = nt * 8 + 2 * tig;
                *(float2*)&s->sg[r0][cidx]     = make_float2(d[nt][0], d[nt][1]);
                *(float2*)&s->sg[r0 + 8][cidx] = make_float2(d[nt][2], d[nt][3]);
            }
        }
        __syncthreads();

        {
            float2 giA = *(const float2*)&s->sg[jc][4 * qc];
            float2 giB = *(const float2*)&s->sg[jc][4 * qc + 2];
            float2 gfA = *(const float2*)&s->sg[64 + jc][4 * qc];
            float2 gfB = *(const float2*)&s->sg[64 + jc][4 * qc + 2];
            float2 ggA = *(const float2*)&s->sg[128 + jc][4 * qc];
            float2 ggB = *(const float2*)&s->sg[128 + jc][4 * qc + 2];
            float2 goA = *(const float2*)&s->sg[192 + jc][4 * qc];
            float2 goB = *(const float2*)&s->sg[192 + jc][4 * qc + 2];
            float bi = s->bias[jc], bf = s->bias[64 + jc];
            float bg = s->bias[128 + jc], bo = s->bias[192 + jc];

            float i0 = sigt(giA.x + bi), i1 = sigt(giA.y + bi), i2 = sigt(giB.x + bi), i3 = sigt(giB.y + bi);
            float f0 = sigt(gfA.x + bf), f1 = sigt(gfA.y + bf), f2 = sigt(gfB.x + bf), f3 = sigt(gfB.y + bf);
            float t0 = tanha(ggA.x + bg), t1 = tanha(ggA.y + bg), t2 = tanha(ggB.x + bg), t3 = tanha(ggB.y + bg);
            float o0 = sigt(goA.x + bo), o1 = sigt(goA.y + bo), o2 = sigt(goB.x + bo), o3 = sigt(goB.y + bo);
            cs0 = fmaf(f0, cs0, i0 * t0); cs1 = fmaf(f1, cs1, i1 * t1);
            cs2 = fmaf(f2, cs2, i2 * t2); cs3 = fmaf(f3, cs3, i3 * t3);
            h0r = o0 * tanha(cs0); h1r = o1 * tanha(cs1);
            h2r = o2 * tanha(cs2); h3r = o3 * tanha(cs3);

            s->hT[4 * qc + 0][jc] = __float2half_rn(h0r);
            s->hT[4 * qc + 1][jc] = __float2half_rn(h1r);
            s->hT[4 * qc + 2][jc] = __float2half_rn(h2r);
            s->hT[4 * qc + 3][jc] = __float2half_rn(h3r);
            const size_t eb = (b0 + 4 * qc) * (size_t)(LL * HH) + step * HH + jc;
            g_enc_h[eb]                = __float2half_rn(h0r);
            g_enc_h[eb + LL * HH]      = __float2half_rn(h1r);
            g_enc_h[eb + 2 * LL * HH]  = __float2half_rn(h2r);
            g_enc_h[eb + 3 * LL * HH]  = __float2half_rn(h3r);
        }
        __syncthreads();
    }
    g_h0_pk[(bp0 + 2 * qc) * HH + jc]     = make_float2(h0r, h1r);
    g_h0_pk[(bp0 + 2 * qc + 1) * HH + jc] = make_float2(h2r, h3r);
    g_c0_pk[(bp0 + 2 * qc) * HH + jc]     = make_float2(cs0, cs1);
    g_c0_pk[(bp0 + 2 * qc + 1) * HH + jc] = make_float2(cs2, cs3);
}

// ---------------------------------------------------------------------------
// Decoder: 16 batches/block, grid = 256. Phases: B attn(12w) / CD fused
// softmax+ctx (warp-per-batch) / E comb(4w)+gatesH(12w) / F gatesC / A cell.
// ---------------------------------------------------------------------------
struct __align__(16) DecSmem {
    __half  encS[DNB][LL * HH];   // 196608, [n][l*64+j]
    __half  abT[DNB][136];        // [emb|comb (0..63); h (64..127)]
    __half  cbT[DNB][136];        // [emb (0..63); ctx (64..127)]
    __half2 aw2d[DNB][LL];        // duplicated softmax weights, 6144
    __half  awl[LL][18];          // attn logits [l][n], fp16, stride 18
    __half  sg[256][18];          // gate pre-acts [row][n], fp16
    float   embW[CC][HH];
    float   outW[CC][HH];
    float   biasg[256];
    float   attn_bS[LL];
    float   comb_bS[HH];
    float   emb_bS[HH];
    float   out_bS[CC];
};  // ~230.2 KB

__global__ __launch_bounds__(512, 1) void dec_kernel(
    const float* __restrict__ x_enc,
    const float* __restrict__ emb_W, const float* __restrict__ emb_b,
    const float* __restrict__ attn_W, const float* __restrict__ attn_b,
    const float* __restrict__ comb_W, const float* __restrict__ comb_b,
    const float* __restrict__ Wih, const float* __restrict__ Whh,
    const float* __restrict__ bih, const float* __restrict__ bhh,
    const float* __restrict__ out_W, const float* __restrict__ out_b,
    float* __restrict__ y)
{
    extern __shared__ char smem_raw[];
    DecSmem* s = reinterpret_cast<DecSmem*>(smem_raw);
    const int t = threadIdx.x;
    const int wid = t >> 5, lane = t & 31;
    const int g4 = lane >> 2, tig = lane & 3;
    const int b0 = blockIdx.x * DNB;
    const int bp0 = blockIdx.x * (DNB / 2);

    // ---- A fragments ----
    unsigned Ag[8][4];       // gates rows 16*wid (Wih k<64 | Whh k>=64)
    unsigned Ax[8][4] = {};  // attn (wid<12: rows 16*(wid%6)) / comb (wid>=12: rows 16*(wid-12))
    {
        const int r0 = 16 * wid + g4;
#pragma unroll
        for (int kt = 0; kt < 8; kt++) {
            const int c0 = 16 * kt + 2 * tig;
#pragma unroll
            for (int h_ = 0; h_ < 4; h_++) {
                const int rr = r0 + ((h_ & 1) ? 8 : 0);
                const int cc = c0 + ((h_ & 2) ? 8 : 0);
                float w0 = (cc < 64) ? Wih[rr * 64 + cc] : Whh[rr * 64 + cc - 64];
                float w1 = (cc + 1 < 64) ? Wih[rr * 64 + cc + 1] : Whh[rr * 64 + cc + 1 - 64];
                Ag[kt][h_] = h2u(w0, w1);
            }
        }
        if (wid < 12) {
            const int ra = 16 * (wid < 6 ? wid : wid - 6) + g4;
#pragma unroll
            for (int kt = 0; kt < 8; kt++) {
                const int c0 = 16 * kt + 2 * tig;
#pragma unroll
                for (int h_ = 0; h_ < 4; h_++) {
                    const int rr = ra + ((h_ & 1) ? 8 : 0);
                    const int cc = c0 + ((h_ & 2) ? 8 : 0);
                    Ax[kt][h_] = h2u(attn_W[rr * 128 + cc], attn_W[rr * 128 + cc + 1]);
                }
            }
        } else {
            const int rc = 16 * (wid - 12) + g4;
#pragma unroll
            for (int kt = 0; kt < 8; kt++) {
                const int c0 = 16 * kt + 2 * tig;
#pragma unroll
                for (int h_ = 0; h_ < 4; h_++) {
                    const int rr = rc + ((h_ & 1) ? 8 : 0);
                    const int cc = c0 + ((h_ & 2) ? 8 : 0);
                    Ax[kt][h_] = h2u(comb_W[rr * 128 + cc], comb_W[rr * 128 + cc + 1]);
                }
            }
        }
    }

    // ---- Stage SMEM ----
    {
        const float4* eg = (const float4*)(g_enc_h + (size_t)b0 * (LL * HH));
        float4* es = (float4*)s->encS;
        for (int i = t; i < DNB * LL * HH / 8; i += 512) es[i] = eg[i];
    }
    for (int i = t; i < CC * HH; i += 512) {
        int j = i >> 3, k = i & 7;
        s->embW[k][j] = emb_W[i];
        ((float*)s->outW)[i] = out_W[i];
    }
    if (t < 256) s->biasg[t] = bih[t] + bhh[t];
    if (t < LL) s->attn_bS[t] = attn_b[t];
    if (t < HH) { s->comb_bS[t] = comb_b[t]; s->emb_bS[t] = emb_b[t]; }
    if (t < CC) s->out_bS[t] = out_b[t];
    __syncthreads();

    // ---- Per-warp batch state (warp n = batch n) ----
    const int n = wid, j0 = lane, j1 = lane + 32;
    float cst0, cst1, hv0, hv1;
    {
        float2 hA = g_h0_pk[(bp0 + (n >> 1)) * HH + j0];
        float2 hB = g_h0_pk[(bp0 + (n >> 1)) * HH + j1];
        float2 cA = g_c0_pk[(bp0 + (n >> 1)) * HH + j0];
        float2 cB = g_c0_pk[(bp0 + (n >> 1)) * HH + j1];
        hv0 = (n & 1) ? hA.y : hA.x;  hv1 = (n & 1) ? hB.y : hB.x;
        cst0 = (n & 1) ? cA.y : cA.x; cst1 = (n & 1) ? cB.y : cB.x;
    }
    float4 sl0 = make_float4(0, 0, 0, 0), sl1 = sl0;
    if (lane == 0) {
        const float* xb = x_enc + (size_t)(b0 + n) * (LL * CC) + (LL - 1) * CC;
        sl0 = *(const float4*)xb;
        sl1 = *(const float4*)(xb + 4);
    }
    // cached per-lane constants
    const float bg_i = s->biasg[j0],       bg_i1 = s->biasg[j1];
    const float bg_f = s->biasg[64 + j0],  bg_f1 = s->biasg[64 + j1];
    const float bg_g = s->biasg[128 + j0], bg_g1 = s->biasg[128 + j1];
    const float bg_o = s->biasg[192 + j0], bg_o1 = s->biasg[192 + j1];
    const float ab0 = s->attn_bS[lane], ab1 = s->attn_bS[lane + 32], ab2 = s->attn_bS[lane + 64];
    const float eb0 = s->emb_bS[j0], eb1 = s->emb_bS[j1];

    // init: emb = relu(emb_b) (first dec input is 0); h
    {
        float e0 = fmaxf(eb0, 0.f), e1 = fmaxf(eb1, 0.f);
        s->abT[n][j0] = __float2half_rn(e0); s->abT[n][j1] = __float2half_rn(e1);
        s->cbT[n][j0] = __float2half_rn(e0); s->cbT[n][j1] = __float2half_rn(e1);
        s->abT[n][64 + j0] = __float2half_rn(hv0);
        s->abT[n][64 + j1] = __float2half_rn(hv1);
    }
    __syncthreads();

    for (int step = 0; step < TT; step++) {
        // B) attn logits via MMA: 12 warps = 6 m-tiles x 2 n-halves
        if (wid < 12) {
            const int mw = (wid < 6) ? wid : wid - 6;
            const int nh = (wid < 6) ? 0 : 1;
            const __half* br = s->abT[8 * nh + g4];
            float d0 = 0.f, d1 = 0.f, d2 = 0.f, d3 = 0.f;
#pragma unroll
            for (int kt = 0; kt < 8; kt++) {
                unsigned bf0 = *(const unsigned*)&br[16 * kt + 2 * tig];
                unsigned bf1 = *(const unsigned*)&br[16 * kt + 2 * tig + 8];
                mma16816(d0, d1, d2, d3, Ax[kt][0], Ax[kt][1], Ax[kt][2], Ax[kt][3], bf0, bf1);
            }
            const int r0 = 16 * mw + g4, c0 = 8 * nh + 2 * tig;
            *(__half2*)&s->awl[r0][c0]     = __floats2half2_rn(d0, d1);
            *(__half2*)&s->awl[r0 + 8][c0] = __floats2half2_rn(d2, d3);
        }
        __syncthreads();

        // CD) fused softmax + ctx (warp n = batch n)
        {
            float z0 = __half2float(s->awl[lane][n])      + ab0;
            float z1 = __half2float(s->awl[lane + 32][n]) + ab1;
            float z2 = __half2float(s->awl[lane + 64][n]) + ab2;
            float m = fmaxf(z0, fmaxf(z1, z2));
#pragma unroll
            for (int o = 16; o; o >>= 1) m = fmaxf(m, __shfl_xor_sync(0xffffffffu, m, o));
            float e0 = __expf(z0 - m), e1 = __expf(z1 - m), e2 = __expf(z2 - m);
            float sum = e0 + e1 + e2;
#pragma unroll
            for (int o = 16; o; o >>= 1) sum += __shfl_xor_sync(0xffffffffu, sum, o);
            float inv = 1.0f / sum;
            s->aw2d[n][lane]      = __float2half2_rn(e0 * inv);
            s->aw2d[n][lane + 32] = __float2half2_rn(e1 * inv);
            s->aw2d[n][lane + 64] = __float2half2_rn(e2 * inv);
            __syncwarp();

            // ctx: lane owns j = {2*lane, 2*lane+1}
            const __half* er = s->encS[n];
            const __half2* awp = &s->aw2d[n][0];
            __half2 a0 = __float2half2_rn(0.f), a1 = a0, a2 = a0, a3 = a0;
#pragma unroll 6
            for (int l = 0; l < LL; l += 4) {
                a0 = __hfma2(awp[l],     *(const __half2*)&er[(l    ) * HH + 2 * lane], a0);
                a1 = __hfma2(awp[l + 1], *(const __half2*)&er[(l + 1) * HH + 2 * lane], a1);
                a2 = __hfma2(awp[l + 2], *(const __half2*)&er[(l + 2) * HH + 2 * lane], a2);
                a3 = __hfma2(awp[l + 3], *(const __half2*)&er[(l + 3) * HH + 2 * lane], a3);
            }
            a0 = __hadd2(__hadd2(a0, a1), __hadd2(a2, a3));
            *(__half2*)&s->cbT[n][64 + 2 * lane] = a0;
        }
        __syncthreads();

        // E) comb via MMA (warps 12-15) -> abT[.][0..63]; gates h-half (warps 0-11)
        float gd0[4] = {0, 0, 0, 0}, gd1[4] = {0, 0, 0, 0};
        if (wid >= 12) {
            const __half* br0 = s->cbT[g4];
            const __half* br1 = s->cbT[8 + g4];
            float d0[4] = {0, 0, 0, 0}, d1[4] = {0, 0, 0, 0};
#pragma unroll
            for (int kt = 0; kt < 8; kt++) {
                unsigned a0f = *(const unsigned*)&br0[16 * kt + 2 * tig];
                unsigned a1f = *(const unsigned*)&br0[16 * kt + 2 * tig + 8];
                mma16816(d0[0], d0[1], d0[2], d0[3], Ax[kt][0], Ax[kt][1], Ax[kt][2], Ax[kt][3], a0f, a1f);
                unsigned b0f = *(const unsigned*)&br1[16 * kt + 2 * tig];
                unsigned b1f = *(const unsigned*)&br1[16 * kt + 2 * tig + 8];
                mma16816(d1[0], d1[1], d1[2], d1[3], Ax[kt][0], Ax[kt][1], Ax[kt][2], Ax[kt][3], b0f, b1f);
            }
            const int r0 = 16 * (wid - 12) + g4;
            float cb0 = s->comb_bS[r0], cb8 = s->comb_bS[r0 + 8];
            s->abT[2 * tig][r0]         = __float2half_rn(d0[0] + cb0);
            s->abT[2 * tig + 1][r0]     = __float2half_rn(d0[1] + cb0);
            s->abT[2 * tig][r0 + 8]     = __float2half_rn(d0[2] + cb8);
            s->abT[2 * tig + 1][r0 + 8] = __float2half_rn(d0[3] + cb8);
            s->abT[8 + 2 * tig][r0]         = __float2half_rn(d1[0] + cb0);
            s->abT[8 + 2 * tig + 1][r0]     = __float2half_rn(d1[1] + cb0);
            s->abT[8 + 2 * tig][r0 + 8]     = __float2half_rn(d1[2] + cb8);
            s->abT[8 + 2 * tig + 1][r0 + 8] = __float2half_rn(d1[3] + cb8);
        } else {
            // gates h-half (kt 4..7) into carried accumulators
            const __half* br0 = s->abT[g4];
            const __half* br1 = s->abT[8 + g4];
#pragma unroll
            for (int kt = 4; kt < 8; kt++) {
                unsigned a0f = *(const unsigned*)&br0[16 * kt + 2 * tig];
                unsigned a1f = *(const unsigned*)&br0[16 * kt + 2 * tig + 8];
                mma16816(gd0[0], gd0[1], gd0[2], gd0[3], Ag[kt][0], Ag[kt][1], Ag[kt][2], Ag[kt][3], a0f, a1f);
                unsigned b0f = *(const unsigned*)&br1[16 * kt + 2 * tig];
                unsigned b1f = *(const unsigned*)&br1[16 * kt + 2 * tig + 8];
                mma16816(gd1[0], gd1[1], gd1[2], gd1[3], Ag[kt][0], Ag[kt][1], Ag[kt][2], Ag[kt][3], b0f, b1f);
            }
        }
        __syncthreads();

        // F) gates comb-half (all warps); warps 12-15 also do their h-half
        {
            const __half* br0 = s->abT[g4];
            const __half* br1 = s->abT[8 + g4];
            if (wid >= 12) {
#pragma unroll
                for (int kt = 4; kt < 8; kt++) {
                    unsigned a0f = *(const unsigned*)&br0[16 * kt + 2 * tig];
                    unsigned a1f = *(const unsigned*)&br0[16 * kt + 2 * tig + 8];
                    mma16816(gd0[0], gd0[1], gd0[2], gd0[3], Ag[kt][0], Ag[kt][1], Ag[kt][2], Ag[kt][3], a0f, a1f);
                    unsigned b0f = *(const unsigned*)&br1[16 * kt + 2 * tig];
                    unsigned b1f = *(const unsigned*)&br1[16 * kt + 2 * tig + 8];
                    mma16816(gd1[0], gd1[1], gd1[2], gd1[3], Ag[kt][0], Ag[kt][1], Ag[kt][2], Ag[kt][3], b0f, b1f);
                }
            }
#pragma unroll
            for (int kt = 0; kt < 4; kt++) {
                unsigned a0f = *(const unsigned*)&br0[16 * kt + 2 * tig];
                unsigned a1f = *(const unsigned*)&br0[16 * kt + 2 * tig + 8];
                mma16816(gd0[0], gd0[1], gd0[2], gd0[3], Ag[kt][0], Ag[kt][1], Ag[kt][2], Ag[kt][3], a0f, a1f);
                unsigned b0f = *(const unsigned*)&br1[16 * kt + 2 * tig];
                unsigned b1f = *(const unsigned*)&br1[16 * kt + 2 * tig + 8];
                mma16816(gd1[0], gd1[1], gd1[2], gd1[3], Ag[kt][0], Ag[kt][1], Ag[kt][2], Ag[kt][3], b0f, b1f);
            }
            const int r0 = 16 * wid + g4;
            *(__half2*)&s->sg[r0][2 * tig]         = __floats2half2_rn(gd0[0], gd0[1]);
            *(__half2*)&s->sg[r0 + 8][2 * tig]     = __floats2half2_rn(gd0[2], gd0[3]);
            *(__half2*)&s->sg[r0][8 + 2 * tig]     = __floats2half2_rn(gd1[0], gd1[1]);
            *(__half2*)&s->sg[r0 + 8][8 + 2 * tig] = __floats2half2_rn(gd1[2], gd1[3]);
        }
        __syncthreads();

        // A) cell + pred + y + next emb (warp n = batch n)
        {
            float gi0 = __half2float(s->sg[j0][n])       + bg_i;
            float gi1 = __half2float(s->sg[j1][n])       + bg_i1;
            float gf0 = __half2float(s->sg[64 + j0][n])  + bg_f;
            float gf1 = __half2float(s->sg[64 + j1][n])  + bg_f1;
            float gg0 = __half2float(s->sg[128 + j0][n]) + bg_g;
            float gg1 = __half2float(s->sg[128 + j1][n]) + bg_g1;
            float go0 = __half2float(s->sg[192 + j0][n]) + bg_o;
            float go1 = __half2float(s->sg[192 + j1][n]) + bg_o1;
            float i0 = sigt(gi0), i1 = sigt(gi1);
            float f0 = sigt(gf0), f1 = sigt(gf1);
            float tg0 = tanha(gg0), tg1 = tanha(gg1);
            float o0 = sigt(go0), o1 = sigt(go1);
            cst0 = fmaf(f0, cst0, i0 * tg0);
            cst1 = fmaf(f1, cst1, i1 * tg1);
            hv0 = o0 * tanha(cst0);
            hv1 = o1 * tanha(cst1);

            float pc[8];
#pragma unroll
            for (int c = 0; c < 8; c++)
                pc[c] = fmaf(s->outW[c][j0], hv0, s->outW[c][j1] * hv1);
#pragma unroll
            for (int o = 16; o; o >>= 1) {
#pragma unroll
                for (int c = 0; c < 8; c++) pc[c] += __shfl_xor_sync(0xffffffffu, pc[c], o);
            }
#pragma unroll
            for (int c = 0; c < 8; c++) pc[c] += s->out_bS[c];

            if (lane == 0) {
                float* yp = y + ((size_t)(b0 + n) * TT + step) * CC;
                *(float4*)yp       = make_float4(pc[0] + sl0.x, pc[1] + sl0.y, pc[2] + sl0.z, pc[3] + sl0.w);
                *(float4*)(yp + 4) = make_float4(pc[4] + sl1.x, pc[5] + sl1.y, pc[6] + sl1.z, pc[7] + sl1.w);
            }

            float e0 = eb0, e1 = eb1;
#pragma unroll
            for (int c = 0; c < 8; c++) {
                e0 = fmaf(s->embW[c][j0], pc[c], e0);
                e1 = fmaf(s->embW[c][j1], pc[c], e1);
            }
            e0 = fmaxf(e0, 0.f); e1 = fmaxf(e1, 0.f);
            s->abT[n][j0] = __float2half_rn(e0); s->abT[n][j1] = __float2half_rn(e1);
            s->cbT[n][j0] = __float2half_rn(e0); s->cbT[n][j1] = __float2half_rn(e1);
            s->abT[n][64 + j0] = __float2half_rn(hv0);
            s->abT[n][64 + j1] = __float2half_rn(hv1);
        }
        __syncthreads();
    }
}

extern "C" void kernel_launch(void* const* d_in, const int* in_sizes, int n_in,
                              void* d_out, int out_size)
{
    const float* x_enc   = (const float*)d_in[0];
    const float* enc_Wih = (const float*)d_in[4];
    const float* enc_Whh = (const float*)d_in[5];
    const float* enc_bih = (const float*)d_in[6];
    const float* enc_bhh = (const float*)d_in[7];
    const float* emb_W   = (const float*)d_in[8];
    const float* emb_b   = (const float*)d_in[9];
    const float* attn_W  = (const float*)d_in[10];
    const float* attn_b  = (const float*)d_in[11];
    const float* comb_W  = (const float*)d_in[12];
    const float* comb_b  = (const float*)d_in[13];
    const float* dec_Wih = (const float*)d_in[14];
    const float* dec_Whh = (const float*)d_in[15];
    const float* dec_bih = (const float*)d_in[16];
    const float* dec_bhh = (const float*)d_in[17];
    const float* out_W   = (const float*)d_in[18];
    const float* out_b   = (const float*)d_in[19];
    float* y = (float*)d_out;

    cudaFuncSetAttribute(enc_kernel, cudaFuncAttributeMaxDynamicSharedMemorySize,
                         (int)sizeof(EncSmem));
    cudaFuncSetAttribute(dec_kernel, cudaFuncAttributeMaxDynamicSharedMemorySize,
                         (int)sizeof(DecSmem));

    enc_kernel<<<BB / ENB, 512, sizeof(EncSmem)>>>(x_enc, enc_Wih, enc_Whh, enc_bih, enc_bhh);
    dec_kernel<<<BB / DNB, 512, sizeof(DecSmem)>>>(x_enc, emb_W, emb_b, attn_W, attn_b,
                                                   comb_W, comb_b, dec_Wih, dec_Whh,
                                                   dec_bih, dec_bhh, out_W, out_b, y);
}

// round 10
// speedup vs baseline: 10.0624x; 1.0061x over previous
#include <cuda_runtime.h>
#include <cuda_fp16.h>

#define HH 64
#define CC 8
#define LL 96
#define TT 24
#define BB 4096
#define ENB 32   // encoder batches per block
#define DNB 16   // decoder batches per block

// Scratch (device globals — no allocations allowed)
__device__ __half g_enc_h[(size_t)BB * LL * HH];   // batch-major fp16 enc_out
__device__ float2 g_h0_pk[(BB / 2) * HH];
__device__ float2 g_c0_pk[(BB / 2) * HH];

__device__ __forceinline__ float tanha(float x) {
    float r; asm("tanh.approx.f32 %0, %1;" : "=f"(r) : "f"(x)); return r;
}
__device__ __forceinline__ float sigt(float x) {
    return fmaf(tanha(x * 0.5f), 0.5f, 0.5f);
}
__device__ __forceinline__ unsigned h2u(float x, float y) {
    __half2 h = __floats2half2_rn(x, y);
    return *reinterpret_cast<unsigned*>(&h);
}
__device__ __forceinline__ unsigned s2u(const void* p) {
    unsigned a;
    asm("{ .reg .u64 t; cvta.to.shared.u64 t, %1; cvt.u32.u64 %0, t; }" : "=r"(a) : "l"(p));
    return a;
}
__device__ __forceinline__ void mma16816(
    float& d0, float& d1, float& d2, float& d3,
    unsigned a0, unsigned a1, unsigned a2, unsigned a3,
    unsigned b0, unsigned b1)
{
    asm volatile(
        "mma.sync.aligned.m16n8k16.row.col.f32.f16.f16.f32 "
        "{%0,%1,%2,%3}, {%4,%5,%6,%7}, {%8,%9}, {%0,%1,%2,%3};"
        : "+f"(d0), "+f"(d1), "+f"(d2), "+f"(d3)
        : "r"(a0), "r"(a1), "r"(a2), "r"(a3), "r"(b0), "r"(b1));
}
__device__ __forceinline__ void ldsm4t(unsigned& a0, unsigned& a1, unsigned& a2, unsigned& a3,
                                       unsigned addr)
{
    asm volatile("ldmatrix.sync.aligned.m8n8.x4.trans.shared.b16 {%0,%1,%2,%3}, [%4];"
                 : "=r"(a0), "=r"(a1), "=r"(a2), "=r"(a3) : "r"(addr));
}

// ---------------------------------------------------------------------------
// Encoder: 32 batches/block, grid = 128 (one wave). Gates via HMMA. (as R8)
// ---------------------------------------------------------------------------
struct __align__(16) EncSmem {
    __half xT[ENB][776];
    __half hT[ENB][72];
    float  sg[256][34];
    float  bias[256];
};

__global__ __launch_bounds__(512, 1) void enc_kernel(
    const float* __restrict__ x_enc,
    const float* __restrict__ Wih, const float* __restrict__ Whh,
    const float* __restrict__ bih, const float* __restrict__ bhh)
{
    extern __shared__ char smem_raw[];
    EncSmem* s = reinterpret_cast<EncSmem*>(smem_raw);
    const int t = threadIdx.x;
    const int wid = t >> 5, lane = t & 31;
    const int g4 = lane >> 2, tig = lane & 3;
    const size_t b0 = (size_t)blockIdx.x * ENB;
    const int bp0 = blockIdx.x * (ENB / 2);

    unsigned A[5][4];
    {
        const int r0 = 16 * wid + g4;
#pragma unroll
        for (int kt = 0; kt < 5; kt++) {
            const int c0 = 16 * kt + 2 * tig;
#pragma unroll
            for (int half_ = 0; half_ < 4; half_++) {
                const int rr = r0 + ((half_ & 1) ? 8 : 0);
                const int cc = c0 + ((half_ & 2) ? 8 : 0);
                float w0, w1;
                w0 = (cc < 64) ? Whh[rr * 64 + cc] : ((cc < 72) ? Wih[rr * 8 + cc - 64] : 0.f);
                w1 = (cc + 1 < 64) ? Whh[rr * 64 + cc + 1] : ((cc + 1 < 72) ? Wih[rr * 8 + cc + 1 - 64] : 0.f);
                A[kt][half_] = h2u(w0, w1);
            }
        }
    }
    if (t < 256) s->bias[t] = bih[t] + bhh[t];

    for (int i = t; i < ENB * 768; i += 512) {
        int n = i / 768, idx = i % 768, c = idx & 7;
        const float* xb = x_enc + (b0 + n) * 768;
        s->xT[n][idx] = __float2half_rn(xb[idx] - xb[760 + c]);
    }
    for (int i = t; i < ENB * 72; i += 512) ((__half*)s->hT)[i] = __ushort_as_half(0);
    __syncthreads();

    const int jc = t & 63, qc = t >> 6;
    float cs0 = 0.f, cs1 = 0.f, cs2 = 0.f, cs3 = 0.f;
    float h0r = 0.f, h1r = 0.f, h2r = 0.f, h3r = 0.f;

    for (int step = 0; step < LL; step++) {
        float d[4][4];
#pragma unroll
        for (int nt = 0; nt < 4; nt++) { d[nt][0] = d[nt][1] = d[nt][2] = d[nt][3] = 0.f; }
#pragma unroll
        for (int nt = 0; nt < 4; nt++) {
            const __half* hrow = s->hT[nt * 8 + g4];
#pragma unroll
            for (int kt = 0; kt < 4; kt++) {
                unsigned bf0 = *(const unsigned*)&hrow[16 * kt + 2 * tig];
                unsigned bf1 = *(const unsigned*)&hrow[16 * kt + 2 * tig + 8];
                mma16816(d[nt][0], d[nt][1], d[nt][2], d[nt][3],
                         A[kt][0], A[kt][1], A[kt][2], A[kt][3], bf0, bf1);
            }
            unsigned bx = *(const unsigned*)&s->xT[nt * 8 + g4][step * 8 + 2 * tig];
            mma16816(d[nt][0], d[nt][1], d[nt][2], d[nt][3],
                     A[4][0], A[4][1], A[4][2], A[4][3], bx, 0u);
        }
        {
            const int r0 = 16 * wid + g4;
#pragma unroll
            for (int nt = 0; nt < 4; nt++) {
                const int cidx = nt * 8 + 2 * tig;
                *(float2*)&s->sg[r0][cidx]     = make_float2(d[nt][0], d[nt][1]);
                *(float2*)&s->sg[r0 + 8][cidx] = make_float2(d[nt][2], d[nt][3]);
            }
        }
        __syncthreads();

        {
            float2 giA = *(const float2*)&s->sg[jc][4 * qc];
            float2 giB = *(const float2*)&s->sg[jc][4 * qc + 2];
            float2 gfA = *(const float2*)&s->sg[64 + jc][4 * qc];
            float2 gfB = *(const float2*)&s->sg[64 + jc][4 * qc + 2];
            float2 ggA = *(const float2*)&s->sg[128 + jc][4 * qc];
            float2 ggB = *(const float2*)&s->sg[128 + jc][4 * qc + 2];
            float2 goA = *(const float2*)&s->sg[192 + jc][4 * qc];
            float2 goB = *(const float2*)&s->sg[192 + jc][4 * qc + 2];
            float bi = s->bias[jc], bf = s->bias[64 + jc];
            float bg = s->bias[128 + jc], bo = s->bias[192 + jc];

            float i0 = sigt(giA.x + bi), i1 = sigt(giA.y + bi), i2 = sigt(giB.x + bi), i3 = sigt(giB.y + bi);
            float f0 = sigt(gfA.x + bf), f1 = sigt(gfA.y + bf), f2 = sigt(gfB.x + bf), f3 = sigt(gfB.y + bf);
            float t0 = tanha(ggA.x + bg), t1 = tanha(ggA.y + bg), t2 = tanha(ggB.x + bg), t3 = tanha(ggB.y + bg);
            float o0 = sigt(goA.x + bo), o1 = sigt(goA.y + bo), o2 = sigt(goB.x + bo), o3 = sigt(goB.y + bo);
            cs0 = fmaf(f0, cs0, i0 * t0); cs1 = fmaf(f1, cs1, i1 * t1);
            cs2 = fmaf(f2, cs2, i2 * t2); cs3 = fmaf(f3, cs3, i3 * t3);
            h0r = o0 * tanha(cs0); h1r = o1 * tanha(cs1);
            h2r = o2 * tanha(cs2); h3r = o3 * tanha(cs3);

            s->hT[4 * qc + 0][jc] = __float2half_rn(h0r);
            s->hT[4 * qc + 1][jc] = __float2half_rn(h1r);
            s->hT[4 * qc + 2][jc] = __float2half_rn(h2r);
            s->hT[4 * qc + 3][jc] = __float2half_rn(h3r);
            const size_t eb = (b0 + 4 * qc) * (size_t)(LL * HH) + step * HH + jc;
            g_enc_h[eb]                = __float2half_rn(h0r);
            g_enc_h[eb + LL * HH]      = __float2half_rn(h1r);
            g_enc_h[eb + 2 * LL * HH]  = __float2half_rn(h2r);
            g_enc_h[eb + 3 * LL * HH]  = __float2half_rn(h3r);
        }
        __syncthreads();
    }
    g_h0_pk[(bp0 + 2 * qc) * HH + jc]     = make_float2(h0r, h1r);
    g_h0_pk[(bp0 + 2 * qc + 1) * HH + jc] = make_float2(h2r, h3r);
    g_c0_pk[(bp0 + 2 * qc) * HH + jc]     = make_float2(cs0, cs1);
    g_c0_pk[(bp0 + 2 * qc + 1) * HH + jc] = make_float2(cs2, cs3);
}

// ---------------------------------------------------------------------------
// Decoder: 16 batches/block, grid = 256. ctx via ldmatrix.trans + MMA with
// XOR-swizzled enc tiles; aw stays in registers (shuffle-built B fragments).
// ---------------------------------------------------------------------------
struct __align__(16) DecSmem {
    __half  encS[DNB][LL * HH];   // 196608, [n][l*64 + swz(group,l)*8+j%8]
    __half  abT[DNB][136];        // [emb|comb (0..63); h (64..127)]
    __half  cbT[DNB][136];        // [emb (0..63); ctx (64..127)]
    __half  awl[LL][18];          // attn logits [l][n], fp16, stride 18
    __half  sg[256][18];          // gate pre-acts [row][n], fp16
    float   embW[CC][HH];
    float   outW[CC][HH];
    float   biasg[256];
    float   attn_bS[LL];
    float   comb_bS[HH];
    float   emb_bS[HH];
    float   out_bS[CC];
};  // ~224 KB

__global__ __launch_bounds__(512, 1) void dec_kernel(
    const float* __restrict__ x_enc,
    const float* __restrict__ emb_W, const float* __restrict__ emb_b,
    const float* __restrict__ attn_W, const float* __restrict__ attn_b,
    const float* __restrict__ comb_W, const float* __restrict__ comb_b,
    const float* __restrict__ Wih, const float* __restrict__ Whh,
    const float* __restrict__ bih, const float* __restrict__ bhh,
    const float* __restrict__ out_W, const float* __restrict__ out_b,
    float* __restrict__ y)
{
    extern __shared__ char smem_raw[];
    DecSmem* s = reinterpret_cast<DecSmem*>(smem_raw);
    const int t = threadIdx.x;
    const int wid = t >> 5, lane = t & 31;
    const int g4 = lane >> 2, tig = lane & 3;
    const int b0 = blockIdx.x * DNB;
    const int bp0 = blockIdx.x * (DNB / 2);

    // ---- A fragments ----
    unsigned Ag[8][4];       // gates rows 16*wid (Wih k<64 | Whh k>=64)
    unsigned Ax[8][4] = {};  // attn (wid<12) / comb (wid>=12)
    {
        const int r0 = 16 * wid + g4;
#pragma unroll
        for (int kt = 0; kt < 8; kt++) {
            const int c0 = 16 * kt + 2 * tig;
#pragma unroll
            for (int h_ = 0; h_ < 4; h_++) {
                const int rr = r0 + ((h_ & 1) ? 8 : 0);
                const int cc = c0 + ((h_ & 2) ? 8 : 0);
                float w0 = (cc < 64) ? Wih[rr * 64 + cc] : Whh[rr * 64 + cc - 64];
                float w1 = (cc + 1 < 64) ? Wih[rr * 64 + cc + 1] : Whh[rr * 64 + cc + 1 - 64];
                Ag[kt][h_] = h2u(w0, w1);
            }
        }
        if (wid < 12) {
            const int ra = 16 * (wid < 6 ? wid : wid - 6) + g4;
#pragma unroll
            for (int kt = 0; kt < 8; kt++) {
                const int c0 = 16 * kt + 2 * tig;
#pragma unroll
                for (int h_ = 0; h_ < 4; h_++) {
                    const int rr = ra + ((h_ & 1) ? 8 : 0);
                    const int cc = c0 + ((h_ & 2) ? 8 : 0);
                    Ax[kt][h_] = h2u(attn_W[rr * 128 + cc], attn_W[rr * 128 + cc + 1]);
                }
            }
        } else {
            const int rc = 16 * (wid - 12) + g4;
#pragma unroll
            for (int kt = 0; kt < 8; kt++) {
                const int c0 = 16 * kt + 2 * tig;
#pragma unroll
                for (int h_ = 0; h_ < 4; h_++) {
                    const int rr = rc + ((h_ & 1) ? 8 : 0);
                    const int cc = c0 + ((h_ & 2) ? 8 : 0);
                    Ax[kt][h_] = h2u(comb_W[rr * 128 + cc], comb_W[rr * 128 + cc + 1]);
                }
            }
        }
    }

    // ---- Stage SMEM (enc with XOR swizzle on 16B groups) ----
    {
        const float4* eg = (const float4*)(g_enc_h + (size_t)b0 * (LL * HH));
        float4* es = (float4*)s->encS;
        for (int i = t; i < DNB * LL * 8; i += 512) {
            int nl = i >> 3, g = i & 7;
            int l = nl % LL;
            es[nl * 8 + (g ^ (l & 7))] = eg[i];
        }
    }
    for (int i = t; i < CC * HH; i += 512) {
        int j = i >> 3, k = i & 7;
        s->embW[k][j] = emb_W[i];
        ((float*)s->outW)[i] = out_W[i];
    }
    if (t < 256) s->biasg[t] = bih[t] + bhh[t];
    if (t < LL) s->attn_bS[t] = attn_b[t];
    if (t < HH) { s->comb_bS[t] = comb_b[t]; s->emb_bS[t] = emb_b[t]; }
    if (t < CC) s->out_bS[t] = out_b[t];
    __syncthreads();

    // ---- Per-warp batch state (warp n = batch n) ----
    const int n = wid, j0 = lane, j1 = lane + 32;
    float cst0, cst1, hv0, hv1;
    {
        float2 hA = g_h0_pk[(bp0 + (n >> 1)) * HH + j0];
        float2 hB = g_h0_pk[(bp0 + (n >> 1)) * HH + j1];
        float2 cA = g_c0_pk[(bp0 + (n >> 1)) * HH + j0];
        float2 cB = g_c0_pk[(bp0 + (n >> 1)) * HH + j1];
        hv0 = (n & 1) ? hA.y : hA.x;  hv1 = (n & 1) ? hB.y : hB.x;
        cst0 = (n & 1) ? cA.y : cA.x; cst1 = (n & 1) ? cB.y : cB.x;
    }
    float4 sl0 = make_float4(0, 0, 0, 0), sl1 = sl0;
    if (lane == 0) {
        const float* xb = x_enc + (size_t)(b0 + n) * (LL * CC) + (LL - 1) * CC;
        sl0 = *(const float4*)xb;
        sl1 = *(const float4*)(xb + 4);
    }
    const float bg_i = s->biasg[j0],       bg_i1 = s->biasg[j1];
    const float bg_f = s->biasg[64 + j0],  bg_f1 = s->biasg[64 + j1];
    const float bg_g = s->biasg[128 + j0], bg_g1 = s->biasg[128 + j1];
    const float bg_o = s->biasg[192 + j0], bg_o1 = s->biasg[192 + j1];
    const float ab0 = s->attn_bS[lane], ab1 = s->attn_bS[lane + 32], ab2 = s->attn_bS[lane + 64];
    const float eb0 = s->emb_bS[j0], eb1 = s->emb_bS[j1];

    // ldmatrix lane geometry (for ctx A tiles)
    const int kRowOff = (lane & 7) + 8 * ((lane >> 4) & 1);
    const int mHalf   = (lane >> 3) & 1;

    {
        float e0 = fmaxf(eb0, 0.f), e1 = fmaxf(eb1, 0.f);
        s->abT[n][j0] = __float2half_rn(e0); s->abT[n][j1] = __float2half_rn(e1);
        s->cbT[n][j0] = __float2half_rn(e0); s->cbT[n][j1] = __float2half_rn(e1);
        s->abT[n][64 + j0] = __float2half_rn(hv0);
        s->abT[n][64 + j1] = __float2half_rn(hv1);
    }
    __syncthreads();

    for (int step = 0; step < TT; step++) {
        // B) attn logits via MMA: 12 warps = 6 m-tiles x 2 n-halves
        if (wid < 12) {
            const int mw = (wid < 6) ? wid : wid - 6;
            const int nh = (wid < 6) ? 0 : 1;
            const __half* br = s->abT[8 * nh + g4];
            float d0 = 0.f, d1 = 0.f, d2 = 0.f, d3 = 0.f;
#pragma unroll
            for (int kt = 0; kt < 8; kt++) {
                unsigned bf0 = *(const unsigned*)&br[16 * kt + 2 * tig];
                unsigned bf1 = *(const unsigned*)&br[16 * kt + 2 * tig + 8];
                mma16816(d0, d1, d2, d3, Ax[kt][0], Ax[kt][1], Ax[kt][2], Ax[kt][3], bf0, bf1);
            }
            const int r0 = 16 * mw + g4, c0 = 8 * nh + 2 * tig;
            *(__half2*)&s->awl[r0][c0]     = __floats2half2_rn(d0, d1);
            *(__half2*)&s->awl[r0 + 8][c0] = __floats2half2_rn(d2, d3);
        }
        __syncthreads();

        // CD) softmax in registers + ctx via ldmatrix.trans MMA (warp n = batch n)
        {
            float z0 = __half2float(s->awl[lane][n])      + ab0;
            float z1 = __half2float(s->awl[lane + 32][n]) + ab1;
            float z2 = __half2float(s->awl[lane + 64][n]) + ab2;
            float m = fmaxf(z0, fmaxf(z1, z2));
#pragma unroll
            for (int o = 16; o; o >>= 1) m = fmaxf(m, __shfl_xor_sync(0xffffffffu, m, o));
            float e0 = __expf(z0 - m), e1 = __expf(z1 - m), e2 = __expf(z2 - m);
            float sum = e0 + e1 + e2;
#pragma unroll
            for (int o = 16; o; o >>= 1) sum += __shfl_xor_sync(0xffffffffu, sum, o);
            float inv = 1.0f / sum;
            float w0 = e0 * inv, w1 = e1 * inv, w2 = e2 * inv;  // aw[lane], aw[lane+32], aw[lane+64]

            float D[4][4];
#pragma unroll
            for (int jt = 0; jt < 4; jt++) { D[jt][0] = D[jt][1] = D[jt][2] = D[jt][3] = 0.f; }
            const __half* er = s->encS[n];
#pragma unroll
            for (int kt = 0; kt < 6; kt++) {
                float wsrc = (kt < 2) ? w0 : (kt < 4) ? w1 : w2;
                int sb = (kt & 1) * 16 + 2 * tig;
                float vA = __shfl_sync(0xffffffffu, wsrc, sb);
                float vB = __shfl_sync(0xffffffffu, wsrc, sb + 1);
                float vC = __shfl_sync(0xffffffffu, wsrc, sb + 8);
                float vD = __shfl_sync(0xffffffffu, wsrc, sb + 9);
                unsigned bf0 = (g4 == 0) ? h2u(vA, vB) : 0u;
                unsigned bf1 = (g4 == 0) ? h2u(vC, vD) : 0u;
                const int kRow = 16 * kt + kRowOff;
#pragma unroll
                for (int jt = 0; jt < 4; jt++) {
                    const int mGroup = 2 * jt + mHalf;
                    unsigned addr = s2u(&er[kRow * HH + ((mGroup ^ (kRow & 7)) << 3)]);
                    unsigned a0, a1, a2, a3;
                    ldsm4t(a0, a1, a2, a3, addr);
                    mma16816(D[jt][0], D[jt][1], D[jt][2], D[jt][3],
                             a0, a1, a2, a3, bf0, bf1);
                }
            }
            if (tig == 0) {
#pragma unroll
                for (int jt = 0; jt < 4; jt++) {
                    s->cbT[n][64 + 16 * jt + g4]     = __float2half_rn(D[jt][0]);
                    s->cbT[n][64 + 16 * jt + g4 + 8] = __float2half_rn(D[jt][2]);
                }
            }
        }
        __syncthreads();

        // E) comb via MMA (warps 12-15) -> abT[.][0..63]; gates h-half (warps 0-11)
        float gd0[4] = {0, 0, 0, 0}, gd1[4] = {0, 0, 0, 0};
        if (wid >= 12) {
            const __half* br0 = s->cbT[g4];
            const __half* br1 = s->cbT[8 + g4];
            float d0[4] = {0, 0, 0, 0}, d1[4] = {0, 0, 0, 0};
#pragma unroll
            for (int kt = 0; kt < 8; kt++) {
                unsigned a0f = *(const unsigned*)&br0[16 * kt + 2 * tig];
                unsigned a1f = *(const unsigned*)&br0[16 * kt + 2 * tig + 8];
                mma16816(d0[0], d0[1], d0[2], d0[3], Ax[kt][0], Ax[kt][1], Ax[kt][2], Ax[kt][3], a0f, a1f);
                unsigned b0f = *(const unsigned*)&br1[16 * kt + 2 * tig];
                unsigned b1f = *(const unsigned*)&br1[16 * kt + 2 * tig + 8];
                mma16816(d1[0], d1[1], d1[2], d1[3], Ax[kt][0], Ax[kt][1], Ax[kt][2], Ax[kt][3], b0f, b1f);
            }
            const int r0 = 16 * (wid - 12) + g4;
            float cb0 = s->comb_bS[r0], cb8 = s->comb_bS[r0 + 8];
            s->abT[2 * tig][r0]         = __float2half_rn(d0[0] + cb0);
            s->abT[2 * tig + 1][r0]     = __float2half_rn(d0[1] + cb0);
            s->abT[2 * tig][r0 + 8]     = __float2half_rn(d0[2] + cb8);
            s->abT[2 * tig + 1][r0 + 8] = __float2half_rn(d0[3] + cb8);
            s->abT[8 + 2 * tig][r0]         = __float2half_rn(d1[0] + cb0);
            s->abT[8 + 2 * tig + 1][r0]     = __float2half_rn(d1[1] + cb0);
            s->abT[8 + 2 * tig][r0 + 8]     = __float2half_rn(d1[2] + cb8);
            s->abT[8 + 2 * tig + 1][r0 + 8] = __float2half_rn(d1[3] + cb8);
        } else {
            const __half* br0 = s->abT[g4];
            const __half* br1 = s->abT[8 + g4];
#pragma unroll
            for (int kt = 4; kt < 8; kt++) {
                unsigned a0f = *(const unsigned*)&br0[16 * kt + 2 * tig];
                unsigned a1f = *(const unsigned*)&br0[16 * kt + 2 * tig + 8];
                mma16816(gd0[0], gd0[1], gd0[2], gd0[3], Ag[kt][0], Ag[kt][1], Ag[kt][2], Ag[kt][3], a0f, a1f);
                unsigned b0f = *(const unsigned*)&br1[16 * kt + 2 * tig];
                unsigned b1f = *(const unsigned*)&br1[16 * kt + 2 * tig + 8];
                mma16816(gd1[0], gd1[1], gd1[2], gd1[3], Ag[kt][0], Ag[kt][1], Ag[kt][2], Ag[kt][3], b0f, b1f);
            }
        }
        __syncthreads();

        // F) gates comb-half (all warps); warps 12-15 also their h-half
        {
            const __half* br0 = s->abT[g4];
            const __half* br1 = s->abT[8 + g4];
            if (wid >= 12) {
#pragma unroll
                for (int kt = 4; kt < 8; kt++) {
                    unsigned a0f = *(const unsigned*)&br0[16 * kt + 2 * tig];
                    unsigned a1f = *(const unsigned*)&br0[16 * kt + 2 * tig + 8];
                    mma16816(gd0[0], gd0[1], gd0[2], gd0[3], Ag[kt][0], Ag[kt][1], Ag[kt][2], Ag[kt][3], a0f, a1f);
                    unsigned b0f = *(const unsigned*)&br1[16 * kt + 2 * tig];
                    unsigned b1f = *(const unsigned*)&br1[16 * kt + 2 * tig + 8];
                    mma16816(gd1[0], gd1[1], gd1[2], gd1[3], Ag[kt][0], Ag[kt][1], Ag[kt][2], Ag[kt][3], b0f, b1f);
                }
            }
#pragma unroll
            for (int kt = 0; kt < 4; kt++) {
                unsigned a0f = *(const unsigned*)&br0[16 * kt + 2 * tig];
                unsigned a1f = *(const unsigned*)&br0[16 * kt + 2 * tig + 8];
                mma16816(gd0[0], gd0[1], gd0[2], gd0[3], Ag[kt][0], Ag[kt][1], Ag[kt][2], Ag[kt][3], a0f, a1f);
                unsigned b0f = *(const unsigned*)&br1[16 * kt + 2 * tig];
                unsigned b1f = *(const unsigned*)&br1[16 * kt + 2 * tig + 8];
                mma16816(gd1[0], gd1[1], gd1[2], gd1[3], Ag[kt][0], Ag[kt][1], Ag[kt][2], Ag[kt][3], b0f, b1f);
            }
            const int r0 = 16 * wid + g4;
            *(__half2*)&s->sg[r0][2 * tig]         = __floats2half2_rn(gd0[0], gd0[1]);
            *(__half2*)&s->sg[r0 + 8][2 * tig]     = __floats2half2_rn(gd0[2], gd0[3]);
            *(__half2*)&s->sg[r0][8 + 2 * tig]     = __floats2half2_rn(gd1[0], gd1[1]);
            *(__half2*)&s->sg[r0 + 8][8 + 2 * tig] = __floats2half2_rn(gd1[2], gd1[3]);
        }
        __syncthreads();

        // A) cell + pred + y + next emb (warp n = batch n)
        {
            float gi0 = __half2float(s->sg[j0][n])       + bg_i;
            float gi1 = __half2float(s->sg[j1][n])       + bg_i1;
            float gf0 = __half2float(s->sg[64 + j0][n])  + bg_f;
            float gf1 = __half2float(s->sg[64 + j1][n])  + bg_f1;
            float gg0 = __half2float(s->sg[128 + j0][n]) + bg_g;
            float gg1 = __half2float(s->sg[128 + j1][n]) + bg_g1;
            float go0 = __half2float(s->sg[192 + j0][n]) + bg_o;
            float go1 = __half2float(s->sg[192 + j1][n]) + bg_o1;
            float i0 = sigt(gi0), i1 = sigt(gi1);
            float f0 = sigt(gf0), f1 = sigt(gf1);
            float tg0 = tanha(gg0), tg1 = tanha(gg1);
            float o0 = sigt(go0), o1 = sigt(go1);
            cst0 = fmaf(f0, cst0, i0 * tg0);
            cst1 = fmaf(f1, cst1, i1 * tg1);
            hv0 = o0 * tanha(cst0);
            hv1 = o1 * tanha(cst1);

            float pc[8];
#pragma unroll
            for (int c = 0; c < 8; c++)
                pc[c] = fmaf(s->outW[c][j0], hv0, s->outW[c][j1] * hv1);
#pragma unroll
            for (int o = 16; o; o >>= 1) {
#pragma unroll
                for (int c = 0; c < 8; c++) pc[c] += __shfl_xor_sync(0xffffffffu, pc[c], o);
            }
#pragma unroll
            for (int c = 0; c < 8; c++) pc[c] += s->out_bS[c];

            if (lane == 0) {
                float* yp = y + ((size_t)(b0 + n) * TT + step) * CC;
                *(float4*)yp       = make_float4(pc[0] + sl0.x, pc[1] + sl0.y, pc[2] + sl0.z, pc[3] + sl0.w);
                *(float4*)(yp + 4) = make_float4(pc[4] + sl1.x, pc[5] + sl1.y, pc[6] + sl1.z, pc[7] + sl1.w);
            }

            float e0 = eb0, e1 = eb1;
#pragma unroll
            for (int c = 0; c < 8; c++) {
                e0 = fmaf(s->embW[c][j0], pc[c], e0);
                e1 = fmaf(s->embW[c][j1], pc[c], e1);
            }
            e0 = fmaxf(e0, 0.f); e1 = fmaxf(e1, 0.f);
            s->abT[n][j0] = __float2half_rn(e0); s->abT[n][j1] = __float2half_rn(e1);
            s->cbT[n][j0] = __float2half_rn(e0); s->cbT[n][j1] = __float2half_rn(e1);
            s->abT[n][64 + j0] = __float2half_rn(hv0);
            s->abT[n][64 + j1] = __float2half_rn(hv1);
        }
        __syncthreads();
    }
}

extern "C" void kernel_launch(void* const* d_in, const int* in_sizes, int n_in,
                              void* d_out, int out_size)
{
    const float* x_enc   = (const float*)d_in[0];
    const float* enc_Wih = (const float*)d_in[4];
    const float* enc_Whh = (const float*)d_in[5];
    const float* enc_bih = (const float*)d_in[6];
    const float* enc_bhh = (const float*)d_in[7];
    const float* emb_W   = (const float*)d_in[8];
    const float* emb_b   = (const float*)d_in[9];
    const float* attn_W  = (const float*)d_in[10];
    const float* attn_b  = (const float*)d_in[11];
    const float* comb_W  = (const float*)d_in[12];
    const float* comb_b  = (const float*)d_in[13];
    const float* dec_Wih = (const float*)d_in[14];
    const float* dec_Whh = (const float*)d_in[15];
    const float* dec_bih = (const float*)d_in[16];
    const float* dec_bhh = (const float*)d_in[17];
    const float* out_W   = (const float*)d_in[18];
    const float* out_b   = (const float*)d_in[19];
    float* y = (float*)d_out;

    cudaFuncSetAttribute(enc_kernel, cudaFuncAttributeMaxDynamicSharedMemorySize,
                         (int)sizeof(EncSmem));
    cudaFuncSetAttribute(dec_kernel, cudaFuncAttributeMaxDynamicSharedMemorySize,
                         (int)sizeof(DecSmem));

    enc_kernel<<<BB / ENB, 512, sizeof(EncSmem)>>>(x_enc, enc_Wih, enc_Whh, enc_bih, enc_bhh);
    dec_kernel<<<BB / DNB, 512, sizeof(DecSmem)>>>(x_enc, emb_W, emb_b, attn_W, attn_b,
                                                   comb_W, comb_b, dec_Wih, dec_Whh,
                                                   dec_bih, dec_bhh, out_W, out_b, y);
}

// round 11
// speedup vs baseline: 11.6446x; 1.1572x over previous
#include <cuda_runtime.h>
#include <cuda_fp16.h>

#define HH 64
#define CC 8
#define LL 96
#define TT 24
#define BB 4096
#define ENB 16   // encoder batches per block (2 blocks/SM)
#define DNB 16   // decoder batches per block

// Scratch (device globals — no allocations allowed)
__device__ __half g_enc_h[(size_t)BB * LL * HH];   // batch-major fp16 enc_out
__device__ float2 g_h0_pk[(BB / 2) * HH];
__device__ float2 g_c0_pk[(BB / 2) * HH];

__device__ __forceinline__ float tanha(float x) {
    float r; asm("tanh.approx.f32 %0, %1;" : "=f"(r) : "f"(x)); return r;
}
__device__ __forceinline__ float sigt(float x) {
    return fmaf(tanha(x * 0.5f), 0.5f, 0.5f);
}
__device__ __forceinline__ unsigned h2u(float x, float y) {
    __half2 h = __floats2half2_rn(x, y);
    return *reinterpret_cast<unsigned*>(&h);
}
__device__ __forceinline__ unsigned s2u(const void* p) {
    unsigned a;
    asm("{ .reg .u64 t; cvta.to.shared.u64 t, %1; cvt.u32.u64 %0, t; }" : "=r"(a) : "l"(p));
    return a;
}
__device__ __forceinline__ void mma16816(
    float& d0, float& d1, float& d2, float& d3,
    unsigned a0, unsigned a1, unsigned a2, unsigned a3,
    unsigned b0, unsigned b1)
{
    asm volatile(
        "mma.sync.aligned.m16n8k16.row.col.f32.f16.f16.f32 "
        "{%0,%1,%2,%3}, {%4,%5,%6,%7}, {%8,%9}, {%0,%1,%2,%3};"
        : "+f"(d0), "+f"(d1), "+f"(d2), "+f"(d3)
        : "r"(a0), "r"(a1), "r"(a2), "r"(a3), "r"(b0), "r"(b1));
}
__device__ __forceinline__ void ldsm4t(unsigned& a0, unsigned& a1, unsigned& a2, unsigned& a3,
                                       unsigned addr)
{
    asm volatile("ldmatrix.sync.aligned.m8n8.x4.trans.shared.b16 {%0,%1,%2,%3}, [%4];"
                 : "=r"(a0), "=r"(a1), "=r"(a2), "=r"(a3) : "r"(addr));
}

// ---------------------------------------------------------------------------
// Encoder: 16 batches/block, 256 threads, 2 blocks/SM (all 256 blocks in one
// wave). Each warp owns 2 m-tiles (rows 32*wid..32*wid+31) x 2 n-tiles.
// ---------------------------------------------------------------------------
struct __align__(16) EncSmem {
    __half xT[ENB][776];   // 24832 B
    __half hT[ENB][72];    // 2304 B
    float  sg[256][18];    // 18432 B
    float  bias[256];      // 1024 B
};  // ~46.6 KB

__global__ __launch_bounds__(256, 2) void enc_kernel(
    const float* __restrict__ x_enc,
    const float* __restrict__ Wih, const float* __restrict__ Whh,
    const float* __restrict__ bih, const float* __restrict__ bhh)
{
    extern __shared__ char smem_raw[];
    EncSmem* s = reinterpret_cast<EncSmem*>(smem_raw);
    const int t = threadIdx.x;
    const int wid = t >> 5, lane = t & 31;
    const int g4 = lane >> 2, tig = lane & 3;
    const size_t b0 = (size_t)blockIdx.x * ENB;
    const int bp0 = blockIdx.x * (ENB / 2);

    // A fragments: 2 m-tiles per warp, 5 k-tiles each
    unsigned A[2][5][4];
#pragma unroll
    for (int mi = 0; mi < 2; mi++) {
        const int r0 = 16 * (2 * wid + mi) + g4;
#pragma unroll
        for (int kt = 0; kt < 5; kt++) {
            const int c0 = 16 * kt + 2 * tig;
#pragma unroll
            for (int half_ = 0; half_ < 4; half_++) {
                const int rr = r0 + ((half_ & 1) ? 8 : 0);
                const int cc = c0 + ((half_ & 2) ? 8 : 0);
                float w0, w1;
                w0 = (cc < 64) ? Whh[rr * 64 + cc] : ((cc < 72) ? Wih[rr * 8 + cc - 64] : 0.f);
                w1 = (cc + 1 < 64) ? Whh[rr * 64 + cc + 1] : ((cc + 1 < 72) ? Wih[rr * 8 + cc + 1 - 64] : 0.f);
                A[mi][kt][half_] = h2u(w0, w1);
            }
        }
    }
    s->bias[t] = bih[t] + bhh[t];

    // Stage x deltas fp16, zero hT
    for (int i = t; i < ENB * 768; i += 256) {
        int n = i / 768, idx = i % 768, c = idx & 7;
        const float* xb = x_enc + (b0 + n) * 768;
        s->xT[n][idx] = __float2half_rn(xb[idx] - xb[760 + c]);
    }
    for (int i = t; i < ENB * 72; i += 256) ((__half*)s->hT)[i] = __ushort_as_half(0);
    __syncthreads();

    const int jc = t & 63, qc = t >> 6;   // cell: thread -> (j, batches 4qc..4qc+3)
    float cs0 = 0.f, cs1 = 0.f, cs2 = 0.f, cs3 = 0.f;
    float h0r = 0.f, h1r = 0.f, h2r = 0.f, h3r = 0.f;

    for (int step = 0; step < LL; step++) {
        float d[2][2][4];
#pragma unroll
        for (int mi = 0; mi < 2; mi++)
#pragma unroll
            for (int nt = 0; nt < 2; nt++) { d[mi][nt][0] = d[mi][nt][1] = d[mi][nt][2] = d[mi][nt][3] = 0.f; }

#pragma unroll
        for (int nt = 0; nt < 2; nt++) {
            const __half* hrow = s->hT[nt * 8 + g4];
            unsigned bh[4][2];
#pragma unroll
            for (int kt = 0; kt < 4; kt++) {
                bh[kt][0] = *(const unsigned*)&hrow[16 * kt + 2 * tig];
                bh[kt][1] = *(const unsigned*)&hrow[16 * kt + 2 * tig + 8];
            }
            unsigned bx = *(const unsigned*)&s->xT[nt * 8 + g4][step * 8 + 2 * tig];
#pragma unroll
            for (int mi = 0; mi < 2; mi++) {
#pragma unroll
                for (int kt = 0; kt < 4; kt++)
                    mma16816(d[mi][nt][0], d[mi][nt][1], d[mi][nt][2], d[mi][nt][3],
                             A[mi][kt][0], A[mi][kt][1], A[mi][kt][2], A[mi][kt][3],
                             bh[kt][0], bh[kt][1]);
                mma16816(d[mi][nt][0], d[mi][nt][1], d[mi][nt][2], d[mi][nt][3],
                         A[mi][4][0], A[mi][4][1], A[mi][4][2], A[mi][4][3], bx, 0u);
            }
        }
#pragma unroll
        for (int mi = 0; mi < 2; mi++) {
            const int r0 = 16 * (2 * wid + mi) + g4;
#pragma unroll
            for (int nt = 0; nt < 2; nt++) {
                const int cidx = nt * 8 + 2 * tig;
                *(float2*)&s->sg[r0][cidx]     = make_float2(d[mi][nt][0], d[mi][nt][1]);
                *(float2*)&s->sg[r0 + 8][cidx] = make_float2(d[mi][nt][2], d[mi][nt][3]);
            }
        }
        __syncthreads();

        {
            float2 giA = *(const float2*)&s->sg[jc][4 * qc];
            float2 giB = *(const float2*)&s->sg[jc][4 * qc + 2];
            float2 gfA = *(const float2*)&s->sg[64 + jc][4 * qc];
            float2 gfB = *(const float2*)&s->sg[64 + jc][4 * qc + 2];
            float2 ggA = *(const float2*)&s->sg[128 + jc][4 * qc];
            float2 ggB = *(const float2*)&s->sg[128 + jc][4 * qc + 2];
            float2 goA = *(const float2*)&s->sg[192 + jc][4 * qc];
            float2 goB = *(const float2*)&s->sg[192 + jc][4 * qc + 2];
            float bi = s->bias[jc], bf = s->bias[64 + jc];
            float bg = s->bias[128 + jc], bo = s->bias[192 + jc];

            float i0 = sigt(giA.x + bi), i1 = sigt(giA.y + bi), i2 = sigt(giB.x + bi), i3 = sigt(giB.y + bi);
            float f0 = sigt(gfA.x + bf), f1 = sigt(gfA.y + bf), f2 = sigt(gfB.x + bf), f3 = sigt(gfB.y + bf);
            float t0 = tanha(ggA.x + bg), t1 = tanha(ggA.y + bg), t2 = tanha(ggB.x + bg), t3 = tanha(ggB.y + bg);
            float o0 = sigt(goA.x + bo), o1 = sigt(goA.y + bo), o2 = sigt(goB.x + bo), o3 = sigt(goB.y + bo);
            cs0 = fmaf(f0, cs0, i0 * t0); cs1 = fmaf(f1, cs1, i1 * t1);
            cs2 = fmaf(f2, cs2, i2 * t2); cs3 = fmaf(f3, cs3, i3 * t3);
            h0r = o0 * tanha(cs0); h1r = o1 * tanha(cs1);
            h2r = o2 * tanha(cs2); h3r = o3 * tanha(cs3);

            s->hT[4 * qc + 0][jc] = __float2half_rn(h0r);
            s->hT[4 * qc + 1][jc] = __float2half_rn(h1r);
            s->hT[4 * qc + 2][jc] = __float2half_rn(h2r);
            s->hT[4 * qc + 3][jc] = __float2half_rn(h3r);
            const size_t eb = (b0 + 4 * qc) * (size_t)(LL * HH) + step * HH + jc;
            g_enc_h[eb]                = __float2half_rn(h0r);
            g_enc_h[eb + LL * HH]      = __float2half_rn(h1r);
            g_enc_h[eb + 2 * LL * HH]  = __float2half_rn(h2r);
            g_enc_h[eb + 3 * LL * HH]  = __float2half_rn(h3r);
        }
        __syncthreads();
    }
    g_h0_pk[(bp0 + 2 * qc) * HH + jc]     = make_float2(h0r, h1r);
    g_h0_pk[(bp0 + 2 * qc + 1) * HH + jc] = make_float2(h2r, h3r);
    g_c0_pk[(bp0 + 2 * qc) * HH + jc]     = make_float2(cs0, cs1);
    g_c0_pk[(bp0 + 2 * qc + 1) * HH + jc] = make_float2(cs2, cs3);
}

// ---------------------------------------------------------------------------
// Decoder: 16 batches/block, grid = 256 (as R9) + shortened CD chain:
// exp without max-sub, unnormalized-weight ctx MMA, sum-reduce overlapped.
// ---------------------------------------------------------------------------
struct __align__(16) DecSmem {
    __half  encS[DNB][LL * HH];   // 196608, [n][l*64 + swz(group,l)*8+j%8]
    __half  abT[DNB][136];        // [emb|comb (0..63); h (64..127)]
    __half  cbT[DNB][136];        // [emb (0..63); ctx (64..127)]
    __half  awl[LL][18];          // attn logits [l][n], fp16, stride 18
    __half  sg[256][18];          // gate pre-acts [row][n], fp16
    float   embW[CC][HH];
    float   outW[CC][HH];
    float   biasg[256];
    float   attn_bS[LL];
    float   comb_bS[HH];
    float   emb_bS[HH];
    float   out_bS[CC];
};  // ~224 KB

__global__ __launch_bounds__(512, 1) void dec_kernel(
    const float* __restrict__ x_enc,
    const float* __restrict__ emb_W, const float* __restrict__ emb_b,
    const float* __restrict__ attn_W, const float* __restrict__ attn_b,
    const float* __restrict__ comb_W, const float* __restrict__ comb_b,
    const float* __restrict__ Wih, const float* __restrict__ Whh,
    const float* __restrict__ bih, const float* __restrict__ bhh,
    const float* __restrict__ out_W, const float* __restrict__ out_b,
    float* __restrict__ y)
{
    extern __shared__ char smem_raw[];
    DecSmem* s = reinterpret_cast<DecSmem*>(smem_raw);
    const int t = threadIdx.x;
    const int wid = t >> 5, lane = t & 31;
    const int g4 = lane >> 2, tig = lane & 3;
    const int b0 = blockIdx.x * DNB;
    const int bp0 = blockIdx.x * (DNB / 2);

    // ---- A fragments ----
    unsigned Ag[8][4];       // gates rows 16*wid (Wih k<64 | Whh k>=64)
    unsigned Ax[8][4] = {};  // attn (wid<12) / comb (wid>=12)
    {
        const int r0 = 16 * wid + g4;
#pragma unroll
        for (int kt = 0; kt < 8; kt++) {
            const int c0 = 16 * kt + 2 * tig;
#pragma unroll
            for (int h_ = 0; h_ < 4; h_++) {
                const int rr = r0 + ((h_ & 1) ? 8 : 0);
                const int cc = c0 + ((h_ & 2) ? 8 : 0);
                float w0 = (cc < 64) ? Wih[rr * 64 + cc] : Whh[rr * 64 + cc - 64];
                float w1 = (cc + 1 < 64) ? Wih[rr * 64 + cc + 1] : Whh[rr * 64 + cc + 1 - 64];
                Ag[kt][h_] = h2u(w0, w1);
            }
        }
        if (wid < 12) {
            const int ra = 16 * (wid < 6 ? wid : wid - 6) + g4;
#pragma unroll
            for (int kt = 0; kt < 8; kt++) {
                const int c0 = 16 * kt + 2 * tig;
#pragma unroll
                for (int h_ = 0; h_ < 4; h_++) {
                    const int rr = ra + ((h_ & 1) ? 8 : 0);
                    const int cc = c0 + ((h_ & 2) ? 8 : 0);
                    Ax[kt][h_] = h2u(attn_W[rr * 128 + cc], attn_W[rr * 128 + cc + 1]);
                }
            }
        } else {
            const int rc = 16 * (wid - 12) + g4;
#pragma unroll
            for (int kt = 0; kt < 8; kt++) {
                const int c0 = 16 * kt + 2 * tig;
#pragma unroll
                for (int h_ = 0; h_ < 4; h_++) {
                    const int rr = rc + ((h_ & 1) ? 8 : 0);
                    const int cc = c0 + ((h_ & 2) ? 8 : 0);
                    Ax[kt][h_] = h2u(comb_W[rr * 128 + cc], comb_W[rr * 128 + cc + 1]);
                }
            }
        }
    }

    // ---- Stage SMEM (enc with XOR swizzle on 16B groups) ----
    {
        const float4* eg = (const float4*)(g_enc_h + (size_t)b0 * (LL * HH));
        float4* es = (float4*)s->encS;
        for (int i = t; i < DNB * LL * 8; i += 512) {
            int nl = i >> 3, g = i & 7;
            int l = nl % LL;
            es[nl * 8 + (g ^ (l & 7))] = eg[i];
        }
    }
    for (int i = t; i < CC * HH; i += 512) {
        int j = i >> 3, k = i & 7;
        s->embW[k][j] = emb_W[i];
        ((float*)s->outW)[i] = out_W[i];
    }
    if (t < 256) s->biasg[t] = bih[t] + bhh[t];
    if (t < LL) s->attn_bS[t] = attn_b[t];
    if (t < HH) { s->comb_bS[t] = comb_b[t]; s->emb_bS[t] = emb_b[t]; }
    if (t < CC) s->out_bS[t] = out_b[t];
    __syncthreads();

    // ---- Per-warp batch state (warp n = batch n) ----
    const int n = wid, j0 = lane, j1 = lane + 32;
    float cst0, cst1, hv0, hv1;
    {
        float2 hA = g_h0_pk[(bp0 + (n >> 1)) * HH + j0];
        float2 hB = g_h0_pk[(bp0 + (n >> 1)) * HH + j1];
        float2 cA = g_c0_pk[(bp0 + (n >> 1)) * HH + j0];
        float2 cB = g_c0_pk[(bp0 + (n >> 1)) * HH + j1];
        hv0 = (n & 1) ? hA.y : hA.x;  hv1 = (n & 1) ? hB.y : hB.x;
        cst0 = (n & 1) ? cA.y : cA.x; cst1 = (n & 1) ? cB.y : cB.x;
    }
    float4 sl0 = make_float4(0, 0, 0, 0), sl1 = sl0;
    if (lane == 0) {
        const float* xb = x_enc + (size_t)(b0 + n) * (LL * CC) + (LL - 1) * CC;
        sl0 = *(const float4*)xb;
        sl1 = *(const float4*)(xb + 4);
    }
    const float bg_i = s->biasg[j0],       bg_i1 = s->biasg[j1];
    const float bg_f = s->biasg[64 + j0],  bg_f1 = s->biasg[64 + j1];
    const float bg_g = s->biasg[128 + j0], bg_g1 = s->biasg[128 + j1];
    const float bg_o = s->biasg[192 + j0], bg_o1 = s->biasg[192 + j1];
    const float ab0 = s->attn_bS[lane], ab1 = s->attn_bS[lane + 32], ab2 = s->attn_bS[lane + 64];
    const float eb0 = s->emb_bS[j0], eb1 = s->emb_bS[j1];

    const int kRowOff = (lane & 7) + 8 * ((lane >> 4) & 1);
    const int mHalf   = (lane >> 3) & 1;

    {
        float e0 = fmaxf(eb0, 0.f), e1 = fmaxf(eb1, 0.f);
        s->abT[n][j0] = __float2half_rn(e0); s->abT[n][j1] = __float2half_rn(e1);
        s->cbT[n][j0] = __float2half_rn(e0); s->cbT[n][j1] = __float2half_rn(e1);
        s->abT[n][64 + j0] = __float2half_rn(hv0);
        s->abT[n][64 + j1] = __float2half_rn(hv1);
    }
    __syncthreads();

    for (int step = 0; step < TT; step++) {
        // B) attn logits via MMA: 12 warps = 6 m-tiles x 2 n-halves
        if (wid < 12) {
            const int mw = (wid < 6) ? wid : wid - 6;
            const int nh = (wid < 6) ? 0 : 1;
            const __half* br = s->abT[8 * nh + g4];
            float d0 = 0.f, d1 = 0.f, d2 = 0.f, d3 = 0.f;
#pragma unroll
            for (int kt = 0; kt < 8; kt++) {
                unsigned bf0 = *(const unsigned*)&br[16 * kt + 2 * tig];
                unsigned bf1 = *(const unsigned*)&br[16 * kt + 2 * tig + 8];
                mma16816(d0, d1, d2, d3, Ax[kt][0], Ax[kt][1], Ax[kt][2], Ax[kt][3], bf0, bf1);
            }
            const int r0 = 16 * mw + g4, c0 = 8 * nh + 2 * tig;
            *(__half2*)&s->awl[r0][c0]     = __floats2half2_rn(d0, d1);
            *(__half2*)&s->awl[r0 + 8][c0] = __floats2half2_rn(d2, d3);
        }
        __syncthreads();

        // CD) exp (no max-sub; logits are O(1)) + ctx MMA with unnormalized
        // weights; sum-reduce overlaps MMA drain; scale D by inv at the end.
        {
            float z0 = __half2float(s->awl[lane][n])      + ab0;
            float z1 = __half2float(s->awl[lane + 32][n]) + ab1;
            float z2 = __half2float(s->awl[lane + 64][n]) + ab2;
            float e0 = __expf(z0), e1 = __expf(z1), e2 = __expf(z2);

            float D[4][4];
#pragma unroll
            for (int jt = 0; jt < 4; jt++) { D[jt][0] = D[jt][1] = D[jt][2] = D[jt][3] = 0.f; }
            const __half* er = s->encS[n];
#pragma unroll
            for (int kt = 0; kt < 6; kt++) {
                float wsrc = (kt < 2) ? e0 : (kt < 4) ? e1 : e2;
                int sb = (kt & 1) * 16 + 2 * tig;
                float vA = __shfl_sync(0xffffffffu, wsrc, sb);
                float vB = __shfl_sync(0xffffffffu, wsrc, sb + 1);
                float vC = __shfl_sync(0xffffffffu, wsrc, sb + 8);
                float vD = __shfl_sync(0xffffffffu, wsrc, sb + 9);
                unsigned bf0 = (g4 == 0) ? h2u(vA, vB) : 0u;
                unsigned bf1 = (g4 == 0) ? h2u(vC, vD) : 0u;
                const int kRow = 16 * kt + kRowOff;
#pragma unroll
                for (int jt = 0; jt < 4; jt++) {
                    const int mGroup = 2 * jt + mHalf;
                    unsigned addr = s2u(&er[kRow * HH + ((mGroup ^ (kRow & 7)) << 3)]);
                    unsigned a0, a1, a2, a3;
                    ldsm4t(a0, a1, a2, a3, addr);
                    mma16816(D[jt][0], D[jt][1], D[jt][2], D[jt][3],
                             a0, a1, a2, a3, bf0, bf1);
                }
            }
            // sum reduce (independent of MMA chain — overlaps its drain)
            float sum = e0 + e1 + e2;
#pragma unroll
            for (int o = 16; o; o >>= 1) sum += __shfl_xor_sync(0xffffffffu, sum, o);
            float inv = 1.0f / sum;
            if (tig == 0) {
#pragma unroll
                for (int jt = 0; jt < 4; jt++) {
                    s->cbT[n][64 + 16 * jt + g4]     = __float2half_rn(D[jt][0] * inv);
                    s->cbT[n][64 + 16 * jt + g4 + 8] = __float2half_rn(D[jt][2] * inv);
                }
            }
        }
        __syncthreads();

        // E) comb via MMA (warps 12-15) -> abT[.][0..63]; gates h-half (warps 0-11)
        float gd0[4] = {0, 0, 0, 0}, gd1[4] = {0, 0, 0, 0};
        if (wid >= 12) {
            const __half* br0 = s->cbT[g4];
            const __half* br1 = s->cbT[8 + g4];
            float d0[4] = {0, 0, 0, 0}, d1[4] = {0, 0, 0, 0};
#pragma unroll
            for (int kt = 0; kt < 8; kt++) {
                unsigned a0f = *(const unsigned*)&br0[16 * kt + 2 * tig];
                unsigned a1f = *(const unsigned*)&br0[16 * kt + 2 * tig + 8];
                mma16816(d0[0], d0[1], d0[2], d0[3], Ax[kt][0], Ax[kt][1], Ax[kt][2], Ax[kt][3], a0f, a1f);
                unsigned b0f = *(const unsigned*)&br1[16 * kt + 2 * tig];
                unsigned b1f = *(const unsigned*)&br1[16 * kt + 2 * tig + 8];
                mma16816(d1[0], d1[1], d1[2], d1[3], Ax[kt][0], Ax[kt][1], Ax[kt][2], Ax[kt][3], b0f, b1f);
            }
            const int r0 = 16 * (wid - 12) + g4;
            float cb0 = s->comb_bS[r0], cb8 = s->comb_bS[r0 + 8];
            s->abT[2 * tig][r0]         = __float2half_rn(d0[0] + cb0);
            s->abT[2 * tig + 1][r0]     = __float2half_rn(d0[1] + cb0);
            s->abT[2 * tig][r0 + 8]     = __float2half_rn(d0[2] + cb8);
            s->abT[2 * tig + 1][r0 + 8] = __float2half_rn(d0[3] + cb8);
            s->abT[8 + 2 * tig][r0]         = __float2half_rn(d1[0] + cb0);
            s->abT[8 + 2 * tig + 1][r0]     = __float2half_rn(d1[1] + cb0);
            s->abT[8 + 2 * tig][r0 + 8]     = __float2half_rn(d1[2] + cb8);
            s->abT[8 + 2 * tig + 1][r0 + 8] = __float2half_rn(d1[3] + cb8);
        } else {
            const __half* br0 = s->abT[g4];
            const __half* br1 = s->abT[8 + g4];
#pragma unroll
            for (int kt = 4; kt < 8; kt++) {
                unsigned a0f = *(const unsigned*)&br0[16 * kt + 2 * tig];
                unsigned a1f = *(const unsigned*)&br0[16 * kt + 2 * tig + 8];
                mma16816(gd0[0], gd0[1], gd0[2], gd0[3], Ag[kt][0], Ag[kt][1], Ag[kt][2], Ag[kt][3], a0f, a1f);
                unsigned b0f = *(const unsigned*)&br1[16 * kt + 2 * tig];
                unsigned b1f = *(const unsigned*)&br1[16 * kt + 2 * tig + 8];
                mma16816(gd1[0], gd1[1], gd1[2], gd1[3], Ag[kt][0], Ag[kt][1], Ag[kt][2], Ag[kt][3], b0f, b1f);
            }
        }
        __syncthreads();

        // F) gates comb-half (all warps); warps 12-15 also their h-half
        {
            const __half* br0 = s->abT[g4];
            const __half* br1 = s->abT[8 + g4];
            if (wid >= 12) {
#pragma unroll
                for (int kt = 4; kt < 8; kt++) {
                    unsigned a0f = *(const unsigned*)&br0[16 * kt + 2 * tig];
                    unsigned a1f = *(const unsigned*)&br0[16 * kt + 2 * tig + 8];
                    mma16816(gd0[0], gd0[1], gd0[2], gd0[3], Ag[kt][0], Ag[kt][1], Ag[kt][2], Ag[kt][3], a0f, a1f);
                    unsigned b0f = *(const unsigned*)&br1[16 * kt + 2 * tig];
                    unsigned b1f = *(const unsigned*)&br1[16 * kt + 2 * tig + 8];
                    mma16816(gd1[0], gd1[1], gd1[2], gd1[3], Ag[kt][0], Ag[kt][1], Ag[kt][2], Ag[kt][3], b0f, b1f);
                }
            }
#pragma unroll
            for (int kt = 0; kt < 4; kt++) {
                unsigned a0f = *(const unsigned*)&br0[16 * kt + 2 * tig];
                unsigned a1f = *(const unsigned*)&br0[16 * kt + 2 * tig + 8];
                mma16816(gd0[0], gd0[1], gd0[2], gd0[3], Ag[kt][0], Ag[kt][1], Ag[kt][2], Ag[kt][3], a0f, a1f);
                unsigned b0f = *(const unsigned*)&br1[16 * kt + 2 * tig];
                unsigned b1f = *(const unsigned*)&br1[16 * kt + 2 * tig + 8];
                mma16816(gd1[0], gd1[1], gd1[2], gd1[3], Ag[kt][0], Ag[kt][1], Ag[kt][2], Ag[kt][3], b0f, b1f);
            }
            const int r0 = 16 * wid + g4;
            *(__half2*)&s->sg[r0][2 * tig]         = __floats2half2_rn(gd0[0], gd0[1]);
            *(__half2*)&s->sg[r0 + 8][2 * tig]     = __floats2half2_rn(gd0[2], gd0[3]);
            *(__half2*)&s->sg[r0][8 + 2 * tig]     = __floats2half2_rn(gd1[0], gd1[1]);
            *(__half2*)&s->sg[r0 + 8][8 + 2 * tig] = __floats2half2_rn(gd1[2], gd1[3]);
        }
        __syncthreads();

        // A) cell + pred + y + next emb (warp n = batch n)
        {
            float gi0 = __half2float(s->sg[j0][n])       + bg_i;
            float gi1 = __half2float(s->sg[j1][n])       + bg_i1;
            float gf0 = __half2float(s->sg[64 + j0][n])  + bg_f;
            float gf1 = __half2float(s->sg[64 + j1][n])  + bg_f1;
            float gg0 = __half2float(s->sg[128 + j0][n]) + bg_g;
            float gg1 = __half2float(s->sg[128 + j1][n]) + bg_g1;
            float go0 = __half2float(s->sg[192 + j0][n]) + bg_o;
            float go1 = __half2float(s->sg[192 + j1][n]) + bg_o1;
            float i0 = sigt(gi0), i1 = sigt(gi1);
            float f0 = sigt(gf0), f1 = sigt(gf1);
            float tg0 = tanha(gg0), tg1 = tanha(gg1);
            float o0 = sigt(go0), o1 = sigt(go1);
            cst0 = fmaf(f0, cst0, i0 * tg0);
            cst1 = fmaf(f1, cst1, i1 * tg1);
            hv0 = o0 * tanha(cst0);
            hv1 = o1 * tanha(cst1);

            float pc[8];
#pragma unroll
            for (int c = 0; c < 8; c++)
                pc[c] = fmaf(s->outW[c][j0], hv0, s->outW[c][j1] * hv1);
#pragma unroll
            for (int o = 16; o; o >>= 1) {
#pragma unroll
                for (int c = 0; c < 8; c++) pc[c] += __shfl_xor_sync(0xffffffffu, pc[c], o);
            }
#pragma unroll
            for (int c = 0; c < 8; c++) pc[c] += s->out_bS[c];

            if (lane == 0) {
                float* yp = y + ((size_t)(b0 + n) * TT + step) * CC;
                *(float4*)yp       = make_float4(pc[0] + sl0.x, pc[1] + sl0.y, pc[2] + sl0.z, pc[3] + sl0.w);
                *(float4*)(yp + 4) = make_float4(pc[4] + sl1.x, pc[5] + sl1.y, pc[6] + sl1.z, pc[7] + sl1.w);
            }

            float e0 = eb0, e1 = eb1;
#pragma unroll
            for (int c = 0; c < 8; c++) {
                e0 = fmaf(s->embW[c][j0], pc[c], e0);
                e1 = fmaf(s->embW[c][j1], pc[c], e1);
            }
            e0 = fmaxf(e0, 0.f); e1 = fmaxf(e1, 0.f);
            s->abT[n][j0] = __float2half_rn(e0); s->abT[n][j1] = __float2half_rn(e1);
            s->cbT[n][j0] = __float2half_rn(e0); s->cbT[n][j1] = __float2half_rn(e1);
            s->abT[n][64 + j0] = __float2half_rn(hv0);
            s->abT[n][64 + j1] = __float2half_rn(hv1);
        }
        __syncthreads();
    }
}

extern "C" void kernel_launch(void* const* d_in, const int* in_sizes, int n_in,
                              void* d_out, int out_size)
{
    const float* x_enc   = (const float*)d_in[0];
    const float* enc_Wih = (const float*)d_in[4];
    const float* enc_Whh = (const float*)d_in[5];
    const float* enc_bih = (const float*)d_in[6];
    const float* enc_bhh = (const float*)d_in[7];
    const float* emb_W   = (const float*)d_in[8];
    const float* emb_b   = (const float*)d_in[9];
    const float* attn_W  = (const float*)d_in[10];
    const float* attn_b  = (const float*)d_in[11];
    const float* comb_W  = (const float*)d_in[12];
    const float* comb_b  = (const float*)d_in[13];
    const float* dec_Wih = (const float*)d_in[14];
    const float* dec_Whh = (const float*)d_in[15];
    const float* dec_bih = (const float*)d_in[16];
    const float* dec_bhh = (const float*)d_in[17];
    const float* out_W   = (const float*)d_in[18];
    const float* out_b   = (const float*)d_in[19];
    float* y = (float*)d_out;

    cudaFuncSetAttribute(enc_kernel, cudaFuncAttributeMaxDynamicSharedMemorySize,
                         (int)sizeof(EncSmem));
    cudaFuncSetAttribute(dec_kernel, cudaFuncAttributeMaxDynamicSharedMemorySize,
                         (int)sizeof(DecSmem));

    enc_kernel<<<BB / ENB, 256, sizeof(EncSmem)>>>(x_enc, enc_Wih, enc_Whh, enc_bih, enc_bhh);
    dec_kernel<<<BB / DNB, 512, sizeof(DecSmem)>>>(x_enc, emb_W, emb_b, attn_W, attn_b,
                                                   comb_W, comb_b, dec_Wih, dec_Whh,
                                                   dec_bih, dec_bhh, out_W, out_b, y);
}